// round 2
// baseline (speedup 1.0000x reference)
#include <cuda_runtime.h>
#include <math.h>

#define NB     256
#define NA     128
#define NATOMS 32768
#define AEV    1008
#define MO     256
#define NOUT   128
#define FIN    384
#define NP     262144
#define NSP    4
#define NPAD   33280          // 260 tiles of 128 rows (worst-case species padding)
#define NT     (NPAD/128)

// ---------------- scratch (device globals; no allocation allowed) ----------
__device__ float g_aevP[(size_t)NPAD*AEV];   // permuted (species-grouped) AEV
__device__ float g_feat1[(size_t)NPAD*FIN];  // [internal0 | merged0]
__device__ float g_feat2[(size_t)NPAD*FIN];  // [internal1 | merged1]
__device__ float g_neigh[(size_t)NPAD*NOUT];
__device__ float g_decay[NP];
__device__ int   g_e0[NP], g_e1[NP];         // edge endpoints in permuted space
__device__ int   g_p2n[NATOMS];              // orig -> permuted row
__device__ int   g_n2o[NPAD];                // permuted row -> orig (-1 = pad)
__device__ int   g_tilesp[NT];               // species of each 128-row tile
__device__ float g_pre[NATOMS];              // per-atom pre-charge (orig order)

__device__ __forceinline__ float* bufsel(int c){
    switch(c){
        case 0: return g_aevP;
        case 1: return g_feat1;
        case 2: return g_feat2;
        default: return g_neigh;
    }
}

__device__ __forceinline__ float gelu_tanh(float x){
    float t = tanhf(0.7978845608028654f * (x + 0.044715f * x * x * x));
    return 0.5f * x * (1.0f + t);
}

// ---------------- permutation: deterministic species grouping --------------
__global__ void __launch_bounds__(1024) perm_kernel(const int* __restrict__ species){
    __shared__ int sc[NSP][1024];
    __shared__ int stot[NSP];
    __shared__ int sbase[NSP+1];
    int t = threadIdx.x;
    for (int r = t; r < NPAD; r += 1024) g_n2o[r] = -1;

    int c0=0,c1=0,c2=0,c3=0;
    int b0 = t*32;
    #pragma unroll
    for (int j=0;j<32;j++){
        int s = species[b0+j];
        c0 += (s==0); c1 += (s==1); c2 += (s==2); c3 += (s==3);
    }
    sc[0][t]=c0; sc[1][t]=c1; sc[2][t]=c2; sc[3][t]=c3;
    __syncthreads();
    if (t < NSP){
        int run = 0;
        for (int i=0;i<1024;i++){ int v=sc[t][i]; sc[t][i]=run; run+=v; }
        stot[t]=run;
    }
    __syncthreads();
    if (t==0){
        int b=0;
        for (int s=0;s<NSP;s++){ sbase[s]=b; b += ((stot[s]+127)>>7)<<7; }
        sbase[NSP]=b;
        for (int tt=0; tt<NT; tt++){
            int rs = tt*128; int sp=0;
            for (int s=1;s<NSP;s++) if (rs >= sbase[s]) sp=s;
            g_tilesp[tt]=sp;
        }
    }
    __syncthreads();
    int run2[NSP] = {0,0,0,0};
    for (int j=0;j<32;j++){
        int i = b0+j; int s = species[i];
        int pos = sbase[s] + sc[s][t] + run2[s];
        run2[s]++;
        g_p2n[i]=pos; g_n2o[pos]=i;
    }
}

// ---------------- gather AEV rows into permuted buffer ---------------------
__global__ void gather_kernel(const float* __restrict__ aev){
    int r = blockIdx.x;
    int t = threadIdx.x;
    if (t >= AEV/4) return;
    int src = g_n2o[r];
    float4 v = make_float4(0.f,0.f,0.f,0.f);
    if (src >= 0) v = ((const float4*)aev)[(size_t)src*(AEV/4) + t];
    ((float4*)g_aevP)[(size_t)r*(AEV/4) + t] = v;
}

// ---------------- edges: decay + endpoint remap -----------------------------
__global__ void edge_kernel(const int* __restrict__ ai,
                            const float* __restrict__ dist,
                            const float* __restrict__ fa,
                            const float* __restrict__ pf){
    int p = blockIdx.x*256 + threadIdx.x;
    float d = dist[p];
    float factor = fa[0], pre = pf[0];
    float x = fminf(fmaxf(d*(1.0f/5.2f), 0.0f), 1.0f - 1e-6f);
    float f = (d < 5.2f) ? expf(1.0f - 1.0f/(1.0f - x*x)) : 0.0f;
    g_decay[p] = pre*pre*expf(-factor*factor*d)*f;
    g_e0[p] = g_p2n[ai[p]];
    g_e1[p] = g_p2n[ai[NP + p]];
}

// ---------------- species-routed GEMM (fp32 SIMT, 128x128x8) ---------------
__global__ void __launch_bounds__(256) gemm_kernel(
    int abuf, int lda,
    const float* __restrict__ W, const float* __restrict__ bias,
    int cbuf, int ldc, int coff,
    int K, int Nout, int act)
{
    const float* A = bufsel(abuf);
    float* C = bufsel(cbuf);
    __shared__ float As[2][8][128];
    __shared__ float Bs[2][8][128];
    int bx = blockIdx.x, by = blockIdx.y;
    int sp = g_tilesp[by];
    const float* Ap = A + (size_t)by*128*lda;
    const float* Wp = W + (size_t)sp*K*Nout + bx*128;
    int tid = threadIdx.x;
    int arow = tid>>1, acol = (tid&1)*4;
    int brow = tid>>5, bcol = (tid&31)*4;
    int tm = (tid>>4)*8, tn = (tid&15)*8;

    float acc[8][8];
    #pragma unroll
    for (int i=0;i<8;i++)
        #pragma unroll
        for (int j=0;j<8;j++) acc[i][j]=0.f;

    float4 a = *(const float4*)(Ap + (size_t)arow*lda + acol);
    float4 b = *(const float4*)(Wp + (size_t)brow*Nout + bcol);
    As[0][acol+0][arow]=a.x; As[0][acol+1][arow]=a.y;
    As[0][acol+2][arow]=a.z; As[0][acol+3][arow]=a.w;
    *(float4*)&Bs[0][brow][bcol] = b;
    __syncthreads();

    int nk = K >> 3;
    for (int kk=0; kk<nk; kk++){
        int cur = kk&1, nxt = cur^1;
        if (kk+1 < nk){
            a = *(const float4*)(Ap + (size_t)arow*lda + (kk+1)*8 + acol);
            b = *(const float4*)(Wp + (size_t)((kk+1)*8 + brow)*Nout + bcol);
        }
        #pragma unroll
        for (int k=0;k<8;k++){
            float ar[8], br[8];
            *(float4*)(ar)   = *(const float4*)&As[cur][k][tm];
            *(float4*)(ar+4) = *(const float4*)&As[cur][k][tm+4];
            *(float4*)(br)   = *(const float4*)&Bs[cur][k][tn];
            *(float4*)(br+4) = *(const float4*)&Bs[cur][k][tn+4];
            #pragma unroll
            for (int i=0;i<8;i++)
                #pragma unroll
                for (int j=0;j<8;j++)
                    acc[i][j] = fmaf(ar[i], br[j], acc[i][j]);
        }
        if (kk+1 < nk){
            As[nxt][acol+0][arow]=a.x; As[nxt][acol+1][arow]=a.y;
            As[nxt][acol+2][arow]=a.z; As[nxt][acol+3][arow]=a.w;
            *(float4*)&Bs[nxt][brow][bcol] = b;
        }
        __syncthreads();
    }

    const float* bp = bias + sp*Nout + bx*128 + tn;
    float bb[8];
    #pragma unroll
    for (int j=0;j<8;j++) bb[j] = bp[j];
    #pragma unroll
    for (int i=0;i<8;i++){
        size_t row = (size_t)by*128 + tm + i;
        float* cp = C + row*ldc + coff + bx*128 + tn;
        float vv[8];
        #pragma unroll
        for (int j=0;j<8;j++){
            float x = acc[i][j] + bb[j];
            vv[j] = act ? gelu_tanh(x) : x;
        }
        ((float4*)cp)[0] = make_float4(vv[0],vv[1],vv[2],vv[3]);
        ((float4*)cp)[1] = make_float4(vv[4],vv[5],vv[6],vv[7]);
    }
}

// ---------------- zero the merged columns (feat[:,256:384]) ----------------
__global__ void zero_kernel(int cbuf){
    float* feat = bufsel(cbuf);
    feat[(size_t)blockIdx.x*FIN + 256 + threadIdx.x] = 0.f;
}

// ---------------- symmetric edge scatter-add --------------------------------
// 32 float4 chunks per edge (NOUT=128 floats). One work item = one chunk of one edge.
__global__ void __launch_bounds__(256) scatter_kernel(int cbuf){
    float* feat = bufsel(cbuf);
    int wi = blockIdx.x*256 + threadIdx.x;   // P*32 work items
    int p = wi >> 5, q = wi & 31;
    float d = g_decay[p];
    int e0 = g_e0[p], e1 = g_e1[p];
    const float4* n4 = (const float4*)g_neigh;
    float4 v1 = n4[(size_t)e1*32 + q];
    float4 v0 = n4[(size_t)e0*32 + q];
    float* d0 = feat + (size_t)e0*FIN + 256 + q*4;
    float* d1 = feat + (size_t)e1*FIN + 256 + q*4;
    atomicAdd(d0+0, v1.x*d); atomicAdd(d0+1, v1.y*d);
    atomicAdd(d0+2, v1.z*d); atomicAdd(d0+3, v1.w*d);
    atomicAdd(d1+0, v0.x*d); atomicAdd(d1+1, v0.y*d);
    atomicAdd(d1+2, v0.z*d); atomicAdd(d1+3, v0.w*d);
}

// ---------------- final routed linear (FIN->1) + outputs -------------------
__global__ void __launch_bounds__(256) final_kernel(const int* __restrict__ species,
                                                    const float* __restrict__ Wf,
                                                    const float* __restrict__ bf,
                                                    float* __restrict__ out){
    int gt = blockIdx.x*256 + threadIdx.x;
    int i = gt >> 5, lane = gt & 31;
    if (i >= NATOMS) return;
    int s = species[i];
    int r = g_p2n[i];
    const float* f = g_feat2 + (size_t)r*FIN;
    const float* w = Wf + s*FIN;
    float sum = 0.f;
    #pragma unroll
    for (int j=0;j<12;j++){
        int k = lane + 32*j;
        sum = fmaf(f[k], w[k], sum);
    }
    #pragma unroll
    for (int o=16;o;o>>=1) sum += __shfl_xor_sync(0xffffffffu, sum, o);
    if (lane == 0){
        float pre = sum + bf[s];
        g_pre[i] = pre;
        out[2*NATOMS + i] = pre;         // pre
        out[i] = (float)s;               // species (as float)
    }
}

// ---------------- per-molecule charge redistribution ------------------------
__global__ void charge_kernel(const float* __restrict__ tq, float* __restrict__ out){
    __shared__ float ss[4];
    int b = blockIdx.x, a = threadIdx.x;
    float p = g_pre[b*NA + a];
    float v = p;
    #pragma unroll
    for (int o=16;o;o>>=1) v += __shfl_xor_sync(0xffffffffu, v, o);
    int w = a>>5, lane = a&31;
    if (lane == 0) ss[w] = v;
    __syncthreads();
    float sum = ss[0]+ss[1]+ss[2]+ss[3];
    out[NATOMS + b*NA + a] = p + (tq[b] - sum)*(1.0f/128.0f);
}

// ---------------- launch ----------------------------------------------------
extern "C" void kernel_launch(void* const* d_in, const int* in_sizes, int n_in,
                              void* d_out, int out_size){
    const int*   species = (const int*)  d_in[0];
    const float* aev     = (const float*)d_in[1];
    const int*   ai12    = (const int*)  d_in[2];
    const float* dist    = (const float*)d_in[3];
    const float* tq      = (const float*)d_in[4];
    const float* Wm0     = (const float*)d_in[5];
    const float* bm0     = (const float*)d_in[6];
    const float* Wn0     = (const float*)d_in[7];
    const float* bn0     = (const float*)d_in[8];
    const float* Wm1     = (const float*)d_in[9];
    const float* bm1     = (const float*)d_in[10];
    const float* Wn1     = (const float*)d_in[11];
    const float* bn1     = (const float*)d_in[12];
    const float* Wf      = (const float*)d_in[13];
    const float* bf      = (const float*)d_in[14];
    const float* factor  = (const float*)d_in[15];
    const float* prefac  = (const float*)d_in[16];
    float* out = (float*)d_out;

    perm_kernel  <<<1, 1024>>>(species);
    gather_kernel<<<NPAD, 256>>>(aev);
    edge_kernel  <<<NP/256, 256>>>(ai12, dist, factor, prefac);

    // pass 0
    gemm_kernel<<<dim3(2, NT), 256>>>(0, AEV, Wm0, bm0, 1, FIN, 0, AEV, MO, 1);
    gemm_kernel<<<dim3(1, NT), 256>>>(1, FIN, Wn0, bn0, 3, NOUT, 0, MO, NOUT, 1);
    zero_kernel   <<<NPAD, 128>>>(1);
    scatter_kernel<<<NP*32/256, 256>>>(1);

    // pass 1
    gemm_kernel<<<dim3(2, NT), 256>>>(1, FIN, Wm1, bm1, 2, FIN, 0, FIN, MO, 1);
    gemm_kernel<<<dim3(1, NT), 256>>>(2, FIN, Wn1, bn1, 3, NOUT, 0, MO, NOUT, 1);
    zero_kernel   <<<NPAD, 128>>>(2);
    scatter_kernel<<<NP*32/256, 256>>>(2);

    // outputs
    final_kernel <<<NATOMS*32/256, 256>>>(species, Wf, bf, out);
    charge_kernel<<<NB, NA>>>(tq, out);
}

// round 4
// speedup vs baseline: 1.4299x; 1.4299x over previous
#include <cuda_runtime.h>
#include <cuda_bf16.h>
#include <math.h>
#include <stdint.h>

#define NB     256
#define NA     128
#define NATOMS 32768
#define AEV    1008
#define AEVP   1024
#define MO     256
#define NOUT   128
#define FIN    384
#define NP     262144
#define NSP    4
#define NPAD   33280
#define NT     (NPAD/128)

// ---------------- scratch (device globals) ----------------------------------
__device__ __align__(16) __nv_bfloat16 g_ah[(size_t)NPAD*AEVP];
__device__ __align__(16) __nv_bfloat16 g_al[(size_t)NPAD*AEVP];
__device__ __align__(16) __nv_bfloat16 g_f1h[(size_t)NPAD*FIN];
__device__ __align__(16) __nv_bfloat16 g_f1l[(size_t)NPAD*FIN];
__device__ __align__(16) __nv_bfloat16 g_f2h[(size_t)NPAD*MO];
__device__ __align__(16) __nv_bfloat16 g_f2l[(size_t)NPAD*MO];
__device__ float g_feat2[(size_t)NPAD*FIN];     // fp32: internal1 | merged (also temp merged0)
__device__ float g_neigh[(size_t)NPAD*NOUT];
__device__ float g_decay[NP];
__device__ int   g_e0[NP], g_e1[NP];
__device__ int   g_p2n[NATOMS];
__device__ int   g_n2o[NPAD];
__device__ int   g_tilesp[NT];
__device__ float g_pre[NATOMS];
// transposed + hi/lo-split weights: [S][Nout][Kpad]
__device__ __align__(16) __nv_bfloat16 g_wm0h[(size_t)NSP*MO*AEVP],  g_wm0l[(size_t)NSP*MO*AEVP];
__device__ __align__(16) __nv_bfloat16 g_wn0h[(size_t)NSP*NOUT*MO],  g_wn0l[(size_t)NSP*NOUT*MO];
__device__ __align__(16) __nv_bfloat16 g_wm1h[(size_t)NSP*MO*FIN],   g_wm1l[(size_t)NSP*MO*FIN];
__device__ __align__(16) __nv_bfloat16 g_wn1h[(size_t)NSP*NOUT*MO],  g_wn1l[(size_t)NSP*NOUT*MO];

// ---------------- small helpers ---------------------------------------------
__device__ __forceinline__ uint32_t smem_u32(const void* p){
    uint32_t a;
    asm("{ .reg .u64 t; cvta.to.shared.u64 t, %1; cvt.u32.u64 %0, t; }" : "=r"(a) : "l"(p));
    return a;
}
__device__ __forceinline__ void cp16(uint32_t dst, const void* src){
    asm volatile("cp.async.cg.shared.global [%0], [%1], 16;" :: "r"(dst), "l"(src) : "memory");
}
__device__ __forceinline__ void cp_commit(){
    asm volatile("cp.async.commit_group;" ::: "memory");
}
template<int N> __device__ __forceinline__ void cp_wait(){
    asm volatile("cp.async.wait_group %0;" :: "n"(N) : "memory");
}
__device__ __forceinline__ void ldsm4(uint32_t* r, uint32_t addr){
    asm volatile("ldmatrix.sync.aligned.m8n8.x4.shared.b16 {%0,%1,%2,%3}, [%4];"
        : "=r"(r[0]),"=r"(r[1]),"=r"(r[2]),"=r"(r[3]) : "r"(addr));
}
__device__ __forceinline__ void mma16816(float* d, const uint32_t* a, uint32_t b0, uint32_t b1){
    asm volatile("mma.sync.aligned.m16n8k16.row.col.f32.bf16.bf16.f32 "
        "{%0,%1,%2,%3}, {%4,%5,%6,%7}, {%8,%9}, {%0,%1,%2,%3};"
        : "+f"(d[0]),"+f"(d[1]),"+f"(d[2]),"+f"(d[3])
        : "r"(a[0]),"r"(a[1]),"r"(a[2]),"r"(a[3]), "r"(b0),"r"(b1));
}
__device__ __forceinline__ float gelu_tanh(float x){
    float t = tanhf(0.7978845608028654f * (x + 0.044715f * x * x * x));
    return 0.5f * x * (1.0f + t);
}
__device__ __forceinline__ void split_hl(float x, __nv_bfloat16& h, __nv_bfloat16& l){
    h = __float2bfloat16(x);
    l = __float2bfloat16(x - __bfloat162float(h));
}

// ---------------- permutation: deterministic species grouping ---------------
__global__ void __launch_bounds__(1024) perm_kernel(const int* __restrict__ species){
    __shared__ int sc[NSP][1024];
    __shared__ int stot[NSP];
    __shared__ int sbase[NSP+1];
    int t = threadIdx.x;
    for (int r = t; r < NPAD; r += 1024) g_n2o[r] = -1;
    int c0=0,c1=0,c2=0,c3=0;
    int b0 = t*32;
    #pragma unroll
    for (int j=0;j<32;j++){
        int s = species[b0+j];
        c0 += (s==0); c1 += (s==1); c2 += (s==2); c3 += (s==3);
    }
    sc[0][t]=c0; sc[1][t]=c1; sc[2][t]=c2; sc[3][t]=c3;
    __syncthreads();
    if (t < NSP){
        int run = 0;
        for (int i=0;i<1024;i++){ int v=sc[t][i]; sc[t][i]=run; run+=v; }
        stot[t]=run;
    }
    __syncthreads();
    if (t==0){
        int b=0;
        for (int s=0;s<NSP;s++){ sbase[s]=b; b += ((stot[s]+127)>>7)<<7; }
        sbase[NSP]=b;
        for (int tt=0; tt<NT; tt++){
            int rs = tt*128; int sp=0;
            for (int s=1;s<NSP;s++) if (rs >= sbase[s]) sp=s;
            g_tilesp[tt]=sp;
        }
    }
    __syncthreads();
    int run2[NSP] = {0,0,0,0};
    for (int j=0;j<32;j++){
        int i = b0+j; int s = species[i];
        int pos = sbase[s] + sc[s][t] + run2[s];
        run2[s]++;
        g_p2n[i]=pos; g_n2o[pos]=i;
    }
}

// ---------------- gather AEV rows -> permuted bf16 hi/lo --------------------
__global__ void __launch_bounds__(256) gather_split_kernel(const float* __restrict__ aev){
    int r = blockIdx.x;
    int src = g_n2o[r];
    int col = threadIdx.x * 4;
    float4 v = make_float4(0.f,0.f,0.f,0.f);
    if (src >= 0 && col < AEV) v = *(const float4*)(aev + (size_t)src*AEV + col);
    float a[4] = {v.x, v.y, v.z, v.w};
    __nv_bfloat16 h[4], l[4];
    #pragma unroll
    for (int j=0;j<4;j++) split_hl(a[j], h[j], l[j]);
    *(uint64_t*)(g_ah + (size_t)r*AEVP + col) = *(const uint64_t*)h;
    *(uint64_t*)(g_al + (size_t)r*AEVP + col) = *(const uint64_t*)l;
}

// ---------------- weight transpose + split: W[S][K][N] -> T[S][N][Kpad] ----
__global__ void __launch_bounds__(256) wprep_kernel(const float* __restrict__ W,
                                                    __nv_bfloat16* __restrict__ Th,
                                                    __nv_bfloat16* __restrict__ Tl,
                                                    int K, int Nout, int Kpad){
    long idx = (long)blockIdx.x*256 + threadIdx.x;
    long total = (long)NSP*Nout*Kpad;
    if (idx >= total) return;
    int k = idx % Kpad;
    int n = (idx / Kpad) % Nout;
    int s = idx / ((long)Kpad*Nout);
    float v = (k < K) ? W[((size_t)s*K + k)*Nout + n] : 0.f;
    __nv_bfloat16 h, l; split_hl(v, h, l);
    Th[idx] = h; Tl[idx] = l;
}

// ---------------- edges: decay + endpoint remap -----------------------------
__global__ void edge_kernel(const int* __restrict__ ai,
                            const float* __restrict__ dist,
                            const float* __restrict__ fa,
                            const float* __restrict__ pf){
    int p = blockIdx.x*256 + threadIdx.x;
    float d = dist[p];
    float factor = fa[0], pre = pf[0];
    float x = fminf(fmaxf(d*(1.0f/5.2f), 0.0f), 1.0f - 1e-6f);
    float f = (d < 5.2f) ? expf(1.0f - 1.0f/(1.0f - x*x)) : 0.0f;
    g_decay[p] = pre*pre*expf(-factor*factor*d)*f;
    g_e0[p] = g_p2n[ai[p]];
    g_e1[p] = g_p2n[ai[NP + p]];
}

// ---------------- HMMA GEMM: C[128 x 128-tile] = A @ W^T, bf16 hi/lo 3-pass -
// A: hi/lo bf16 [NPAD x lda] row-major. W: hi/lo bf16 [S][Nout][K] (K-major).
// grid = (Nout/128, NT). 8 warps: 4 along M (32 rows), 2 along N (64 cols).
#define PITCH 80
#define BUFSZ (128*PITCH)
__global__ void __launch_bounds__(256) tgemm_kernel(
    const __nv_bfloat16* __restrict__ Ah, const __nv_bfloat16* __restrict__ Al, int lda,
    const __nv_bfloat16* __restrict__ Wh, const __nv_bfloat16* __restrict__ Wl,
    const float* __restrict__ bias,
    int K, int Nout,
    float* C32, int ldc32,
    __nv_bfloat16* Ch, __nv_bfloat16* Cl, int ldcb,
    int act)
{
    __shared__ __align__(128) uint8_t sm[4*BUFSZ];  // A0,A1,B0,B1
    uint32_t smA = smem_u32(sm);
    uint32_t smB = smA + 2*BUFSZ;

    int tid = threadIdx.x, lane = tid & 31, wid = tid >> 5;
    int wm = wid & 3, wn = wid >> 2;
    int bx = blockIdx.x, by = blockIdx.y;
    int sp = g_tilesp[by];

    const __nv_bfloat16* AhR = Ah + (size_t)by*128*lda;
    const __nv_bfloat16* AlR = Al + (size_t)by*128*lda;
    const __nv_bfloat16* WhS = Wh + ((size_t)sp*Nout + bx*128)*K;
    const __nv_bfloat16* WlS = Wl + ((size_t)sp*Nout + bx*128)*K;

    float d[2][8][4];
    #pragma unroll
    for (int i=0;i<2;i++)
        #pragma unroll
        for (int j=0;j<8;j++)
            #pragma unroll
            for (int q=0;q<4;q++) d[i][j][q]=0.f;

    int nkc = K >> 5;        // 32-wide K chunks per phase
    int nch = 3*nkc;

    // per-thread load slots: 4 x cp16 (A: items 0..511, B: 512..1023)
    int itRow[4], itSeg[4], itB[4];
    #pragma unroll
    for (int t=0;t<4;t++){
        int it = tid + t*256;
        itB[t] = it >> 9;
        int j = it & 511;
        itRow[t] = j >> 2; itSeg[t] = j & 3;
    }

    // ldmatrix per-thread offsets
    uint32_t aoff = (uint32_t)((wm*32 + (lane & 15))*PITCH + ((lane >> 4) & 1)*16);
    uint32_t boff = (uint32_t)((wn*64 + (lane & 7) + ((lane >> 4) & 1)*8)*PITCH + ((lane >> 3) & 1)*16);

    // chunk load helper (macro-ish lambda)
    auto load_chunk = [&](int c, int buf){
        int p = c / nkc, kc = c % nkc;
        const __nv_bfloat16* As = (p == 1) ? AlR : AhR;
        const __nv_bfloat16* Bs = (p == 2) ? WlS : WhS;
        uint32_t dA = smA + buf*BUFSZ;
        uint32_t dB = smB + buf*BUFSZ;
        #pragma unroll
        for (int t=0;t<4;t++){
            int row = itRow[t], seg = itSeg[t];
            const __nv_bfloat16* s = (itB[t] ? Bs + (size_t)row*K : As + (size_t)row*lda)
                                     + kc*32 + seg*8;
            uint32_t dst = (itB[t] ? dB : dA) + row*PITCH + seg*16;
            cp16(dst, s);
        }
        cp_commit();
    };

    load_chunk(0, 0);
    for (int c=0; c<nch; c++){
        int buf = c & 1;
        if (c+1 < nch){ load_chunk(c+1, buf^1); cp_wait<1>(); }
        else cp_wait<0>();
        __syncthreads();
        uint32_t aBase = smA + buf*BUFSZ + aoff;
        uint32_t bBase = smB + buf*BUFSZ + boff;
        #pragma unroll
        for (int ks=0; ks<2; ks++){
            uint32_t a[2][4], b[4][4];
            #pragma unroll
            for (int mi=0; mi<2; mi++) ldsm4(a[mi], aBase + mi*16*PITCH + ks*32);
            #pragma unroll
            for (int np_=0; np_<4; np_++) ldsm4(b[np_], bBase + np_*16*PITCH + ks*32);
            #pragma unroll
            for (int mi=0; mi<2; mi++)
                #pragma unroll
                for (int nj=0; nj<8; nj++)
                    mma16816(d[mi][nj], a[mi], b[nj>>1][(nj&1)*2], b[nj>>1][(nj&1)*2+1]);
        }
        __syncthreads();
    }

    // epilogue: bias + gelu + stores
    const float* bp = bias + sp*Nout + bx*128 + wn*64;
    int rowLo = wm*32 + (lane >> 2);
    int colCta = bx*128 + wn*64;
    #pragma unroll
    for (int mi=0; mi<2; mi++){
        #pragma unroll
        for (int nj=0; nj<8; nj++){
            int c0 = nj*8 + 2*(lane & 3);
            float b0 = bp[c0], b1 = bp[c0+1];
            #pragma unroll
            for (int h=0; h<2; h++){
                size_t gr = (size_t)by*128 + rowLo + mi*16 + h*8;
                float x0 = d[mi][nj][2*h]   + b0;
                float x1 = d[mi][nj][2*h+1] + b1;
                if (act){ x0 = gelu_tanh(x0); x1 = gelu_tanh(x1); }
                int col = colCta + c0;
                if (C32){
                    *(float2*)(C32 + gr*ldc32 + col) = make_float2(x0, x1);
                }
                if (Ch){
                    __nv_bfloat16 h0,l0,h1,l1;
                    split_hl(x0,h0,l0); split_hl(x1,h1,l1);
                    uint32_t hh = (uint32_t)__bfloat16_as_ushort(h0) |
                                  ((uint32_t)__bfloat16_as_ushort(h1) << 16);
                    uint32_t ll = (uint32_t)__bfloat16_as_ushort(l0) |
                                  ((uint32_t)__bfloat16_as_ushort(l1) << 16);
                    *(uint32_t*)(Ch + gr*ldcb + col) = hh;
                    *(uint32_t*)(Cl + gr*ldcb + col) = ll;
                }
            }
        }
    }
}

// ---------------- zero merged columns of g_feat2 ----------------------------
__global__ void zero_kernel(){
    g_feat2[(size_t)blockIdx.x*FIN + 256 + threadIdx.x] = 0.f;
}

// ---------------- symmetric edge scatter-add into g_feat2[:,256:384] --------
__global__ void __launch_bounds__(256) scatter_kernel(){
    int wi = blockIdx.x*256 + threadIdx.x;   // NP*32 work items
    int p = wi >> 5, q = wi & 31;
    float d = g_decay[p];
    int e0 = g_e0[p], e1 = g_e1[p];
    const float4* n4 = (const float4*)g_neigh;
    float4 v1 = n4[(size_t)e1*32 + q];
    float4 v0 = n4[(size_t)e0*32 + q];
    float* d0 = g_feat2 + (size_t)e0*FIN + 256 + q*4;
    float* d1 = g_feat2 + (size_t)e1*FIN + 256 + q*4;
    atomicAdd(d0+0, v1.x*d); atomicAdd(d0+1, v1.y*d);
    atomicAdd(d0+2, v1.z*d); atomicAdd(d0+3, v1.w*d);
    atomicAdd(d1+0, v0.x*d); atomicAdd(d1+1, v0.y*d);
    atomicAdd(d1+2, v0.z*d); atomicAdd(d1+3, v0.w*d);
}

// ---------------- split merged (fp32) -> f1 hi/lo cols 256..383 -------------
__global__ void __launch_bounds__(256) split_merge_kernel(){
    long idx = (long)blockIdx.x*256 + threadIdx.x;     // NPAD*128
    int r = idx >> 7, cidx = idx & 127;
    float x = g_feat2[(size_t)r*FIN + 256 + cidx];
    __nv_bfloat16 h, l; split_hl(x, h, l);
    g_f1h[(size_t)r*FIN + 256 + cidx] = h;
    g_f1l[(size_t)r*FIN + 256 + cidx] = l;
}

// ---------------- final routed linear (FIN->1) + outputs --------------------
__global__ void __launch_bounds__(256) final_kernel(const int* __restrict__ species,
                                                    const float* __restrict__ Wf,
                                                    const float* __restrict__ bf,
                                                    float* __restrict__ out){
    int gt = blockIdx.x*256 + threadIdx.x;
    int i = gt >> 5, lane = gt & 31;
    if (i >= NATOMS) return;
    int s = species[i];
    int r = g_p2n[i];
    const float* f = g_feat2 + (size_t)r*FIN;
    const float* w = Wf + s*FIN;
    float sum = 0.f;
    #pragma unroll
    for (int j=0;j<12;j++){
        int k = lane + 32*j;
        sum = fmaf(f[k], w[k], sum);
    }
    #pragma unroll
    for (int o=16;o;o>>=1) sum += __shfl_xor_sync(0xffffffffu, sum, o);
    if (lane == 0){
        float pre = sum + bf[s];
        g_pre[i] = pre;
        out[2*NATOMS + i] = pre;
        out[i] = (float)s;
    }
}

// ---------------- per-molecule charge redistribution -------------------------
__global__ void charge_kernel(const float* __restrict__ tq, float* __restrict__ out){
    __shared__ float ss[4];
    int b = blockIdx.x, a = threadIdx.x;
    float p = g_pre[b*NA + a];
    float v = p;
    #pragma unroll
    for (int o=16;o;o>>=1) v += __shfl_xor_sync(0xffffffffu, v, o);
    int w = a>>5, lane = a&31;
    if (lane == 0) ss[w] = v;
    __syncthreads();
    float sum = ss[0]+ss[1]+ss[2]+ss[3];
    out[NATOMS + b*NA + a] = p + (tq[b] - sum)*(1.0f/128.0f);
}

// ---------------- launch -----------------------------------------------------
extern "C" void kernel_launch(void* const* d_in, const int* in_sizes, int n_in,
                              void* d_out, int out_size){
    const int*   species = (const int*)  d_in[0];
    const float* aev     = (const float*)d_in[1];
    const int*   ai12    = (const int*)  d_in[2];
    const float* dist    = (const float*)d_in[3];
    const float* tq      = (const float*)d_in[4];
    const float* Wm0     = (const float*)d_in[5];
    const float* bm0     = (const float*)d_in[6];
    const float* Wn0     = (const float*)d_in[7];
    const float* bn0     = (const float*)d_in[8];
    const float* Wm1     = (const float*)d_in[9];
    const float* bm1     = (const float*)d_in[10];
    const float* Wn1     = (const float*)d_in[11];
    const float* bn1     = (const float*)d_in[12];
    const float* Wf      = (const float*)d_in[13];
    const float* bf      = (const float*)d_in[14];
    const float* factor  = (const float*)d_in[15];
    const float* prefac  = (const float*)d_in[16];
    float* out = (float*)d_out;

    // resolve device-global addresses (host side, capture-safe)
    __nv_bfloat16 *ah, *al, *f1h, *f1l, *f2h, *f2l;
    __nv_bfloat16 *wm0h, *wm0l, *wn0h, *wn0l, *wm1h, *wm1l, *wn1h, *wn1l;
    float *feat2, *neigh;
    cudaGetSymbolAddress((void**)&ah,   g_ah);
    cudaGetSymbolAddress((void**)&al,   g_al);
    cudaGetSymbolAddress((void**)&f1h,  g_f1h);
    cudaGetSymbolAddress((void**)&f1l,  g_f1l);
    cudaGetSymbolAddress((void**)&f2h,  g_f2h);
    cudaGetSymbolAddress((void**)&f2l,  g_f2l);
    cudaGetSymbolAddress((void**)&wm0h, g_wm0h);
    cudaGetSymbolAddress((void**)&wm0l, g_wm0l);
    cudaGetSymbolAddress((void**)&wn0h, g_wn0h);
    cudaGetSymbolAddress((void**)&wn0l, g_wn0l);
    cudaGetSymbolAddress((void**)&wm1h, g_wm1h);
    cudaGetSymbolAddress((void**)&wm1l, g_wm1l);
    cudaGetSymbolAddress((void**)&wn1h, g_wn1h);
    cudaGetSymbolAddress((void**)&wn1l, g_wn1l);
    cudaGetSymbolAddress((void**)&feat2, g_feat2);
    cudaGetSymbolAddress((void**)&neigh, g_neigh);

    perm_kernel        <<<1, 1024>>>(species);
    gather_split_kernel<<<NPAD, 256>>>(aev);
    edge_kernel        <<<NP/256, 256>>>(ai12, dist, factor, prefac);
    wprep_kernel<<<(NSP*MO*AEVP)/256, 256>>>(Wm0, wm0h, wm0l, AEV, MO, AEVP);
    wprep_kernel<<<(NSP*NOUT*MO)/256, 256>>>(Wn0, wn0h, wn0l, MO, NOUT, MO);
    wprep_kernel<<<(NSP*MO*FIN)/256, 256>>>(Wm1, wm1h, wm1l, FIN, MO, FIN);
    wprep_kernel<<<(NSP*NOUT*MO)/256, 256>>>(Wn1, wn1h, wn1l, MO, NOUT, MO);

    // pass 0
    tgemm_kernel<<<dim3(2, NT), 256>>>(ah, al, AEVP, wm0h, wm0l, bm0,
                                       AEVP, MO, (float*)0, 0, f1h, f1l, FIN, 1);
    tgemm_kernel<<<dim3(1, NT), 256>>>(f1h, f1l, FIN, wn0h, wn0l, bn0,
                                       MO, NOUT, neigh, NOUT,
                                       (__nv_bfloat16*)0, (__nv_bfloat16*)0, 0, 1);
    zero_kernel        <<<NPAD, 128>>>();
    scatter_kernel     <<<NP*32/256, 256>>>();
    split_merge_kernel <<<NPAD*128/256, 256>>>();

    // pass 1
    tgemm_kernel<<<dim3(2, NT), 256>>>(f1h, f1l, FIN, wm1h, wm1l, bm1,
                                       FIN, MO, feat2, FIN, f2h, f2l, MO, 1);
    tgemm_kernel<<<dim3(1, NT), 256>>>(f2h, f2l, MO, wn1h, wn1l, bn1,
                                       MO, NOUT, neigh, NOUT,
                                       (__nv_bfloat16*)0, (__nv_bfloat16*)0, 0, 1);
    zero_kernel        <<<NPAD, 128>>>();
    scatter_kernel     <<<NP*32/256, 256>>>();

    // outputs
    final_kernel <<<NATOMS*32/256, 256>>>(species, Wf, bf, out);
    charge_kernel<<<NB, NA>>>(tq, out);
}

// round 5
// speedup vs baseline: 1.8513x; 1.2947x over previous
#include <cuda_runtime.h>
#include <cuda_bf16.h>
#include <math.h>
#include <stdint.h>

#define NB     256
#define NA     128
#define NATOMS 32768
#define AEV    1008
#define AEVP   1024
#define MO     256
#define NOUT   128
#define FIN    384
#define NP     262144
#define NSP    4
#define NPAD   33280
#define NT     (NPAD/128)

// ---------------- scratch (device globals) ----------------------------------
__device__ __align__(16) __nv_bfloat16 g_ah[(size_t)NPAD*AEVP];
__device__ __align__(16) __nv_bfloat16 g_al[(size_t)NPAD*AEVP];
__device__ __align__(16) __nv_bfloat16 g_f1h[(size_t)NPAD*FIN];
__device__ __align__(16) __nv_bfloat16 g_f1l[(size_t)NPAD*FIN];
__device__ __align__(16) __nv_bfloat16 g_f2h[(size_t)NPAD*MO];
__device__ __align__(16) __nv_bfloat16 g_f2l[(size_t)NPAD*MO];
__device__ float g_feat2[(size_t)NPAD*FIN];     // fp32: internal1 | merged1
__device__ float g_neigh[(size_t)NPAD*NOUT];
__device__ float g_decay[NP];
__device__ int   g_e0[NP], g_e1[NP];
__device__ int   g_p2n[NATOMS];
__device__ int   g_n2o[NPAD];
__device__ int   g_tilesp[NT];
__device__ float g_pre[NATOMS];
// CSR adjacency (rebuilt every launch)
__device__ int   g_deg[NPAD];
__device__ int   g_roff[NPAD+1];
__device__ int   g_cur[NPAD];
__device__ int   g_nbr[2*NP];
__device__ float g_w[2*NP];
// transposed + hi/lo-split weights: [S][Nout][Kpad]
__device__ __align__(16) __nv_bfloat16 g_wm0h[(size_t)NSP*MO*AEVP],  g_wm0l[(size_t)NSP*MO*AEVP];
__device__ __align__(16) __nv_bfloat16 g_wn0h[(size_t)NSP*NOUT*MO],  g_wn0l[(size_t)NSP*NOUT*MO];
__device__ __align__(16) __nv_bfloat16 g_wm1h[(size_t)NSP*MO*FIN],   g_wm1l[(size_t)NSP*MO*FIN];
__device__ __align__(16) __nv_bfloat16 g_wn1h[(size_t)NSP*NOUT*MO],  g_wn1l[(size_t)NSP*NOUT*MO];

// ---------------- small helpers ---------------------------------------------
__device__ __forceinline__ uint32_t smem_u32(const void* p){
    uint32_t a;
    asm("{ .reg .u64 t; cvta.to.shared.u64 t, %1; cvt.u32.u64 %0, t; }" : "=r"(a) : "l"(p));
    return a;
}
__device__ __forceinline__ void cp16(uint32_t dst, const void* src){
    asm volatile("cp.async.cg.shared.global [%0], [%1], 16;" :: "r"(dst), "l"(src) : "memory");
}
__device__ __forceinline__ void cp_commit(){
    asm volatile("cp.async.commit_group;" ::: "memory");
}
template<int N> __device__ __forceinline__ void cp_wait(){
    asm volatile("cp.async.wait_group %0;" :: "n"(N) : "memory");
}
__device__ __forceinline__ void ldsm4(uint32_t* r, uint32_t addr){
    asm volatile("ldmatrix.sync.aligned.m8n8.x4.shared.b16 {%0,%1,%2,%3}, [%4];"
        : "=r"(r[0]),"=r"(r[1]),"=r"(r[2]),"=r"(r[3]) : "r"(addr));
}
__device__ __forceinline__ void mma16816(float* d, const uint32_t* a, uint32_t b0, uint32_t b1){
    asm volatile("mma.sync.aligned.m16n8k16.row.col.f32.bf16.bf16.f32 "
        "{%0,%1,%2,%3}, {%4,%5,%6,%7}, {%8,%9}, {%0,%1,%2,%3};"
        : "+f"(d[0]),"+f"(d[1]),"+f"(d[2]),"+f"(d[3])
        : "r"(a[0]),"r"(a[1]),"r"(a[2]),"r"(a[3]), "r"(b0),"r"(b1));
}
__device__ __forceinline__ float gelu_tanh(float x){
    float t = tanhf(0.7978845608028654f * (x + 0.044715f * x * x * x));
    return 0.5f * x * (1.0f + t);
}
__device__ __forceinline__ void split_hl(float x, __nv_bfloat16& h, __nv_bfloat16& l){
    h = __float2bfloat16(x);
    l = __float2bfloat16(x - __bfloat162float(h));
}

// ---------------- permutation: deterministic species grouping ---------------
__global__ void __launch_bounds__(1024) perm_kernel(const int* __restrict__ species){
    __shared__ int sc[NSP][1024];
    __shared__ int stot[NSP];
    __shared__ int sbase[NSP+1];
    int t = threadIdx.x;
    for (int r = t; r < NPAD; r += 1024){ g_n2o[r] = -1; g_deg[r] = 0; }
    int c0=0,c1=0,c2=0,c3=0;
    int b0 = t*32;
    #pragma unroll
    for (int j=0;j<32;j++){
        int s = species[b0+j];
        c0 += (s==0); c1 += (s==1); c2 += (s==2); c3 += (s==3);
    }
    sc[0][t]=c0; sc[1][t]=c1; sc[2][t]=c2; sc[3][t]=c3;
    __syncthreads();
    if (t < NSP){
        int run = 0;
        for (int i=0;i<1024;i++){ int v=sc[t][i]; sc[t][i]=run; run+=v; }
        stot[t]=run;
    }
    __syncthreads();
    if (t==0){
        int b=0;
        for (int s=0;s<NSP;s++){ sbase[s]=b; b += ((stot[s]+127)>>7)<<7; }
        sbase[NSP]=b;
        for (int tt=0; tt<NT; tt++){
            int rs = tt*128; int sp=0;
            for (int s=1;s<NSP;s++) if (rs >= sbase[s]) sp=s;
            g_tilesp[tt]=sp;
        }
    }
    __syncthreads();
    int run2[NSP] = {0,0,0,0};
    for (int j=0;j<32;j++){
        int i = b0+j; int s = species[i];
        int pos = sbase[s] + sc[s][t] + run2[s];
        run2[s]++;
        g_p2n[i]=pos; g_n2o[pos]=i;
    }
}

// ---------------- gather AEV rows -> permuted bf16 hi/lo --------------------
__global__ void __launch_bounds__(256) gather_split_kernel(const float* __restrict__ aev){
    int r = blockIdx.x;
    int src = g_n2o[r];
    int col = threadIdx.x * 4;
    float4 v = make_float4(0.f,0.f,0.f,0.f);
    if (src >= 0 && col < AEV) v = *(const float4*)(aev + (size_t)src*AEV + col);
    float a[4] = {v.x, v.y, v.z, v.w};
    __nv_bfloat16 h[4], l[4];
    #pragma unroll
    for (int j=0;j<4;j++) split_hl(a[j], h[j], l[j]);
    *(uint64_t*)(g_ah + (size_t)r*AEVP + col) = *(const uint64_t*)h;
    *(uint64_t*)(g_al + (size_t)r*AEVP + col) = *(const uint64_t*)l;
}

// ---------------- weight transpose + split: W[S][K][N] -> T[S][N][Kpad] ----
__global__ void __launch_bounds__(256) wprep_kernel(const float* __restrict__ W,
                                                    __nv_bfloat16* __restrict__ Th,
                                                    __nv_bfloat16* __restrict__ Tl,
                                                    int K, int Nout, int Kpad){
    long idx = (long)blockIdx.x*256 + threadIdx.x;
    long total = (long)NSP*Nout*Kpad;
    if (idx >= total) return;
    int k = idx % Kpad;
    int n = (idx / Kpad) % Nout;
    int s = idx / ((long)Kpad*Nout);
    float v = (k < K) ? W[((size_t)s*K + k)*Nout + n] : 0.f;
    __nv_bfloat16 h, l; split_hl(v, h, l);
    Th[idx] = h; Tl[idx] = l;
}

// ---------------- edges: decay + endpoint remap + degree count ---------------
__global__ void edge_kernel(const int* __restrict__ ai,
                            const float* __restrict__ dist,
                            const float* __restrict__ fa,
                            const float* __restrict__ pf){
    int p = blockIdx.x*256 + threadIdx.x;
    float d = dist[p];
    float factor = fa[0], pre = pf[0];
    float x = fminf(fmaxf(d*(1.0f/5.2f), 0.0f), 1.0f - 1e-6f);
    float f = (d < 5.2f) ? expf(1.0f - 1.0f/(1.0f - x*x)) : 0.0f;
    g_decay[p] = pre*pre*expf(-factor*factor*d)*f;
    int e0 = g_p2n[ai[p]];
    int e1 = g_p2n[ai[NP + p]];
    g_e0[p] = e0; g_e1[p] = e1;
    atomicAdd(&g_deg[e0], 1);
    atomicAdd(&g_deg[e1], 1);
}

// ---------------- exclusive scan of degrees -> row offsets ------------------
#define SCAN_CH 33   // 1024*33 = 33792 >= NPAD
__global__ void __launch_bounds__(1024) scan_kernel(){
    __shared__ int wsum[32];
    int t = threadIdx.x;
    int base = t*SCAN_CH;
    int s = 0;
    for (int j=0;j<SCAN_CH;j++){
        int idx = base+j;
        if (idx < NPAD) s += g_deg[idx];
    }
    int lane = t&31, w = t>>5;
    int v = s;
    #pragma unroll
    for (int o=1;o<32;o<<=1){ int u = __shfl_up_sync(~0u, v, o); if (lane>=o) v += u; }
    if (lane==31) wsum[w] = v;
    __syncthreads();
    if (w==0){
        int x = wsum[lane];
        #pragma unroll
        for (int o=1;o<32;o<<=1){ int u = __shfl_up_sync(~0u, x, o); if (lane>=o) x += u; }
        wsum[lane] = x;
    }
    __syncthreads();
    int excl = v - s + (w>0 ? wsum[w-1] : 0);
    int run = excl;
    for (int j=0;j<SCAN_CH;j++){
        int idx = base+j;
        if (idx < NPAD){
            g_roff[idx] = run;
            g_cur[idx]  = run;
            run += g_deg[idx];
        }
    }
    if (t == 1023) g_roff[NPAD] = run;
}

// ---------------- fill CSR edge lists -----------------------------------------
__global__ void fill_kernel(){
    int p = blockIdx.x*256 + threadIdx.x;
    int e0 = g_e0[p], e1 = g_e1[p];
    float d = g_decay[p];
    int i0 = atomicAdd(&g_cur[e0], 1);
    g_nbr[i0] = e1; g_w[i0] = d;
    int i1 = atomicAdd(&g_cur[e1], 1);
    g_nbr[i1] = e0; g_w[i1] = d;
}

// ---------------- HMMA GEMM: C[128 x 128-tile] = A @ W^T, bf16 hi/lo 3-pass -
#define PITCH 80
#define BUFSZ (128*PITCH)
__global__ void __launch_bounds__(256) tgemm_kernel(
    const __nv_bfloat16* __restrict__ Ah, const __nv_bfloat16* __restrict__ Al, int lda,
    const __nv_bfloat16* __restrict__ Wh, const __nv_bfloat16* __restrict__ Wl,
    const float* __restrict__ bias,
    int K, int Nout,
    float* C32, int ldc32,
    __nv_bfloat16* Ch, __nv_bfloat16* Cl, int ldcb,
    int act)
{
    __shared__ __align__(128) uint8_t sm[4*BUFSZ];
    uint32_t smA = smem_u32(sm);
    uint32_t smB = smA + 2*BUFSZ;

    int tid = threadIdx.x, lane = tid & 31, wid = tid >> 5;
    int wm = wid & 3, wn = wid >> 2;
    int bx = blockIdx.x, by = blockIdx.y;
    int sp = g_tilesp[by];

    const __nv_bfloat16* AhR = Ah + (size_t)by*128*lda;
    const __nv_bfloat16* AlR = Al + (size_t)by*128*lda;
    const __nv_bfloat16* WhS = Wh + ((size_t)sp*Nout + bx*128)*K;
    const __nv_bfloat16* WlS = Wl + ((size_t)sp*Nout + bx*128)*K;

    float d[2][8][4];
    #pragma unroll
    for (int i=0;i<2;i++)
        #pragma unroll
        for (int j=0;j<8;j++)
            #pragma unroll
            for (int q=0;q<4;q++) d[i][j][q]=0.f;

    int nkc = K >> 5;
    int nch = 3*nkc;

    int itRow[4], itSeg[4], itB[4];
    #pragma unroll
    for (int t=0;t<4;t++){
        int it = tid + t*256;
        itB[t] = it >> 9;
        int j = it & 511;
        itRow[t] = j >> 2; itSeg[t] = j & 3;
    }

    uint32_t aoff = (uint32_t)((wm*32 + (lane & 15))*PITCH + ((lane >> 4) & 1)*16);
    uint32_t boff = (uint32_t)((wn*64 + (lane & 7) + ((lane >> 4) & 1)*8)*PITCH + ((lane >> 3) & 1)*16);

    auto load_chunk = [&](int c, int buf){
        int p = c / nkc, kc = c % nkc;
        const __nv_bfloat16* As = (p == 1) ? AlR : AhR;
        const __nv_bfloat16* Bs = (p == 2) ? WlS : WhS;
        uint32_t dA = smA + buf*BUFSZ;
        uint32_t dB = smB + buf*BUFSZ;
        #pragma unroll
        for (int t=0;t<4;t++){
            int row = itRow[t], seg = itSeg[t];
            const __nv_bfloat16* s = (itB[t] ? Bs + (size_t)row*K : As + (size_t)row*lda)
                                     + kc*32 + seg*8;
            uint32_t dst = (itB[t] ? dB : dA) + row*PITCH + seg*16;
            cp16(dst, s);
        }
        cp_commit();
    };

    load_chunk(0, 0);
    for (int c=0; c<nch; c++){
        int buf = c & 1;
        if (c+1 < nch){ load_chunk(c+1, buf^1); cp_wait<1>(); }
        else cp_wait<0>();
        __syncthreads();
        uint32_t aBase = smA + buf*BUFSZ + aoff;
        uint32_t bBase = smB + buf*BUFSZ + boff;
        #pragma unroll
        for (int ks=0; ks<2; ks++){
            uint32_t a[2][4], b[4][4];
            #pragma unroll
            for (int mi=0; mi<2; mi++) ldsm4(a[mi], aBase + mi*16*PITCH + ks*32);
            #pragma unroll
            for (int np_=0; np_<4; np_++) ldsm4(b[np_], bBase + np_*16*PITCH + ks*32);
            #pragma unroll
            for (int mi=0; mi<2; mi++)
                #pragma unroll
                for (int nj=0; nj<8; nj++)
                    mma16816(d[mi][nj], a[mi], b[nj>>1][(nj&1)*2], b[nj>>1][(nj&1)*2+1]);
        }
        __syncthreads();
    }

    const float* bp = bias + sp*Nout + bx*128 + wn*64;
    int rowLo = wm*32 + (lane >> 2);
    int colCta = bx*128 + wn*64;
    #pragma unroll
    for (int mi=0; mi<2; mi++){
        #pragma unroll
        for (int nj=0; nj<8; nj++){
            int c0 = nj*8 + 2*(lane & 3);
            float b0 = bp[c0], b1 = bp[c0+1];
            #pragma unroll
            for (int h=0; h<2; h++){
                size_t gr = (size_t)by*128 + rowLo + mi*16 + h*8;
                float x0 = d[mi][nj][2*h]   + b0;
                float x1 = d[mi][nj][2*h+1] + b1;
                if (act){ x0 = gelu_tanh(x0); x1 = gelu_tanh(x1); }
                int col = colCta + c0;
                if (C32){
                    *(float2*)(C32 + gr*ldc32 + col) = make_float2(x0, x1);
                }
                if (Ch){
                    __nv_bfloat16 h0,l0,h1,l1;
                    split_hl(x0,h0,l0); split_hl(x1,h1,l1);
                    uint32_t hh = (uint32_t)__bfloat16_as_ushort(h0) |
                                  ((uint32_t)__bfloat16_as_ushort(h1) << 16);
                    uint32_t ll = (uint32_t)__bfloat16_as_ushort(l0) |
                                  ((uint32_t)__bfloat16_as_ushort(l1) << 16);
                    *(uint32_t*)(Ch + gr*ldcb + col) = hh;
                    *(uint32_t*)(Cl + gr*ldcb + col) = ll;
                }
            }
        }
    }
}

// ---------------- CSR gather: merged[r][t] = sum_nb neigh[nb][t]*w ----------
// mode 0: write bf16 hi/lo into f1 cols 256..383; mode 1: write fp32 feat2.
__global__ void __launch_bounds__(128) mpgather_kernel(int mode){
    int r = blockIdx.x, t = threadIdx.x;
    int s = g_roff[r], e = g_roff[r+1];
    float acc = 0.f;
    int j = s;
    for (; j+1 < e; j += 2){
        int nb0 = g_nbr[j], nb1 = g_nbr[j+1];
        float w0 = g_w[j],  w1 = g_w[j+1];
        float x0 = g_neigh[(size_t)nb0*NOUT + t];
        float x1 = g_neigh[(size_t)nb1*NOUT + t];
        acc = fmaf(x0, w0, acc);
        acc = fmaf(x1, w1, acc);
    }
    if (j < e)
        acc = fmaf(g_neigh[(size_t)g_nbr[j]*NOUT + t], g_w[j], acc);
    if (mode == 0){
        __nv_bfloat16 h, l; split_hl(acc, h, l);
        g_f1h[(size_t)r*FIN + 256 + t] = h;
        g_f1l[(size_t)r*FIN + 256 + t] = l;
    } else {
        g_feat2[(size_t)r*FIN + 256 + t] = acc;
    }
}

// ---------------- final routed linear (FIN->1) + outputs --------------------
__global__ void __launch_bounds__(256) final_kernel(const int* __restrict__ species,
                                                    const float* __restrict__ Wf,
                                                    const float* __restrict__ bf,
                                                    float* __restrict__ out){
    int gt = blockIdx.x*256 + threadIdx.x;
    int i = gt >> 5, lane = gt & 31;
    if (i >= NATOMS) return;
    int s = species[i];
    int r = g_p2n[i];
    const float* f = g_feat2 + (size_t)r*FIN;
    const float* w = Wf + s*FIN;
    float sum = 0.f;
    #pragma unroll
    for (int j=0;j<12;j++){
        int k = lane + 32*j;
        sum = fmaf(f[k], w[k], sum);
    }
    #pragma unroll
    for (int o=16;o;o>>=1) sum += __shfl_xor_sync(0xffffffffu, sum, o);
    if (lane == 0){
        float pre = sum + bf[s];
        g_pre[i] = pre;
        out[2*NATOMS + i] = pre;
        out[i] = (float)s;
    }
}

// ---------------- per-molecule charge redistribution -------------------------
__global__ void charge_kernel(const float* __restrict__ tq, float* __restrict__ out){
    __shared__ float ss[4];
    int b = blockIdx.x, a = threadIdx.x;
    float p = g_pre[b*NA + a];
    float v = p;
    #pragma unroll
    for (int o=16;o;o>>=1) v += __shfl_xor_sync(0xffffffffu, v, o);
    int w = a>>5, lane = a&31;
    if (lane == 0) ss[w] = v;
    __syncthreads();
    float sum = ss[0]+ss[1]+ss[2]+ss[3];
    out[NATOMS + b*NA + a] = p + (tq[b] - sum)*(1.0f/128.0f);
}

// ---------------- launch -----------------------------------------------------
extern "C" void kernel_launch(void* const* d_in, const int* in_sizes, int n_in,
                              void* d_out, int out_size){
    const int*   species = (const int*)  d_in[0];
    const float* aev     = (const float*)d_in[1];
    const int*   ai12    = (const int*)  d_in[2];
    const float* dist    = (const float*)d_in[3];
    const float* tq      = (const float*)d_in[4];
    const float* Wm0     = (const float*)d_in[5];
    const float* bm0     = (const float*)d_in[6];
    const float* Wn0     = (const float*)d_in[7];
    const float* bn0     = (const float*)d_in[8];
    const float* Wm1     = (const float*)d_in[9];
    const float* bm1     = (const float*)d_in[10];
    const float* Wn1     = (const float*)d_in[11];
    const float* bn1     = (const float*)d_in[12];
    const float* Wf      = (const float*)d_in[13];
    const float* bf      = (const float*)d_in[14];
    const float* factor  = (const float*)d_in[15];
    const float* prefac  = (const float*)d_in[16];
    float* out = (float*)d_out;

    __nv_bfloat16 *ah, *al, *f1h, *f1l, *f2h, *f2l;
    __nv_bfloat16 *wm0h, *wm0l, *wn0h, *wn0l, *wm1h, *wm1l, *wn1h, *wn1l;
    float *feat2, *neigh;
    cudaGetSymbolAddress((void**)&ah,   g_ah);
    cudaGetSymbolAddress((void**)&al,   g_al);
    cudaGetSymbolAddress((void**)&f1h,  g_f1h);
    cudaGetSymbolAddress((void**)&f1l,  g_f1l);
    cudaGetSymbolAddress((void**)&f2h,  g_f2h);
    cudaGetSymbolAddress((void**)&f2l,  g_f2l);
    cudaGetSymbolAddress((void**)&wm0h, g_wm0h);
    cudaGetSymbolAddress((void**)&wm0l, g_wm0l);
    cudaGetSymbolAddress((void**)&wn0h, g_wn0h);
    cudaGetSymbolAddress((void**)&wn0l, g_wn0l);
    cudaGetSymbolAddress((void**)&wm1h, g_wm1h);
    cudaGetSymbolAddress((void**)&wm1l, g_wm1l);
    cudaGetSymbolAddress((void**)&wn1h, g_wn1h);
    cudaGetSymbolAddress((void**)&wn1l, g_wn1l);
    cudaGetSymbolAddress((void**)&feat2, g_feat2);
    cudaGetSymbolAddress((void**)&neigh, g_neigh);

    perm_kernel        <<<1, 1024>>>(species);
    edge_kernel        <<<NP/256, 256>>>(ai12, dist, factor, prefac);
    scan_kernel        <<<1, 1024>>>();
    fill_kernel        <<<NP/256, 256>>>();
    gather_split_kernel<<<NPAD, 256>>>(aev);
    wprep_kernel<<<(NSP*MO*AEVP)/256, 256>>>(Wm0, wm0h, wm0l, AEV, MO, AEVP);
    wprep_kernel<<<(NSP*NOUT*MO)/256, 256>>>(Wn0, wn0h, wn0l, MO, NOUT, MO);
    wprep_kernel<<<(NSP*MO*FIN)/256, 256>>>(Wm1, wm1h, wm1l, FIN, MO, FIN);
    wprep_kernel<<<(NSP*NOUT*MO)/256, 256>>>(Wn1, wn1h, wn1l, MO, NOUT, MO);

    // pass 0
    tgemm_kernel<<<dim3(2, NT), 256>>>(ah, al, AEVP, wm0h, wm0l, bm0,
                                       AEVP, MO, (float*)0, 0, f1h, f1l, FIN, 1);
    tgemm_kernel<<<dim3(1, NT), 256>>>(f1h, f1l, FIN, wn0h, wn0l, bn0,
                                       MO, NOUT, neigh, NOUT,
                                       (__nv_bfloat16*)0, (__nv_bfloat16*)0, 0, 1);
    mpgather_kernel    <<<NPAD, 128>>>(0);

    // pass 1
    tgemm_kernel<<<dim3(2, NT), 256>>>(f1h, f1l, FIN, wm1h, wm1l, bm1,
                                       FIN, MO, feat2, FIN, f2h, f2l, MO, 1);
    tgemm_kernel<<<dim3(1, NT), 256>>>(f2h, f2l, MO, wn1h, wn1l, bn1,
                                       MO, NOUT, neigh, NOUT,
                                       (__nv_bfloat16*)0, (__nv_bfloat16*)0, 0, 1);
    mpgather_kernel    <<<NPAD, 128>>>(1);

    // outputs
    final_kernel <<<NATOMS*32/256, 256>>>(species, Wf, bf, out);
    charge_kernel<<<NB, NA>>>(tq, out);
}

// round 6
// speedup vs baseline: 2.0247x; 1.0936x over previous
#include <cuda_runtime.h>
#include <cuda_bf16.h>
#include <math.h>
#include <stdint.h>

#define NB     256
#define NA     128
#define NATOMS 32768
#define AEV    1008
#define AEVP   1024
#define MO     256
#define NOUT   128
#define FIN    384
#define NP     262144
#define NSP    4
#define NPAD   33280
#define NT     (NPAD/128)

// ---------------- scratch (device globals) ----------------------------------
__device__ __align__(16) __nv_bfloat16 g_ah[(size_t)NPAD*AEVP];
__device__ __align__(16) __nv_bfloat16 g_al[(size_t)NPAD*AEVP];
__device__ __align__(16) __nv_bfloat16 g_f1h[(size_t)NPAD*FIN];
__device__ __align__(16) __nv_bfloat16 g_f1l[(size_t)NPAD*FIN];
__device__ __align__(16) __nv_bfloat16 g_f2h[(size_t)NPAD*MO];
__device__ __align__(16) __nv_bfloat16 g_f2l[(size_t)NPAD*MO];
__device__ float g_feat2[(size_t)NPAD*FIN];     // fp32: internal1 | merged1
__device__ float g_neigh[(size_t)NPAD*NOUT];
__device__ float g_decay[NP];
__device__ int   g_e0[NP], g_e1[NP];
__device__ int   g_p2n[NATOMS];
__device__ int   g_n2o[NPAD];
__device__ int   g_tilesp[NT];
__device__ float g_pre[NATOMS];
// CSR adjacency (rebuilt every launch)
__device__ int   g_deg[NPAD];
__device__ int   g_roff[NPAD+1];
__device__ int   g_cur[NPAD];
__device__ int   g_nbr[2*NP];
__device__ float g_w[2*NP];
// transposed + hi/lo-split weights: [S][Nout][Kpad]
__device__ __align__(16) __nv_bfloat16 g_wm0h[(size_t)NSP*MO*AEVP],  g_wm0l[(size_t)NSP*MO*AEVP];
__device__ __align__(16) __nv_bfloat16 g_wn0h[(size_t)NSP*NOUT*MO],  g_wn0l[(size_t)NSP*NOUT*MO];
__device__ __align__(16) __nv_bfloat16 g_wm1h[(size_t)NSP*MO*FIN],   g_wm1l[(size_t)NSP*MO*FIN];
__device__ __align__(16) __nv_bfloat16 g_wn1h[(size_t)NSP*NOUT*MO],  g_wn1l[(size_t)NSP*NOUT*MO];

// ---------------- small helpers ---------------------------------------------
__device__ __forceinline__ uint32_t smem_u32(const void* p){
    uint32_t a;
    asm("{ .reg .u64 t; cvta.to.shared.u64 t, %1; cvt.u32.u64 %0, t; }" : "=r"(a) : "l"(p));
    return a;
}
__device__ __forceinline__ void cp16(uint32_t dst, const void* src){
    asm volatile("cp.async.cg.shared.global [%0], [%1], 16;" :: "r"(dst), "l"(src) : "memory");
}
__device__ __forceinline__ void cp_commit(){
    asm volatile("cp.async.commit_group;" ::: "memory");
}
template<int N> __device__ __forceinline__ void cp_wait(){
    asm volatile("cp.async.wait_group %0;" :: "n"(N) : "memory");
}
__device__ __forceinline__ void ldsm4(uint32_t* r, uint32_t addr){
    asm volatile("ldmatrix.sync.aligned.m8n8.x4.shared.b16 {%0,%1,%2,%3}, [%4];"
        : "=r"(r[0]),"=r"(r[1]),"=r"(r[2]),"=r"(r[3]) : "r"(addr));
}
__device__ __forceinline__ void mma16816(float* d, const uint32_t* a, uint32_t b0, uint32_t b1){
    asm volatile("mma.sync.aligned.m16n8k16.row.col.f32.bf16.bf16.f32 "
        "{%0,%1,%2,%3}, {%4,%5,%6,%7}, {%8,%9}, {%0,%1,%2,%3};"
        : "+f"(d[0]),"+f"(d[1]),"+f"(d[2]),"+f"(d[3])
        : "r"(a[0]),"r"(a[1]),"r"(a[2]),"r"(a[3]), "r"(b0),"r"(b1));
}
__device__ __forceinline__ float gelu_tanh(float x){
    float t = tanhf(0.7978845608028654f * (x + 0.044715f * x * x * x));
    return 0.5f * x * (1.0f + t);
}
__device__ __forceinline__ void split_hl(float x, __nv_bfloat16& h, __nv_bfloat16& l){
    h = __float2bfloat16(x);
    l = __float2bfloat16(x - __bfloat162float(h));
}

// ---------------- permutation: deterministic species grouping ---------------
__global__ void __launch_bounds__(1024) perm_kernel(const int* __restrict__ species){
    __shared__ int sc[NSP][1024];
    __shared__ int stot[NSP];
    __shared__ int sbase[NSP+1];
    int t = threadIdx.x;
    for (int r = t; r < NPAD; r += 1024){ g_n2o[r] = -1; g_deg[r] = 0; }
    int c0=0,c1=0,c2=0,c3=0;
    int b0 = t*32;
    #pragma unroll
    for (int j=0;j<32;j++){
        int s = species[b0+j];
        c0 += (s==0); c1 += (s==1); c2 += (s==2); c3 += (s==3);
    }
    sc[0][t]=c0; sc[1][t]=c1; sc[2][t]=c2; sc[3][t]=c3;
    __syncthreads();
    if (t < NSP){
        int run = 0;
        for (int i=0;i<1024;i++){ int v=sc[t][i]; sc[t][i]=run; run+=v; }
        stot[t]=run;
    }
    __syncthreads();
    if (t==0){
        int b=0;
        for (int s=0;s<NSP;s++){ sbase[s]=b; b += ((stot[s]+127)>>7)<<7; }
        sbase[NSP]=b;
        for (int tt=0; tt<NT; tt++){
            int rs = tt*128; int sp=0;
            for (int s=1;s<NSP;s++) if (rs >= sbase[s]) sp=s;
            g_tilesp[tt]=sp;
        }
    }
    __syncthreads();
    int run2[NSP] = {0,0,0,0};
    for (int j=0;j<32;j++){
        int i = b0+j; int s = species[i];
        int pos = sbase[s] + sc[s][t] + run2[s];
        run2[s]++;
        g_p2n[i]=pos; g_n2o[pos]=i;
    }
}

// ---------------- gather AEV rows -> permuted bf16 hi/lo --------------------
__global__ void __launch_bounds__(256) gather_split_kernel(const float* __restrict__ aev){
    int r = blockIdx.x;
    int src = g_n2o[r];
    int col = threadIdx.x * 4;
    float4 v = make_float4(0.f,0.f,0.f,0.f);
    if (src >= 0 && col < AEV) v = *(const float4*)(aev + (size_t)src*AEV + col);
    float a[4] = {v.x, v.y, v.z, v.w};
    __nv_bfloat16 h[4], l[4];
    #pragma unroll
    for (int j=0;j<4;j++) split_hl(a[j], h[j], l[j]);
    *(uint64_t*)(g_ah + (size_t)r*AEVP + col) = *(const uint64_t*)h;
    *(uint64_t*)(g_al + (size_t)r*AEVP + col) = *(const uint64_t*)l;
}

// ---------------- weight transpose + split: W[S][K][N] -> T[S][N][Kpad] ----
__global__ void __launch_bounds__(256) wprep_kernel(const float* __restrict__ W,
                                                    __nv_bfloat16* __restrict__ Th,
                                                    __nv_bfloat16* __restrict__ Tl,
                                                    int K, int Nout, int Kpad){
    long idx = (long)blockIdx.x*256 + threadIdx.x;
    long total = (long)NSP*Nout*Kpad;
    if (idx >= total) return;
    int k = idx % Kpad;
    int n = (idx / Kpad) % Nout;
    int s = idx / ((long)Kpad*Nout);
    float v = (k < K) ? W[((size_t)s*K + k)*Nout + n] : 0.f;
    __nv_bfloat16 h, l; split_hl(v, h, l);
    Th[idx] = h; Tl[idx] = l;
}

// ---------------- edges: decay + endpoint remap + degree count ---------------
__global__ void edge_kernel(const int* __restrict__ ai,
                            const float* __restrict__ dist,
                            const float* __restrict__ fa,
                            const float* __restrict__ pf){
    int p = blockIdx.x*256 + threadIdx.x;
    float d = dist[p];
    float factor = fa[0], pre = pf[0];
    float x = fminf(fmaxf(d*(1.0f/5.2f), 0.0f), 1.0f - 1e-6f);
    float f = (d < 5.2f) ? expf(1.0f - 1.0f/(1.0f - x*x)) : 0.0f;
    g_decay[p] = pre*pre*expf(-factor*factor*d)*f;
    int e0 = g_p2n[ai[p]];
    int e1 = g_p2n[ai[NP + p]];
    g_e0[p] = e0; g_e1[p] = e1;
    atomicAdd(&g_deg[e0], 1);
    atomicAdd(&g_deg[e1], 1);
}

// ---------------- exclusive scan of degrees -> row offsets ------------------
#define SCAN_CH 33
__global__ void __launch_bounds__(1024) scan_kernel(){
    __shared__ int wsum[32];
    int t = threadIdx.x;
    int base = t*SCAN_CH;
    int s = 0;
    for (int j=0;j<SCAN_CH;j++){
        int idx = base+j;
        if (idx < NPAD) s += g_deg[idx];
    }
    int lane = t&31, w = t>>5;
    int v = s;
    #pragma unroll
    for (int o=1;o<32;o<<=1){ int u = __shfl_up_sync(~0u, v, o); if (lane>=o) v += u; }
    if (lane==31) wsum[w] = v;
    __syncthreads();
    if (w==0){
        int x = wsum[lane];
        #pragma unroll
        for (int o=1;o<32;o<<=1){ int u = __shfl_up_sync(~0u, x, o); if (lane>=o) x += u; }
        wsum[lane] = x;
    }
    __syncthreads();
    int excl = v - s + (w>0 ? wsum[w-1] : 0);
    int run = excl;
    for (int j=0;j<SCAN_CH;j++){
        int idx = base+j;
        if (idx < NPAD){
            g_roff[idx] = run;
            g_cur[idx]  = run;
            run += g_deg[idx];
        }
    }
    if (t == 1023) g_roff[NPAD] = run;
}

// ---------------- fill CSR edge lists -----------------------------------------
__global__ void fill_kernel(){
    int p = blockIdx.x*256 + threadIdx.x;
    int e0 = g_e0[p], e1 = g_e1[p];
    float d = g_decay[p];
    int i0 = atomicAdd(&g_cur[e0], 1);
    g_nbr[i0] = e1; g_w[i0] = d;
    int i1 = atomicAdd(&g_cur[e1], 1);
    g_nbr[i1] = e0; g_w[i1] = d;
}

// ---------------- HMMA GEMM, fused 3-phase hi/lo -----------------------------
// Per 32-wide K chunk: load ah, al, wh, wl tiles once; accumulate
// ah*wh + al*wh + ah*wl into the same fp32 accumulators.
#define PITCH 80
#define TSZ   (128*PITCH)      // 10240 B, one tile (128 rows x 32 bf16)
#define STAGE (4*TSZ)          // 40960 B: ah | al | wh | wl
__global__ void __launch_bounds__(256, 2) tgemm_kernel(
    const __nv_bfloat16* __restrict__ Ah, const __nv_bfloat16* __restrict__ Al, int lda,
    const __nv_bfloat16* __restrict__ Wh, const __nv_bfloat16* __restrict__ Wl,
    const float* __restrict__ bias,
    int K, int Nout,
    float* C32, int ldc32,
    __nv_bfloat16* Ch, __nv_bfloat16* Cl, int ldcb,
    int act)
{
    extern __shared__ __align__(128) uint8_t sm[];   // 2*STAGE dynamic
    uint32_t smBase = smem_u32(sm);

    int tid = threadIdx.x, lane = tid & 31, wid = tid >> 5;
    int wm = wid & 3, wn = wid >> 2;
    int bx = blockIdx.x, by = blockIdx.y;
    int sp = g_tilesp[by];

    const __nv_bfloat16* AhR = Ah + (size_t)by*128*lda;
    const __nv_bfloat16* AlR = Al + (size_t)by*128*lda;
    const __nv_bfloat16* WhS = Wh + ((size_t)sp*Nout + bx*128)*K;
    const __nv_bfloat16* WlS = Wl + ((size_t)sp*Nout + bx*128)*K;

    float d[2][8][4];
    #pragma unroll
    for (int i=0;i<2;i++)
        #pragma unroll
        for (int j=0;j<8;j++)
            #pragma unroll
            for (int q=0;q<4;q++) d[i][j][q]=0.f;

    int nkc = K >> 5;   // 32-wide K chunks

    // per-thread cp.async slots: 8 x 16B covering 4 tiles x 128 rows x 4 segs
    int itTile[8], itRow[8], itSeg[8];
    #pragma unroll
    for (int t=0;t<8;t++){
        int it = tid + t*256;
        itTile[t] = it >> 9;
        int j = it & 511;
        itRow[t] = j >> 2; itSeg[t] = j & 3;
    }

    uint32_t aoff = (uint32_t)((wm*32 + (lane & 15))*PITCH + ((lane >> 4) & 1)*16);
    uint32_t boff = (uint32_t)((wn*64 + (lane & 7) + ((lane >> 4) & 1)*8)*PITCH + ((lane >> 3) & 1)*16);

    auto load_chunk = [&](int kc, int buf){
        uint32_t base = smBase + (uint32_t)buf*STAGE;
        #pragma unroll
        for (int t=0;t<8;t++){
            int tile = itTile[t], row = itRow[t], seg = itSeg[t];
            const __nv_bfloat16* src;
            switch (tile){
                case 0: src = AhR + (size_t)row*lda; break;
                case 1: src = AlR + (size_t)row*lda; break;
                case 2: src = WhS + (size_t)row*K;   break;
                default:src = WlS + (size_t)row*K;   break;
            }
            src += kc*32 + seg*8;
            cp16(base + tile*TSZ + row*PITCH + seg*16, src);
        }
        cp_commit();
    };

    load_chunk(0, 0);
    for (int c=0; c<nkc; c++){
        int buf = c & 1;
        if (c+1 < nkc){ load_chunk(c+1, buf^1); cp_wait<1>(); }
        else cp_wait<0>();
        __syncthreads();
        uint32_t base = smBase + (uint32_t)buf*STAGE;
        #pragma unroll
        for (int ph=0; ph<3; ph++){
            uint32_t aT = base + (ph==1 ? TSZ : 0) + aoff;
            uint32_t bT = base + (ph==2 ? 3*TSZ : 2*TSZ) + boff;
            #pragma unroll
            for (int ks=0; ks<2; ks++){
                uint32_t a[2][4], b[4][4];
                #pragma unroll
                for (int mi=0; mi<2; mi++) ldsm4(a[mi], aT + mi*16*PITCH + ks*32);
                #pragma unroll
                for (int np_=0; np_<4; np_++) ldsm4(b[np_], bT + np_*16*PITCH + ks*32);
                #pragma unroll
                for (int mi=0; mi<2; mi++)
                    #pragma unroll
                    for (int nj=0; nj<8; nj++)
                        mma16816(d[mi][nj], a[mi], b[nj>>1][(nj&1)*2], b[nj>>1][(nj&1)*2+1]);
            }
        }
        __syncthreads();
    }

    const float* bp = bias + sp*Nout + bx*128 + wn*64;
    int rowLo = wm*32 + (lane >> 2);
    int colCta = bx*128 + wn*64;
    #pragma unroll
    for (int mi=0; mi<2; mi++){
        #pragma unroll
        for (int nj=0; nj<8; nj++){
            int c0 = nj*8 + 2*(lane & 3);
            float b0 = bp[c0], b1 = bp[c0+1];
            #pragma unroll
            for (int h=0; h<2; h++){
                size_t gr = (size_t)by*128 + rowLo + mi*16 + h*8;
                float x0 = d[mi][nj][2*h]   + b0;
                float x1 = d[mi][nj][2*h+1] + b1;
                if (act){ x0 = gelu_tanh(x0); x1 = gelu_tanh(x1); }
                int col = colCta + c0;
                if (C32){
                    *(float2*)(C32 + gr*ldc32 + col) = make_float2(x0, x1);
                }
                if (Ch){
                    __nv_bfloat16 h0,l0,h1,l1;
                    split_hl(x0,h0,l0); split_hl(x1,h1,l1);
                    uint32_t hh = (uint32_t)__bfloat16_as_ushort(h0) |
                                  ((uint32_t)__bfloat16_as_ushort(h1) << 16);
                    uint32_t ll = (uint32_t)__bfloat16_as_ushort(l0) |
                                  ((uint32_t)__bfloat16_as_ushort(l1) << 16);
                    *(uint32_t*)(Ch + gr*ldcb + col) = hh;
                    *(uint32_t*)(Cl + gr*ldcb + col) = ll;
                }
            }
        }
    }
}

// ---------------- CSR gather: merged[r][t] = sum_nb neigh[nb][t]*w ----------
__global__ void __launch_bounds__(128) mpgather_kernel(int mode){
    int r = blockIdx.x, t = threadIdx.x;
    int s = g_roff[r], e = g_roff[r+1];
    float acc = 0.f;
    int j = s;
    for (; j+1 < e; j += 2){
        int nb0 = g_nbr[j], nb1 = g_nbr[j+1];
        float w0 = g_w[j],  w1 = g_w[j+1];
        float x0 = g_neigh[(size_t)nb0*NOUT + t];
        float x1 = g_neigh[(size_t)nb1*NOUT + t];
        acc = fmaf(x0, w0, acc);
        acc = fmaf(x1, w1, acc);
    }
    if (j < e)
        acc = fmaf(g_neigh[(size_t)g_nbr[j]*NOUT + t], g_w[j], acc);
    if (mode == 0){
        __nv_bfloat16 h, l; split_hl(acc, h, l);
        g_f1h[(size_t)r*FIN + 256 + t] = h;
        g_f1l[(size_t)r*FIN + 256 + t] = l;
    } else {
        g_feat2[(size_t)r*FIN + 256 + t] = acc;
    }
}

// ---------------- final routed linear (FIN->1) + outputs --------------------
__global__ void __launch_bounds__(256) final_kernel(const int* __restrict__ species,
                                                    const float* __restrict__ Wf,
                                                    const float* __restrict__ bf,
                                                    float* __restrict__ out){
    int gt = blockIdx.x*256 + threadIdx.x;
    int i = gt >> 5, lane = gt & 31;
    if (i >= NATOMS) return;
    int s = species[i];
    int r = g_p2n[i];
    const float* f = g_feat2 + (size_t)r*FIN;
    const float* w = Wf + s*FIN;
    float sum = 0.f;
    #pragma unroll
    for (int j=0;j<12;j++){
        int k = lane + 32*j;
        sum = fmaf(f[k], w[k], sum);
    }
    #pragma unroll
    for (int o=16;o;o>>=1) sum += __shfl_xor_sync(0xffffffffu, sum, o);
    if (lane == 0){
        float pre = sum + bf[s];
        g_pre[i] = pre;
        out[2*NATOMS + i] = pre;
        out[i] = (float)s;
    }
}

// ---------------- per-molecule charge redistribution -------------------------
__global__ void charge_kernel(const float* __restrict__ tq, float* __restrict__ out){
    __shared__ float ss[4];
    int b = blockIdx.x, a = threadIdx.x;
    float p = g_pre[b*NA + a];
    float v = p;
    #pragma unroll
    for (int o=16;o;o>>=1) v += __shfl_xor_sync(0xffffffffu, v, o);
    int w = a>>5, lane = a&31;
    if (lane == 0) ss[w] = v;
    __syncthreads();
    float sum = ss[0]+ss[1]+ss[2]+ss[3];
    out[NATOMS + b*NA + a] = p + (tq[b] - sum)*(1.0f/128.0f);
}

// ---------------- launch -----------------------------------------------------
extern "C" void kernel_launch(void* const* d_in, const int* in_sizes, int n_in,
                              void* d_out, int out_size){
    const int*   species = (const int*)  d_in[0];
    const float* aev     = (const float*)d_in[1];
    const int*   ai12    = (const int*)  d_in[2];
    const float* dist    = (const float*)d_in[3];
    const float* tq      = (const float*)d_in[4];
    const float* Wm0     = (const float*)d_in[5];
    const float* bm0     = (const float*)d_in[6];
    const float* Wn0     = (const float*)d_in[7];
    const float* bn0     = (const float*)d_in[8];
    const float* Wm1     = (const float*)d_in[9];
    const float* bm1     = (const float*)d_in[10];
    const float* Wn1     = (const float*)d_in[11];
    const float* bn1     = (const float*)d_in[12];
    const float* Wf      = (const float*)d_in[13];
    const float* bf      = (const float*)d_in[14];
    const float* factor  = (const float*)d_in[15];
    const float* prefac  = (const float*)d_in[16];
    float* out = (float*)d_out;

    __nv_bfloat16 *ah, *al, *f1h, *f1l, *f2h, *f2l;
    __nv_bfloat16 *wm0h, *wm0l, *wn0h, *wn0l, *wm1h, *wm1l, *wn1h, *wn1l;
    float *feat2, *neigh;
    cudaGetSymbolAddress((void**)&ah,   g_ah);
    cudaGetSymbolAddress((void**)&al,   g_al);
    cudaGetSymbolAddress((void**)&f1h,  g_f1h);
    cudaGetSymbolAddress((void**)&f1l,  g_f1l);
    cudaGetSymbolAddress((void**)&f2h,  g_f2h);
    cudaGetSymbolAddress((void**)&f2l,  g_f2l);
    cudaGetSymbolAddress((void**)&wm0h, g_wm0h);
    cudaGetSymbolAddress((void**)&wm0l, g_wm0l);
    cudaGetSymbolAddress((void**)&wn0h, g_wn0h);
    cudaGetSymbolAddress((void**)&wn0l, g_wn0l);
    cudaGetSymbolAddress((void**)&wm1h, g_wm1h);
    cudaGetSymbolAddress((void**)&wm1l, g_wm1l);
    cudaGetSymbolAddress((void**)&wn1h, g_wn1h);
    cudaGetSymbolAddress((void**)&wn1l, g_wn1l);
    cudaGetSymbolAddress((void**)&feat2, g_feat2);
    cudaGetSymbolAddress((void**)&neigh, g_neigh);

    cudaFuncSetAttribute(tgemm_kernel, cudaFuncAttributeMaxDynamicSharedMemorySize, 2*STAGE);

    perm_kernel        <<<1, 1024>>>(species);
    edge_kernel        <<<NP/256, 256>>>(ai12, dist, factor, prefac);
    scan_kernel        <<<1, 1024>>>();
    fill_kernel        <<<NP/256, 256>>>();
    gather_split_kernel<<<NPAD, 256>>>(aev);
    wprep_kernel<<<(NSP*MO*AEVP)/256, 256>>>(Wm0, wm0h, wm0l, AEV, MO, AEVP);
    wprep_kernel<<<(NSP*NOUT*MO)/256, 256>>>(Wn0, wn0h, wn0l, MO, NOUT, MO);
    wprep_kernel<<<(NSP*MO*FIN)/256, 256>>>(Wm1, wm1h, wm1l, FIN, MO, FIN);
    wprep_kernel<<<(NSP*NOUT*MO)/256, 256>>>(Wn1, wn1h, wn1l, MO, NOUT, MO);

    // pass 0
    tgemm_kernel<<<dim3(2, NT), 256, 2*STAGE>>>(ah, al, AEVP, wm0h, wm0l, bm0,
                                       AEVP, MO, (float*)0, 0, f1h, f1l, FIN, 1);
    tgemm_kernel<<<dim3(1, NT), 256, 2*STAGE>>>(f1h, f1l, FIN, wn0h, wn0l, bn0,
                                       MO, NOUT, neigh, NOUT,
                                       (__nv_bfloat16*)0, (__nv_bfloat16*)0, 0, 1);
    mpgather_kernel    <<<NPAD, 128>>>(0);

    // pass 1
    tgemm_kernel<<<dim3(2, NT), 256, 2*STAGE>>>(f1h, f1l, FIN, wm1h, wm1l, bm1,
                                       FIN, MO, feat2, FIN, f2h, f2l, MO, 1);
    tgemm_kernel<<<dim3(1, NT), 256, 2*STAGE>>>(f2h, f2l, MO, wn1h, wn1l, bn1,
                                       MO, NOUT, neigh, NOUT,
                                       (__nv_bfloat16*)0, (__nv_bfloat16*)0, 0, 1);
    mpgather_kernel    <<<NPAD, 128>>>(1);

    // outputs
    final_kernel <<<NATOMS*32/256, 256>>>(species, Wf, bf, out);
    charge_kernel<<<NB, NA>>>(tq, out);
}

// round 7
// speedup vs baseline: 2.1174x; 1.0458x over previous
#include <cuda_runtime.h>
#include <cuda_bf16.h>
#include <math.h>
#include <stdint.h>

#define NB     256
#define NA     128
#define NATOMS 32768
#define AEV    1008
#define AEVP   1024
#define MO     256
#define NOUT   128
#define FIN    384
#define NP     262144
#define NSP    4
#define NPAD   33280
#define NT     (NPAD/128)

// ---------------- scratch (device globals) ----------------------------------
__device__ __align__(16) __nv_bfloat16 g_f1h[(size_t)NPAD*FIN];
__device__ __align__(16) __nv_bfloat16 g_f1l[(size_t)NPAD*FIN];
__device__ __align__(16) __nv_bfloat16 g_f2h[(size_t)NPAD*MO];
__device__ __align__(16) __nv_bfloat16 g_f2l[(size_t)NPAD*MO];
__device__ float g_feat2[(size_t)NPAD*FIN];     // fp32: internal1 | merged1
__device__ float g_neigh[(size_t)NPAD*NOUT];
__device__ float g_decay[NP];
__device__ int   g_e0[NP], g_e1[NP];
__device__ int   g_p2n[NATOMS];
__device__ int   g_n2o[NPAD];
__device__ int   g_tilesp[NT];
__device__ float g_pre[NATOMS];
// CSR adjacency (rebuilt every launch)
__device__ int   g_deg[NPAD];
__device__ int   g_roff[NPAD+1];
__device__ int   g_cur[NPAD];
__device__ int   g_nbr[2*NP];
__device__ float g_w[2*NP];
// transposed + hi/lo-split weights: [S][Nout][Kpad]
__device__ __align__(16) __nv_bfloat16 g_wm0h[(size_t)NSP*MO*AEVP],  g_wm0l[(size_t)NSP*MO*AEVP];
__device__ __align__(16) __nv_bfloat16 g_wn0h[(size_t)NSP*NOUT*MO],  g_wn0l[(size_t)NSP*NOUT*MO];
__device__ __align__(16) __nv_bfloat16 g_wm1h[(size_t)NSP*MO*FIN],   g_wm1l[(size_t)NSP*MO*FIN];
__device__ __align__(16) __nv_bfloat16 g_wn1h[(size_t)NSP*NOUT*MO],  g_wn1l[(size_t)NSP*NOUT*MO];

// ---------------- small helpers ---------------------------------------------
__device__ __forceinline__ uint32_t smem_u32(const void* p){
    uint32_t a;
    asm("{ .reg .u64 t; cvta.to.shared.u64 t, %1; cvt.u32.u64 %0, t; }" : "=r"(a) : "l"(p));
    return a;
}
__device__ __forceinline__ void cp16(uint32_t dst, const void* src){
    asm volatile("cp.async.cg.shared.global [%0], [%1], 16;" :: "r"(dst), "l"(src) : "memory");
}
__device__ __forceinline__ void cp_commit(){
    asm volatile("cp.async.commit_group;" ::: "memory");
}
template<int N> __device__ __forceinline__ void cp_wait(){
    asm volatile("cp.async.wait_group %0;" :: "n"(N) : "memory");
}
__device__ __forceinline__ void ldsm4(uint32_t* r, uint32_t addr){
    asm volatile("ldmatrix.sync.aligned.m8n8.x4.shared.b16 {%0,%1,%2,%3}, [%4];"
        : "=r"(r[0]),"=r"(r[1]),"=r"(r[2]),"=r"(r[3]) : "r"(addr));
}
__device__ __forceinline__ void mma16816(float* d, const uint32_t* a, uint32_t b0, uint32_t b1){
    asm volatile("mma.sync.aligned.m16n8k16.row.col.f32.bf16.bf16.f32 "
        "{%0,%1,%2,%3}, {%4,%5,%6,%7}, {%8,%9}, {%0,%1,%2,%3};"
        : "+f"(d[0]),"+f"(d[1]),"+f"(d[2]),"+f"(d[3])
        : "r"(a[0]),"r"(a[1]),"r"(a[2]),"r"(a[3]), "r"(b0),"r"(b1));
}
__device__ __forceinline__ float gelu_tanh(float x){
    float t = tanhf(0.7978845608028654f * (x + 0.044715f * x * x * x));
    return 0.5f * x * (1.0f + t);
}
__device__ __forceinline__ void split_hl(float x, __nv_bfloat16& h, __nv_bfloat16& l){
    h = __float2bfloat16(x);
    l = __float2bfloat16(x - __bfloat162float(h));
}

// ---------------- permutation: deterministic species grouping ---------------
__global__ void __launch_bounds__(1024) perm_kernel(const int* __restrict__ species){
    __shared__ int sc[NSP][1024];
    __shared__ int stot[NSP];
    __shared__ int sbase[NSP+1];
    int t = threadIdx.x;
    for (int r = t; r < NPAD; r += 1024){ g_n2o[r] = -1; g_deg[r] = 0; }
    int c0=0,c1=0,c2=0,c3=0;
    int b0 = t*32;
    #pragma unroll
    for (int j=0;j<32;j++){
        int s = species[b0+j];
        c0 += (s==0); c1 += (s==1); c2 += (s==2); c3 += (s==3);
    }
    sc[0][t]=c0; sc[1][t]=c1; sc[2][t]=c2; sc[3][t]=c3;
    __syncthreads();
    if (t < NSP){
        int run = 0;
        for (int i=0;i<1024;i++){ int v=sc[t][i]; sc[t][i]=run; run+=v; }
        stot[t]=run;
    }
    __syncthreads();
    if (t==0){
        int b=0;
        for (int s=0;s<NSP;s++){ sbase[s]=b; b += ((stot[s]+127)>>7)<<7; }
        sbase[NSP]=b;
        for (int tt=0; tt<NT; tt++){
            int rs = tt*128; int sp=0;
            for (int s=1;s<NSP;s++) if (rs >= sbase[s]) sp=s;
            g_tilesp[tt]=sp;
        }
    }
    __syncthreads();
    int run2[NSP] = {0,0,0,0};
    for (int j=0;j<32;j++){
        int i = b0+j; int s = species[i];
        int pos = sbase[s] + sc[s][t] + run2[s];
        run2[s]++;
        g_p2n[i]=pos; g_n2o[pos]=i;
    }
}

// ---------------- weight transpose + split: W[S][K][N] -> T[S][N][Kpad] ----
__global__ void __launch_bounds__(256) wprep_kernel(const float* __restrict__ W,
                                                    __nv_bfloat16* __restrict__ Th,
                                                    __nv_bfloat16* __restrict__ Tl,
                                                    int K, int Nout, int Kpad){
    long idx = (long)blockIdx.x*256 + threadIdx.x;
    long total = (long)NSP*Nout*Kpad;
    if (idx >= total) return;
    int k = idx % Kpad;
    int n = (idx / Kpad) % Nout;
    int s = idx / ((long)Kpad*Nout);
    float v = (k < K) ? W[((size_t)s*K + k)*Nout + n] : 0.f;
    __nv_bfloat16 h, l; split_hl(v, h, l);
    Th[idx] = h; Tl[idx] = l;
}

// ---------------- edges: decay + endpoint remap + degree count ---------------
__global__ void edge_kernel(const int* __restrict__ ai,
                            const float* __restrict__ dist,
                            const float* __restrict__ fa,
                            const float* __restrict__ pf){
    int p = blockIdx.x*256 + threadIdx.x;
    float d = dist[p];
    float factor = fa[0], pre = pf[0];
    float x = fminf(fmaxf(d*(1.0f/5.2f), 0.0f), 1.0f - 1e-6f);
    float f = (d < 5.2f) ? expf(1.0f - 1.0f/(1.0f - x*x)) : 0.0f;
    g_decay[p] = pre*pre*expf(-factor*factor*d)*f;
    int e0 = g_p2n[ai[p]];
    int e1 = g_p2n[ai[NP + p]];
    g_e0[p] = e0; g_e1[p] = e1;
    atomicAdd(&g_deg[e0], 1);
    atomicAdd(&g_deg[e1], 1);
}

// ---------------- exclusive scan of degrees -> row offsets ------------------
#define SCAN_CH 33
__global__ void __launch_bounds__(1024) scan_kernel(){
    __shared__ int wsum[32];
    int t = threadIdx.x;
    int base = t*SCAN_CH;
    int s = 0;
    for (int j=0;j<SCAN_CH;j++){
        int idx = base+j;
        if (idx < NPAD) s += g_deg[idx];
    }
    int lane = t&31, w = t>>5;
    int v = s;
    #pragma unroll
    for (int o=1;o<32;o<<=1){ int u = __shfl_up_sync(~0u, v, o); if (lane>=o) v += u; }
    if (lane==31) wsum[w] = v;
    __syncthreads();
    if (w==0){
        int x = wsum[lane];
        #pragma unroll
        for (int o=1;o<32;o<<=1){ int u = __shfl_up_sync(~0u, x, o); if (lane>=o) x += u; }
        wsum[lane] = x;
    }
    __syncthreads();
    int excl = v - s + (w>0 ? wsum[w-1] : 0);
    int run = excl;
    for (int j=0;j<SCAN_CH;j++){
        int idx = base+j;
        if (idx < NPAD){
            g_roff[idx] = run;
            g_cur[idx]  = run;
            run += g_deg[idx];
        }
    }
    if (t == 1023) g_roff[NPAD] = run;
}

// ---------------- fill CSR edge lists -----------------------------------------
__global__ void fill_kernel(){
    int p = blockIdx.x*256 + threadIdx.x;
    int e0 = g_e0[p], e1 = g_e1[p];
    float d = g_decay[p];
    int i0 = atomicAdd(&g_cur[e0], 1);
    g_nbr[i0] = e1; g_w[i0] = d;
    int i1 = atomicAdd(&g_cur[e1], 1);
    g_nbr[i1] = e0; g_w[i1] = d;
}

// ---------------- HMMA GEMM, fused 3-phase hi/lo -----------------------------
// Per 32-wide K chunk: ah, al, wh, wl tiles in smem; accumulate
// ah*wh + al*wh + ah*wl into the same fp32 accumulators.
// If A32 != null: A rows are fp32 (original order, indirected via g_n2o),
// loaded via LDG.128 + in-register split (kills the standalone gather kernel).
#define PITCH 80
#define TSZ   (128*PITCH)      // 10240 B, one tile (128 rows x 32 bf16)
#define STAGE (4*TSZ)          // 40960 B: ah | al | wh | wl
__global__ void __launch_bounds__(256, 2) tgemm_kernel(
    const float* __restrict__ A32,
    const __nv_bfloat16* __restrict__ Ah, const __nv_bfloat16* __restrict__ Al, int lda,
    const __nv_bfloat16* __restrict__ Wh, const __nv_bfloat16* __restrict__ Wl,
    const float* __restrict__ bias,
    int K, int Nout,
    float* C32, int ldc32,
    __nv_bfloat16* Ch, __nv_bfloat16* Cl, int ldcb,
    int act)
{
    extern __shared__ __align__(128) uint8_t sm[];   // 2*STAGE dynamic
    uint32_t smBase = smem_u32(sm);

    int tid = threadIdx.x, lane = tid & 31, wid = tid >> 5;
    int wm = wid & 3, wn = wid >> 2;
    int bx = blockIdx.x, by = blockIdx.y;
    int sp = g_tilesp[by];

    const __nv_bfloat16* WhS = Wh + ((size_t)sp*Nout + bx*128)*K;
    const __nv_bfloat16* WlS = Wl + ((size_t)sp*Nout + bx*128)*K;

    float d[2][8][4];
    #pragma unroll
    for (int i=0;i<2;i++)
        #pragma unroll
        for (int j=0;j<8;j++)
            #pragma unroll
            for (int q=0;q<4;q++) d[i][j][q]=0.f;

    int nkc = K >> 5;   // 32-wide K chunks

    uint32_t aoff = (uint32_t)((wm*32 + (lane & 15))*PITCH + ((lane >> 4) & 1)*16);
    uint32_t boff = (uint32_t)((wn*64 + (lane & 7) + ((lane >> 4) & 1)*8)*PITCH + ((lane >> 3) & 1)*16);

    auto do_mma = [&](int buf){
        uint32_t base = smBase + (uint32_t)buf*STAGE;
        #pragma unroll
        for (int ph=0; ph<3; ph++){
            uint32_t aT = base + (ph==1 ? TSZ : 0) + aoff;
            uint32_t bT = base + (ph==2 ? 3*TSZ : 2*TSZ) + boff;
            #pragma unroll
            for (int ks=0; ks<2; ks++){
                uint32_t a[2][4], b[4][4];
                #pragma unroll
                for (int mi=0; mi<2; mi++) ldsm4(a[mi], aT + mi*16*PITCH + ks*32);
                #pragma unroll
                for (int np_=0; np_<4; np_++) ldsm4(b[np_], bT + np_*16*PITCH + ks*32);
                #pragma unroll
                for (int mi=0; mi<2; mi++)
                    #pragma unroll
                    for (int nj=0; nj<8; nj++)
                        mma16816(d[mi][nj], a[mi], b[nj>>1][(nj&1)*2], b[nj>>1][(nj&1)*2+1]);
            }
        }
    };

    if (A32 == nullptr){
        // ---- bf16 A path: 8 cp.async slots cover 4 tiles ----
        const __nv_bfloat16* AhR = Ah + (size_t)by*128*lda;
        const __nv_bfloat16* AlR = Al + (size_t)by*128*lda;
        int itTile[8], itRow[8], itSeg[8];
        #pragma unroll
        for (int t=0;t<8;t++){
            int it = tid + t*256;
            itTile[t] = it >> 9;
            int j = it & 511;
            itRow[t] = j >> 2; itSeg[t] = j & 3;
        }
        auto load_chunk = [&](int kc, int buf){
            uint32_t base = smBase + (uint32_t)buf*STAGE;
            #pragma unroll
            for (int t=0;t<8;t++){
                int tile = itTile[t], row = itRow[t], seg = itSeg[t];
                const __nv_bfloat16* src;
                switch (tile){
                    case 0: src = AhR + (size_t)row*lda; break;
                    case 1: src = AlR + (size_t)row*lda; break;
                    case 2: src = WhS + (size_t)row*K;   break;
                    default:src = WlS + (size_t)row*K;   break;
                }
                src += kc*32 + seg*8;
                cp16(base + tile*TSZ + row*PITCH + seg*16, src);
            }
            cp_commit();
        };
        load_chunk(0, 0);
        for (int c=0; c<nkc; c++){
            int buf = c & 1;
            if (c+1 < nkc){ load_chunk(c+1, buf^1); cp_wait<1>(); }
            else cp_wait<0>();
            __syncthreads();
            do_mma(buf);
            __syncthreads();
        }
    } else {
        // ---- fp32 A path (pass-0): LDG.128 + in-register hi/lo split ----
        // A slots: 1024 items = 128 rows x 8 segs (4 floats each); 4 per thread.
        const float* aptr[4];
        bool avalid[4];
        int aRow[4], aSeg[4];
        #pragma unroll
        for (int t=0;t<4;t++){
            int j = tid + t*256;
            aRow[t] = j >> 3; aSeg[t] = j & 7;
            int src = g_n2o[by*128 + aRow[t]];
            avalid[t] = (src >= 0);
            aptr[t] = A32 + (size_t)(src < 0 ? 0 : src)*AEV;
        }
        // W slots: 1024 items = 2 tiles x 128 rows x 4 segs(16B); 4 per thread.
        auto loadW = [&](int kc, int buf){
            uint32_t base = smBase + (uint32_t)buf*STAGE;
            #pragma unroll
            for (int t=0;t<4;t++){
                int j = tid + t*256;
                int tile = 2 + (j >> 9);
                int row = (j >> 2) & 127, seg = j & 3;
                const __nv_bfloat16* src = (tile==3 ? WlS : WhS) + (size_t)row*K + kc*32 + seg*8;
                cp16(base + tile*TSZ + row*PITCH + seg*16, src);
            }
            cp_commit();
        };
        float4 R[4];
        auto ldgA = [&](int kc){
            #pragma unroll
            for (int t=0;t<4;t++){
                int col = kc*32 + aSeg[t]*4;
                if (avalid[t] && col < AEV) R[t] = *(const float4*)(aptr[t] + col);
                else R[t] = make_float4(0.f,0.f,0.f,0.f);
            }
        };
        auto stsA = [&](int buf){
            uint32_t base = (uint32_t)buf*STAGE;
            #pragma unroll
            for (int t=0;t<4;t++){
                float a[4] = {R[t].x, R[t].y, R[t].z, R[t].w};
                __nv_bfloat16 h[4], l[4];
                #pragma unroll
                for (int q=0;q<4;q++) split_hl(a[q], h[q], l[q]);
                uint32_t off = base + (uint32_t)(aRow[t]*PITCH + aSeg[t]*8);
                *(uint64_t*)(sm + off)       = *(const uint64_t*)h;
                *(uint64_t*)(sm + off + TSZ) = *(const uint64_t*)l;
            }
        };
        ldgA(0);
        loadW(0, 0);
        for (int c=0; c<nkc; c++){
            int buf = c & 1;
            stsA(buf);                       // buf free since sync at end of c-2
            if (c+1 < nkc){ ldgA(c+1); loadW(c+1, buf^1); cp_wait<1>(); }
            else cp_wait<0>();
            __syncthreads();
            do_mma(buf);
            __syncthreads();
        }
    }

    const float* bp = bias + sp*Nout + bx*128 + wn*64;
    int rowLo = wm*32 + (lane >> 2);
    int colCta = bx*128 + wn*64;
    #pragma unroll
    for (int mi=0; mi<2; mi++){
        #pragma unroll
        for (int nj=0; nj<8; nj++){
            int c0 = nj*8 + 2*(lane & 3);
            float b0 = bp[c0], b1 = bp[c0+1];
            #pragma unroll
            for (int h=0; h<2; h++){
                size_t gr = (size_t)by*128 + rowLo + mi*16 + h*8;
                float x0 = d[mi][nj][2*h]   + b0;
                float x1 = d[mi][nj][2*h+1] + b1;
                if (act){ x0 = gelu_tanh(x0); x1 = gelu_tanh(x1); }
                int col = colCta + c0;
                if (C32){
                    *(float2*)(C32 + gr*ldc32 + col) = make_float2(x0, x1);
                }
                if (Ch){
                    __nv_bfloat16 h0,l0,h1,l1;
                    split_hl(x0,h0,l0); split_hl(x1,h1,l1);
                    uint32_t hh = (uint32_t)__bfloat16_as_ushort(h0) |
                                  ((uint32_t)__bfloat16_as_ushort(h1) << 16);
                    uint32_t ll = (uint32_t)__bfloat16_as_ushort(l0) |
                                  ((uint32_t)__bfloat16_as_ushort(l1) << 16);
                    *(uint32_t*)(Ch + gr*ldcb + col) = hh;
                    *(uint32_t*)(Cl + gr*ldcb + col) = ll;
                }
            }
        }
    }
}

// ---------------- CSR gather: merged[r][t] = sum_nb neigh[nb][t]*w ----------
__global__ void __launch_bounds__(128) mpgather_kernel(int mode){
    int r = blockIdx.x, t = threadIdx.x;
    int s = g_roff[r], e = g_roff[r+1];
    float acc = 0.f;
    int j = s;
    for (; j+1 < e; j += 2){
        int nb0 = g_nbr[j], nb1 = g_nbr[j+1];
        float w0 = g_w[j],  w1 = g_w[j+1];
        float x0 = g_neigh[(size_t)nb0*NOUT + t];
        float x1 = g_neigh[(size_t)nb1*NOUT + t];
        acc = fmaf(x0, w0, acc);
        acc = fmaf(x1, w1, acc);
    }
    if (j < e)
        acc = fmaf(g_neigh[(size_t)g_nbr[j]*NOUT + t], g_w[j], acc);
    if (mode == 0){
        __nv_bfloat16 h, l; split_hl(acc, h, l);
        g_f1h[(size_t)r*FIN + 256 + t] = h;
        g_f1l[(size_t)r*FIN + 256 + t] = l;
    } else {
        g_feat2[(size_t)r*FIN + 256 + t] = acc;
    }
}

// ---------------- final routed linear (FIN->1) + outputs --------------------
__global__ void __launch_bounds__(256) final_kernel(const int* __restrict__ species,
                                                    const float* __restrict__ Wf,
                                                    const float* __restrict__ bf,
                                                    float* __restrict__ out){
    int gt = blockIdx.x*256 + threadIdx.x;
    int i = gt >> 5, lane = gt & 31;
    if (i >= NATOMS) return;
    int s = species[i];
    int r = g_p2n[i];
    const float* f = g_feat2 + (size_t)r*FIN;
    const float* w = Wf + s*FIN;
    float sum = 0.f;
    #pragma unroll
    for (int j=0;j<12;j++){
        int k = lane + 32*j;
        sum = fmaf(f[k], w[k], sum);
    }
    #pragma unroll
    for (int o=16;o;o>>=1) sum += __shfl_xor_sync(0xffffffffu, sum, o);
    if (lane == 0){
        float pre = sum + bf[s];
        g_pre[i] = pre;
        out[2*NATOMS + i] = pre;
        out[i] = (float)s;
    }
}

// ---------------- per-molecule charge redistribution -------------------------
__global__ void charge_kernel(const float* __restrict__ tq, float* __restrict__ out){
    __shared__ float ss[4];
    int b = blockIdx.x, a = threadIdx.x;
    float p = g_pre[b*NA + a];
    float v = p;
    #pragma unroll
    for (int o=16;o;o>>=1) v += __shfl_xor_sync(0xffffffffu, v, o);
    int w = a>>5, lane = a&31;
    if (lane == 0) ss[w] = v;
    __syncthreads();
    float sum = ss[0]+ss[1]+ss[2]+ss[3];
    out[NATOMS + b*NA + a] = p + (tq[b] - sum)*(1.0f/128.0f);
}

// ---------------- launch -----------------------------------------------------
extern "C" void kernel_launch(void* const* d_in, const int* in_sizes, int n_in,
                              void* d_out, int out_size){
    const int*   species = (const int*)  d_in[0];
    const float* aev     = (const float*)d_in[1];
    const int*   ai12    = (const int*)  d_in[2];
    const float* dist    = (const float*)d_in[3];
    const float* tq      = (const float*)d_in[4];
    const float* Wm0     = (const float*)d_in[5];
    const float* bm0     = (const float*)d_in[6];
    const float* Wn0     = (const float*)d_in[7];
    const float* bn0     = (const float*)d_in[8];
    const float* Wm1     = (const float*)d_in[9];
    const float* bm1     = (const float*)d_in[10];
    const float* Wn1     = (const float*)d_in[11];
    const float* bn1     = (const float*)d_in[12];
    const float* Wf      = (const float*)d_in[13];
    const float* bf      = (const float*)d_in[14];
    const float* factor  = (const float*)d_in[15];
    const float* prefac  = (const float*)d_in[16];
    float* out = (float*)d_out;

    __nv_bfloat16 *f1h, *f1l, *f2h, *f2l;
    __nv_bfloat16 *wm0h, *wm0l, *wn0h, *wn0l, *wm1h, *wm1l, *wn1h, *wn1l;
    float *feat2, *neigh;
    cudaGetSymbolAddress((void**)&f1h,  g_f1h);
    cudaGetSymbolAddress((void**)&f1l,  g_f1l);
    cudaGetSymbolAddress((void**)&f2h,  g_f2h);
    cudaGetSymbolAddress((void**)&f2l,  g_f2l);
    cudaGetSymbolAddress((void**)&wm0h, g_wm0h);
    cudaGetSymbolAddress((void**)&wm0l, g_wm0l);
    cudaGetSymbolAddress((void**)&wn0h, g_wn0h);
    cudaGetSymbolAddress((void**)&wn0l, g_wn0l);
    cudaGetSymbolAddress((void**)&wm1h, g_wm1h);
    cudaGetSymbolAddress((void**)&wm1l, g_wm1l);
    cudaGetSymbolAddress((void**)&wn1h, g_wn1h);
    cudaGetSymbolAddress((void**)&wn1l, g_wn1l);
    cudaGetSymbolAddress((void**)&feat2, g_feat2);
    cudaGetSymbolAddress((void**)&neigh, g_neigh);

    cudaFuncSetAttribute(tgemm_kernel, cudaFuncAttributeMaxDynamicSharedMemorySize, 2*STAGE);

    perm_kernel <<<1, 1024>>>(species);
    edge_kernel <<<NP/256, 256>>>(ai12, dist, factor, prefac);
    scan_kernel <<<1, 1024>>>();
    fill_kernel <<<NP/256, 256>>>();
    wprep_kernel<<<(NSP*MO*AEVP)/256, 256>>>(Wm0, wm0h, wm0l, AEV, MO, AEVP);
    wprep_kernel<<<(NSP*NOUT*MO)/256, 256>>>(Wn0, wn0h, wn0l, MO, NOUT, MO);
    wprep_kernel<<<(NSP*MO*FIN)/256, 256>>>(Wm1, wm1h, wm1l, FIN, MO, FIN);
    wprep_kernel<<<(NSP*NOUT*MO)/256, 256>>>(Wn1, wn1h, wn1l, MO, NOUT, MO);

    // pass 0 (A = fp32 AEV, loaded+split inside the GEMM)
    tgemm_kernel<<<dim3(2, NT), 256, 2*STAGE>>>(aev,
                                       (__nv_bfloat16*)0, (__nv_bfloat16*)0, 0,
                                       wm0h, wm0l, bm0,
                                       AEVP, MO, (float*)0, 0, f1h, f1l, FIN, 1);
    tgemm_kernel<<<dim3(1, NT), 256, 2*STAGE>>>((const float*)0,
                                       f1h, f1l, FIN, wn0h, wn0l, bn0,
                                       MO, NOUT, neigh, NOUT,
                                       (__nv_bfloat16*)0, (__nv_bfloat16*)0, 0, 1);
    mpgather_kernel<<<NPAD, 128>>>(0);

    // pass 1
    tgemm_kernel<<<dim3(2, NT), 256, 2*STAGE>>>((const float*)0,
                                       f1h, f1l, FIN, wm1h, wm1l, bm1,
                                       FIN, MO, feat2, FIN, f2h, f2l, MO, 1);
    tgemm_kernel<<<dim3(1, NT), 256, 2*STAGE>>>((const float*)0,
                                       f2h, f2l, MO, wn1h, wn1l, bn1,
                                       MO, NOUT, neigh, NOUT,
                                       (__nv_bfloat16*)0, (__nv_bfloat16*)0, 0, 1);
    mpgather_kernel<<<NPAD, 128>>>(1);

    // outputs
    final_kernel <<<NATOMS*32/256, 256>>>(species, Wf, bf, out);
    charge_kernel<<<NB, NA>>>(tq, out);
}

// round 8
// speedup vs baseline: 2.3730x; 1.1207x over previous
#include <cuda_runtime.h>
#include <cuda_bf16.h>
#include <math.h>
#include <stdint.h>

#define NB     256
#define NA     128
#define NATOMS 32768
#define AEV    1008
#define AEVP   1024
#define MO     256
#define NOUT   128
#define FIN    384
#define NP     262144
#define NSP    4
#define NPAD   33280
#define NT     (NPAD/128)

// ---------------- scratch (device globals) ----------------------------------
__device__ __align__(16) __nv_bfloat16 g_f1h[(size_t)NPAD*FIN];
__device__ __align__(16) __nv_bfloat16 g_f1l[(size_t)NPAD*FIN];
__device__ __align__(16) __nv_bfloat16 g_f2h[(size_t)NPAD*MO];
__device__ __align__(16) __nv_bfloat16 g_f2l[(size_t)NPAD*MO];
__device__ float g_feat2[(size_t)NPAD*FIN];     // fp32: internal1 | merged1
__device__ float g_neigh[(size_t)NPAD*NOUT];
__device__ float g_decay[NP];
__device__ int   g_e0[NP], g_e1[NP];
__device__ int   g_p2n[NATOMS];
__device__ int   g_n2o[NPAD];
__device__ int   g_tilesp[NT];
__device__ float g_pre[NATOMS];
// CSR adjacency (rebuilt every launch)
__device__ int   g_deg[NPAD];
__device__ int   g_roff[NPAD+1];
__device__ int   g_cur[NPAD];
__device__ int   g_nbr[2*NP];
__device__ float g_w[2*NP];
// transposed + hi/lo-split weights: [S][Nout][Kpad]
__device__ __align__(16) __nv_bfloat16 g_wm0h[(size_t)NSP*MO*AEVP],  g_wm0l[(size_t)NSP*MO*AEVP];
__device__ __align__(16) __nv_bfloat16 g_wn0h[(size_t)NSP*NOUT*MO],  g_wn0l[(size_t)NSP*NOUT*MO];
__device__ __align__(16) __nv_bfloat16 g_wm1h[(size_t)NSP*MO*FIN],   g_wm1l[(size_t)NSP*MO*FIN];
__device__ __align__(16) __nv_bfloat16 g_wn1h[(size_t)NSP*NOUT*MO],  g_wn1l[(size_t)NSP*NOUT*MO];

// ---------------- small helpers ---------------------------------------------
__device__ __forceinline__ uint32_t smem_u32(const void* p){
    uint32_t a;
    asm("{ .reg .u64 t; cvta.to.shared.u64 t, %1; cvt.u32.u64 %0, t; }" : "=r"(a) : "l"(p));
    return a;
}
__device__ __forceinline__ void cp16(uint32_t dst, const void* src){
    asm volatile("cp.async.cg.shared.global [%0], [%1], 16;" :: "r"(dst), "l"(src) : "memory");
}
__device__ __forceinline__ void cp_commit(){
    asm volatile("cp.async.commit_group;" ::: "memory");
}
template<int N> __device__ __forceinline__ void cp_wait(){
    asm volatile("cp.async.wait_group %0;" :: "n"(N) : "memory");
}
__device__ __forceinline__ void ldsm4(uint32_t* r, uint32_t addr){
    asm volatile("ldmatrix.sync.aligned.m8n8.x4.shared.b16 {%0,%1,%2,%3}, [%4];"
        : "=r"(r[0]),"=r"(r[1]),"=r"(r[2]),"=r"(r[3]) : "r"(addr));
}
__device__ __forceinline__ void mma16816(float* d, const uint32_t* a, uint32_t b0, uint32_t b1){
    asm volatile("mma.sync.aligned.m16n8k16.row.col.f32.bf16.bf16.f32 "
        "{%0,%1,%2,%3}, {%4,%5,%6,%7}, {%8,%9}, {%0,%1,%2,%3};"
        : "+f"(d[0]),"+f"(d[1]),"+f"(d[2]),"+f"(d[3])
        : "r"(a[0]),"r"(a[1]),"r"(a[2]),"r"(a[3]), "r"(b0),"r"(b1));
}
__device__ __forceinline__ float gelu_tanh(float x){
    float t = tanhf(0.7978845608028654f * (x + 0.044715f * x * x * x));
    return 0.5f * x * (1.0f + t);
}
__device__ __forceinline__ void split_hl(float x, __nv_bfloat16& h, __nv_bfloat16& l){
    h = __float2bfloat16(x);
    l = __float2bfloat16(x - __bfloat162float(h));
}

// ---------------- permutation: deterministic species grouping ---------------
__global__ void __launch_bounds__(1024) perm_kernel(const int* __restrict__ species){
    __shared__ int sc[NSP][1024];
    __shared__ int stot[NSP];
    __shared__ int sbase[NSP+1];
    int t = threadIdx.x;
    for (int r = t; r < NPAD; r += 1024){ g_n2o[r] = -1; g_deg[r] = 0; }
    int c0=0,c1=0,c2=0,c3=0;
    int b0 = t*32;
    #pragma unroll
    for (int j=0;j<32;j++){
        int s = species[b0+j];
        c0 += (s==0); c1 += (s==1); c2 += (s==2); c3 += (s==3);
    }
    sc[0][t]=c0; sc[1][t]=c1; sc[2][t]=c2; sc[3][t]=c3;
    __syncthreads();
    if (t < NSP){
        int run = 0;
        for (int i=0;i<1024;i++){ int v=sc[t][i]; sc[t][i]=run; run+=v; }
        stot[t]=run;
    }
    __syncthreads();
    if (t==0){
        int b=0;
        for (int s=0;s<NSP;s++){ sbase[s]=b; b += ((stot[s]+127)>>7)<<7; }
        sbase[NSP]=b;
        for (int tt=0; tt<NT; tt++){
            int rs = tt*128; int sp=0;
            for (int s=1;s<NSP;s++) if (rs >= sbase[s]) sp=s;
            g_tilesp[tt]=sp;
        }
    }
    __syncthreads();
    int run2[NSP] = {0,0,0,0};
    for (int j=0;j<32;j++){
        int i = b0+j; int s = species[i];
        int pos = sbase[s] + sc[s][t] + run2[s];
        run2[s]++;
        g_p2n[i]=pos; g_n2o[pos]=i;
    }
}

// ---------------- weight transpose + split: W[S][K][N] -> T[S][N][Kpad] ----
__global__ void __launch_bounds__(256) wprep_kernel(const float* __restrict__ W,
                                                    __nv_bfloat16* __restrict__ Th,
                                                    __nv_bfloat16* __restrict__ Tl,
                                                    int K, int Nout, int Kpad){
    long idx = (long)blockIdx.x*256 + threadIdx.x;
    long total = (long)NSP*Nout*Kpad;
    if (idx >= total) return;
    int k = idx % Kpad;
    int n = (idx / Kpad) % Nout;
    int s = idx / ((long)Kpad*Nout);
    float v = (k < K) ? W[((size_t)s*K + k)*Nout + n] : 0.f;
    __nv_bfloat16 h, l; split_hl(v, h, l);
    Th[idx] = h; Tl[idx] = l;
}

// ---------------- edges: decay + endpoint remap + degree count ---------------
__global__ void edge_kernel(const int* __restrict__ ai,
                            const float* __restrict__ dist,
                            const float* __restrict__ fa,
                            const float* __restrict__ pf){
    int p = blockIdx.x*256 + threadIdx.x;
    float d = dist[p];
    float factor = fa[0], pre = pf[0];
    float x = fminf(fmaxf(d*(1.0f/5.2f), 0.0f), 1.0f - 1e-6f);
    float f = (d < 5.2f) ? expf(1.0f - 1.0f/(1.0f - x*x)) : 0.0f;
    g_decay[p] = pre*pre*expf(-factor*factor*d)*f;
    int e0 = g_p2n[ai[p]];
    int e1 = g_p2n[ai[NP + p]];
    g_e0[p] = e0; g_e1[p] = e1;
    atomicAdd(&g_deg[e0], 1);
    atomicAdd(&g_deg[e1], 1);
}

// ---------------- exclusive scan of degrees -> row offsets ------------------
#define SCAN_CH 33
__global__ void __launch_bounds__(1024) scan_kernel(){
    __shared__ int wsum[32];
    int t = threadIdx.x;
    int base = t*SCAN_CH;
    int s = 0;
    for (int j=0;j<SCAN_CH;j++){
        int idx = base+j;
        if (idx < NPAD) s += g_deg[idx];
    }
    int lane = t&31, w = t>>5;
    int v = s;
    #pragma unroll
    for (int o=1;o<32;o<<=1){ int u = __shfl_up_sync(~0u, v, o); if (lane>=o) v += u; }
    if (lane==31) wsum[w] = v;
    __syncthreads();
    if (w==0){
        int x = wsum[lane];
        #pragma unroll
        for (int o=1;o<32;o<<=1){ int u = __shfl_up_sync(~0u, x, o); if (lane>=o) x += u; }
        wsum[lane] = x;
    }
    __syncthreads();
    int excl = v - s + (w>0 ? wsum[w-1] : 0);
    int run = excl;
    for (int j=0;j<SCAN_CH;j++){
        int idx = base+j;
        if (idx < NPAD){
            g_roff[idx] = run;
            g_cur[idx]  = run;
            run += g_deg[idx];
        }
    }
    if (t == 1023) g_roff[NPAD] = run;
}

// ---------------- fill CSR edge lists -----------------------------------------
__global__ void fill_kernel(){
    int p = blockIdx.x*256 + threadIdx.x;
    int e0 = g_e0[p], e1 = g_e1[p];
    float d = g_decay[p];
    int i0 = atomicAdd(&g_cur[e0], 1);
    g_nbr[i0] = e1; g_w[i0] = d;
    int i1 = atomicAdd(&g_cur[e1], 1);
    g_nbr[i1] = e0; g_w[i1] = d;
}

// ---------------- HMMA GEMM, fused 3-phase hi/lo -----------------------------
// Per 32-wide K chunk: ah, al, wh, wl tiles in smem; accumulate
// ah*wh + al*wh + ah*wl with operand-register reuse (wh shared by ph0/ph1,
// ah shared by ph0/ph2): 12 ldmatrix.x4 per ks instead of 18.
#define PITCH 80
#define TSZ   (128*PITCH)      // 10240 B, one tile (128 rows x 32 bf16)
#define STAGE (4*TSZ)          // 40960 B: ah | al | wh | wl
__global__ void __launch_bounds__(256, 2) tgemm_kernel(
    const float* __restrict__ A32,
    const __nv_bfloat16* __restrict__ Ah, const __nv_bfloat16* __restrict__ Al, int lda,
    const __nv_bfloat16* __restrict__ Wh, const __nv_bfloat16* __restrict__ Wl,
    const float* __restrict__ bias,
    int K, int Nout,
    float* C32, int ldc32,
    __nv_bfloat16* Ch, __nv_bfloat16* Cl, int ldcb,
    int act)
{
    extern __shared__ __align__(128) uint8_t sm[];   // 2*STAGE dynamic
    uint32_t smBase = smem_u32(sm);

    int tid = threadIdx.x, lane = tid & 31, wid = tid >> 5;
    int wm = wid & 3, wn = wid >> 2;
    int bx = blockIdx.x, by = blockIdx.y;
    int sp = g_tilesp[by];

    const __nv_bfloat16* WhS = Wh + ((size_t)sp*Nout + bx*128)*K;
    const __nv_bfloat16* WlS = Wl + ((size_t)sp*Nout + bx*128)*K;

    float d[2][8][4];
    #pragma unroll
    for (int i=0;i<2;i++)
        #pragma unroll
        for (int j=0;j<8;j++)
            #pragma unroll
            for (int q=0;q<4;q++) d[i][j][q]=0.f;

    int nkc = K >> 5;   // 32-wide K chunks

    uint32_t aoff = (uint32_t)((wm*32 + (lane & 15))*PITCH + ((lane >> 4) & 1)*16);
    uint32_t boff = (uint32_t)((wn*64 + (lane & 7) + ((lane >> 4) & 1)*8)*PITCH + ((lane >> 3) & 1)*16);

    auto do_mma = [&](int buf){
        uint32_t base = smBase + (uint32_t)buf*STAGE;
        #pragma unroll
        for (int ks=0; ks<2; ks++){
            uint32_t ah_[2][4], al_[2][4], b_[4][4];
            uint32_t aT = base + aoff + ks*32;
            uint32_t bT = base + boff + ks*32;
            // wh + ah
            #pragma unroll
            for (int mi=0; mi<2; mi++) ldsm4(ah_[mi], aT + mi*16*PITCH);
            #pragma unroll
            for (int np_=0; np_<4; np_++) ldsm4(b_[np_], bT + 2*TSZ + np_*16*PITCH);
            #pragma unroll
            for (int mi=0; mi<2; mi++)
                #pragma unroll
                for (int nj=0; nj<8; nj++)
                    mma16816(d[mi][nj], ah_[mi], b_[nj>>1][(nj&1)*2], b_[nj>>1][(nj&1)*2+1]);
            // al (reuse wh)
            #pragma unroll
            for (int mi=0; mi<2; mi++) ldsm4(al_[mi], aT + TSZ + mi*16*PITCH);
            #pragma unroll
            for (int mi=0; mi<2; mi++)
                #pragma unroll
                for (int nj=0; nj<8; nj++)
                    mma16816(d[mi][nj], al_[mi], b_[nj>>1][(nj&1)*2], b_[nj>>1][(nj&1)*2+1]);
            // wl (reuse ah)
            #pragma unroll
            for (int np_=0; np_<4; np_++) ldsm4(b_[np_], bT + 3*TSZ + np_*16*PITCH);
            #pragma unroll
            for (int mi=0; mi<2; mi++)
                #pragma unroll
                for (int nj=0; nj<8; nj++)
                    mma16816(d[mi][nj], ah_[mi], b_[nj>>1][(nj&1)*2], b_[nj>>1][(nj&1)*2+1]);
        }
    };

    if (A32 == nullptr){
        // ---- bf16 A path: 8 cp.async slots cover 4 tiles ----
        const __nv_bfloat16* AhR = Ah + (size_t)by*128*lda;
        const __nv_bfloat16* AlR = Al + (size_t)by*128*lda;
        int itTile[8], itRow[8], itSeg[8];
        #pragma unroll
        for (int t=0;t<8;t++){
            int it = tid + t*256;
            itTile[t] = it >> 9;
            int j = it & 511;
            itRow[t] = j >> 2; itSeg[t] = j & 3;
        }
        auto load_chunk = [&](int kc, int buf){
            uint32_t base = smBase + (uint32_t)buf*STAGE;
            #pragma unroll
            for (int t=0;t<8;t++){
                int tile = itTile[t], row = itRow[t], seg = itSeg[t];
                const __nv_bfloat16* src;
                switch (tile){
                    case 0: src = AhR + (size_t)row*lda; break;
                    case 1: src = AlR + (size_t)row*lda; break;
                    case 2: src = WhS + (size_t)row*K;   break;
                    default:src = WlS + (size_t)row*K;   break;
                }
                src += kc*32 + seg*8;
                cp16(base + tile*TSZ + row*PITCH + seg*16, src);
            }
            cp_commit();
        };
        load_chunk(0, 0);
        for (int c=0; c<nkc; c++){
            int buf = c & 1;
            if (c+1 < nkc){ load_chunk(c+1, buf^1); cp_wait<1>(); }
            else cp_wait<0>();
            __syncthreads();
            do_mma(buf);
            __syncthreads();
        }
    } else {
        // ---- fp32 A path (pass-0): LDG.128 + in-register hi/lo split ----
        const float* aptr[4];
        bool avalid[4];
        int aRow[4], aSeg[4];
        #pragma unroll
        for (int t=0;t<4;t++){
            int j = tid + t*256;
            aRow[t] = j >> 3; aSeg[t] = j & 7;
            int src = g_n2o[by*128 + aRow[t]];
            avalid[t] = (src >= 0);
            aptr[t] = A32 + (size_t)(src < 0 ? 0 : src)*AEV;
        }
        auto loadW = [&](int kc, int buf){
            uint32_t base = smBase + (uint32_t)buf*STAGE;
            #pragma unroll
            for (int t=0;t<4;t++){
                int j = tid + t*256;
                int tile = 2 + (j >> 9);
                int row = (j >> 2) & 127, seg = j & 3;
                const __nv_bfloat16* src = (tile==3 ? WlS : WhS) + (size_t)row*K + kc*32 + seg*8;
                cp16(base + tile*TSZ + row*PITCH + seg*16, src);
            }
            cp_commit();
        };
        float4 R[4];
        auto ldgA = [&](int kc){
            #pragma unroll
            for (int t=0;t<4;t++){
                int col = kc*32 + aSeg[t]*4;
                if (avalid[t] && col < AEV) R[t] = *(const float4*)(aptr[t] + col);
                else R[t] = make_float4(0.f,0.f,0.f,0.f);
            }
        };
        auto stsA = [&](int buf){
            uint32_t base = (uint32_t)buf*STAGE;
            #pragma unroll
            for (int t=0;t<4;t++){
                float a[4] = {R[t].x, R[t].y, R[t].z, R[t].w};
                __nv_bfloat16 h[4], l[4];
                #pragma unroll
                for (int q=0;q<4;q++) split_hl(a[q], h[q], l[q]);
                uint32_t off = base + (uint32_t)(aRow[t]*PITCH + aSeg[t]*8);
                *(uint64_t*)(sm + off)       = *(const uint64_t*)h;
                *(uint64_t*)(sm + off + TSZ) = *(const uint64_t*)l;
            }
        };
        ldgA(0);
        loadW(0, 0);
        for (int c=0; c<nkc; c++){
            int buf = c & 1;
            stsA(buf);
            if (c+1 < nkc){ ldgA(c+1); loadW(c+1, buf^1); cp_wait<1>(); }
            else cp_wait<0>();
            __syncthreads();
            do_mma(buf);
            __syncthreads();
        }
    }

    const float* bp = bias + sp*Nout + bx*128 + wn*64;
    int rowLo = wm*32 + (lane >> 2);
    int colCta = bx*128 + wn*64;
    #pragma unroll
    for (int mi=0; mi<2; mi++){
        #pragma unroll
        for (int nj=0; nj<8; nj++){
            int c0 = nj*8 + 2*(lane & 3);
            float b0 = bp[c0], b1 = bp[c0+1];
            #pragma unroll
            for (int h=0; h<2; h++){
                size_t gr = (size_t)by*128 + rowLo + mi*16 + h*8;
                float x0 = d[mi][nj][2*h]   + b0;
                float x1 = d[mi][nj][2*h+1] + b1;
                if (act){ x0 = gelu_tanh(x0); x1 = gelu_tanh(x1); }
                int col = colCta + c0;
                if (C32){
                    *(float2*)(C32 + gr*ldc32 + col) = make_float2(x0, x1);
                }
                if (Ch){
                    __nv_bfloat16 h0,l0,h1,l1;
                    split_hl(x0,h0,l0); split_hl(x1,h1,l1);
                    uint32_t hh = (uint32_t)__bfloat16_as_ushort(h0) |
                                  ((uint32_t)__bfloat16_as_ushort(h1) << 16);
                    uint32_t ll = (uint32_t)__bfloat16_as_ushort(l0) |
                                  ((uint32_t)__bfloat16_as_ushort(l1) << 16);
                    *(uint32_t*)(Ch + gr*ldcb + col) = hh;
                    *(uint32_t*)(Cl + gr*ldcb + col) = ll;
                }
            }
        }
    }
}

// ---------------- CSR gather: merged[r][t] = sum_nb neigh[nb][t]*w ----------
__global__ void __launch_bounds__(128) mpgather_kernel(int mode){
    int r = blockIdx.x, t = threadIdx.x;
    int s = g_roff[r], e = g_roff[r+1];
    float acc = 0.f;
    int j = s;
    for (; j+1 < e; j += 2){
        int nb0 = g_nbr[j], nb1 = g_nbr[j+1];
        float w0 = g_w[j],  w1 = g_w[j+1];
        float x0 = g_neigh[(size_t)nb0*NOUT + t];
        float x1 = g_neigh[(size_t)nb1*NOUT + t];
        acc = fmaf(x0, w0, acc);
        acc = fmaf(x1, w1, acc);
    }
    if (j < e)
        acc = fmaf(g_neigh[(size_t)g_nbr[j]*NOUT + t], g_w[j], acc);
    if (mode == 0){
        __nv_bfloat16 h, l; split_hl(acc, h, l);
        g_f1h[(size_t)r*FIN + 256 + t] = h;
        g_f1l[(size_t)r*FIN + 256 + t] = l;
    } else {
        g_feat2[(size_t)r*FIN + 256 + t] = acc;
    }
}

// ---------------- final routed linear (FIN->1) + outputs --------------------
__global__ void __launch_bounds__(256) final_kernel(const int* __restrict__ species,
                                                    const float* __restrict__ Wf,
                                                    const float* __restrict__ bf,
                                                    float* __restrict__ out){
    int gt = blockIdx.x*256 + threadIdx.x;
    int i = gt >> 5, lane = gt & 31;
    if (i >= NATOMS) return;
    int s = species[i];
    int r = g_p2n[i];
    const float* f = g_feat2 + (size_t)r*FIN;
    const float* w = Wf + s*FIN;
    float sum = 0.f;
    #pragma unroll
    for (int j=0;j<12;j++){
        int k = lane + 32*j;
        sum = fmaf(f[k], w[k], sum);
    }
    #pragma unroll
    for (int o=16;o;o>>=1) sum += __shfl_xor_sync(0xffffffffu, sum, o);
    if (lane == 0){
        float pre = sum + bf[s];
        g_pre[i] = pre;
        out[2*NATOMS + i] = pre;
        out[i] = (float)s;
    }
}

// ---------------- per-molecule charge redistribution -------------------------
__global__ void charge_kernel(const float* __restrict__ tq, float* __restrict__ out){
    __shared__ float ss[4];
    int b = blockIdx.x, a = threadIdx.x;
    float p = g_pre[b*NA + a];
    float v = p;
    #pragma unroll
    for (int o=16;o;o>>=1) v += __shfl_xor_sync(0xffffffffu, v, o);
    int w = a>>5, lane = a&31;
    if (lane == 0) ss[w] = v;
    __syncthreads();
    float sum = ss[0]+ss[1]+ss[2]+ss[3];
    out[NATOMS + b*NA + a] = p + (tq[b] - sum)*(1.0f/128.0f);
}

// ---------------- launch -----------------------------------------------------
extern "C" void kernel_launch(void* const* d_in, const int* in_sizes, int n_in,
                              void* d_out, int out_size){
    const int*   species = (const int*)  d_in[0];
    const float* aev     = (const float*)d_in[1];
    const int*   ai12    = (const int*)  d_in[2];
    const float* dist    = (const float*)d_in[3];
    const float* tq      = (const float*)d_in[4];
    const float* Wm0     = (const float*)d_in[5];
    const float* bm0     = (const float*)d_in[6];
    const float* Wn0     = (const float*)d_in[7];
    const float* bn0     = (const float*)d_in[8];
    const float* Wm1     = (const float*)d_in[9];
    const float* bm1     = (const float*)d_in[10];
    const float* Wn1     = (const float*)d_in[11];
    const float* bn1     = (const float*)d_in[12];
    const float* Wf      = (const float*)d_in[13];
    const float* bf      = (const float*)d_in[14];
    const float* factor  = (const float*)d_in[15];
    const float* prefac  = (const float*)d_in[16];
    float* out = (float*)d_out;

    __nv_bfloat16 *f1h, *f1l, *f2h, *f2l;
    __nv_bfloat16 *wm0h, *wm0l, *wn0h, *wn0l, *wm1h, *wm1l, *wn1h, *wn1l;
    float *feat2, *neigh;
    cudaGetSymbolAddress((void**)&f1h,  g_f1h);
    cudaGetSymbolAddress((void**)&f1l,  g_f1l);
    cudaGetSymbolAddress((void**)&f2h,  g_f2h);
    cudaGetSymbolAddress((void**)&f2l,  g_f2l);
    cudaGetSymbolAddress((void**)&wm0h, g_wm0h);
    cudaGetSymbolAddress((void**)&wm0l, g_wm0l);
    cudaGetSymbolAddress((void**)&wn0h, g_wn0h);
    cudaGetSymbolAddress((void**)&wn0l, g_wn0l);
    cudaGetSymbolAddress((void**)&wm1h, g_wm1h);
    cudaGetSymbolAddress((void**)&wm1l, g_wm1l);
    cudaGetSymbolAddress((void**)&wn1h, g_wn1h);
    cudaGetSymbolAddress((void**)&wn1l, g_wn1l);
    cudaGetSymbolAddress((void**)&feat2, g_feat2);
    cudaGetSymbolAddress((void**)&neigh, g_neigh);

    cudaFuncSetAttribute(tgemm_kernel, cudaFuncAttributeMaxDynamicSharedMemorySize, 2*STAGE);

    // side streams + events (created once; never destroyed -> capture-safe)
    static cudaStream_t s1 = 0, s2 = 0;
    static cudaEvent_t evStart = 0, evPerm = 0, evW0m = 0, evWrest = 0, evCsr = 0;
    if (!s1){
        cudaStreamCreateWithFlags(&s1, cudaStreamNonBlocking);
        cudaStreamCreateWithFlags(&s2, cudaStreamNonBlocking);
        cudaEventCreateWithFlags(&evStart, cudaEventDisableTiming);
        cudaEventCreateWithFlags(&evPerm,  cudaEventDisableTiming);
        cudaEventCreateWithFlags(&evW0m,   cudaEventDisableTiming);
        cudaEventCreateWithFlags(&evWrest, cudaEventDisableTiming);
        cudaEventCreateWithFlags(&evCsr,   cudaEventDisableTiming);
    }

    // fork s2: weight prep (independent of everything)
    cudaEventRecord(evStart, 0);
    cudaStreamWaitEvent(s2, evStart, 0);
    wprep_kernel<<<(NSP*MO*AEVP)/256, 256, 0, s2>>>(Wm0, wm0h, wm0l, AEV, MO, AEVP);
    cudaEventRecord(evW0m, s2);
    wprep_kernel<<<(NSP*NOUT*MO)/256, 256, 0, s2>>>(Wn0, wn0h, wn0l, MO, NOUT, MO);
    wprep_kernel<<<(NSP*MO*FIN)/256, 256, 0, s2>>>(Wm1, wm1h, wm1l, FIN, MO, FIN);
    wprep_kernel<<<(NSP*NOUT*MO)/256, 256, 0, s2>>>(Wn1, wn1h, wn1l, MO, NOUT, MO);
    cudaEventRecord(evWrest, s2);

    // main: permutation, then fork s1: CSR build (needs g_p2n / g_deg)
    perm_kernel<<<1, 1024>>>(species);
    cudaEventRecord(evPerm, 0);
    cudaStreamWaitEvent(s1, evPerm, 0);
    edge_kernel<<<NP/256, 256, 0, s1>>>(ai12, dist, factor, prefac);
    scan_kernel<<<1, 1024, 0, s1>>>();
    fill_kernel<<<NP/256, 256, 0, s1>>>();
    cudaEventRecord(evCsr, s1);

    // pass 0 (A = fp32 AEV, loaded+split inside the GEMM)
    cudaStreamWaitEvent(0, evW0m, 0);
    tgemm_kernel<<<dim3(2, NT), 256, 2*STAGE>>>(aev,
                                       (__nv_bfloat16*)0, (__nv_bfloat16*)0, 0,
                                       wm0h, wm0l, bm0,
                                       AEVP, MO, (float*)0, 0, f1h, f1l, FIN, 1);
    cudaStreamWaitEvent(0, evWrest, 0);
    tgemm_kernel<<<dim3(1, NT), 256, 2*STAGE>>>((const float*)0,
                                       f1h, f1l, FIN, wn0h, wn0l, bn0,
                                       MO, NOUT, neigh, NOUT,
                                       (__nv_bfloat16*)0, (__nv_bfloat16*)0, 0, 1);
    cudaStreamWaitEvent(0, evCsr, 0);
    mpgather_kernel<<<NPAD, 128>>>(0);

    // pass 1
    tgemm_kernel<<<dim3(2, NT), 256, 2*STAGE>>>((const float*)0,
                                       f1h, f1l, FIN, wm1h, wm1l, bm1,
                                       FIN, MO, feat2, FIN, f2h, f2l, MO, 1);
    tgemm_kernel<<<dim3(1, NT), 256, 2*STAGE>>>((const float*)0,
                                       f2h, f2l, MO, wn1h, wn1l, bn1,
                                       MO, NOUT, neigh, NOUT,
                                       (__nv_bfloat16*)0, (__nv_bfloat16*)0, 0, 1);
    mpgather_kernel<<<NPAD, 128>>>(1);

    // outputs
    final_kernel <<<NATOMS*32/256, 256>>>(species, Wf, bf, out);
    charge_kernel<<<NB, NA>>>(tq, out);
}

// round 9
// speedup vs baseline: 2.3779x; 1.0021x over previous
#include <cuda_runtime.h>
#include <cuda_bf16.h>
#include <math.h>
#include <stdint.h>

#define NB     256
#define NA     128
#define NATOMS 32768
#define AEV    1008
#define AEVP   1024
#define MO     256
#define NOUT   128
#define FIN    384
#define NP     262144
#define NSP    4
#define NPAD   33280
#define NT     (NPAD/128)

// ---------------- scratch (device globals) ----------------------------------
__device__ __align__(16) __nv_bfloat16 g_f1h[(size_t)NPAD*FIN];
__device__ __align__(16) __nv_bfloat16 g_f1l[(size_t)NPAD*FIN];
__device__ __align__(16) __nv_bfloat16 g_f2h[(size_t)NPAD*MO];
__device__ __align__(16) __nv_bfloat16 g_f2l[(size_t)NPAD*MO];
__device__ float g_feat2[(size_t)NPAD*FIN];     // fp32: internal1 | merged1
__device__ float g_neigh[(size_t)NPAD*NOUT];
__device__ float g_decay[NP];
__device__ int   g_e0[NP], g_e1[NP];
__device__ int   g_p2n[NATOMS];
__device__ int   g_n2o[NPAD];
__device__ int   g_tilesp[NT];
__device__ float g_pre[NATOMS];
// CSR adjacency (rebuilt every launch)
__device__ int   g_deg[NPAD];
__device__ int   g_roff[NPAD+1];
__device__ int   g_cur[NPAD];
__device__ int   g_nbr[2*NP];
__device__ float g_w[2*NP];
// transposed + hi/lo-split weights: [S][Nout][Kpad]
__device__ __align__(16) __nv_bfloat16 g_wm0h[(size_t)NSP*MO*AEVP],  g_wm0l[(size_t)NSP*MO*AEVP];
__device__ __align__(16) __nv_bfloat16 g_wn0h[(size_t)NSP*NOUT*MO],  g_wn0l[(size_t)NSP*NOUT*MO];
__device__ __align__(16) __nv_bfloat16 g_wm1h[(size_t)NSP*MO*FIN],   g_wm1l[(size_t)NSP*MO*FIN];
__device__ __align__(16) __nv_bfloat16 g_wn1h[(size_t)NSP*NOUT*MO],  g_wn1l[(size_t)NSP*NOUT*MO];

// ---------------- small helpers ---------------------------------------------
__device__ __forceinline__ uint32_t smem_u32(const void* p){
    uint32_t a;
    asm("{ .reg .u64 t; cvta.to.shared.u64 t, %1; cvt.u32.u64 %0, t; }" : "=r"(a) : "l"(p));
    return a;
}
__device__ __forceinline__ void cp16(uint32_t dst, const void* src){
    asm volatile("cp.async.cg.shared.global [%0], [%1], 16;" :: "r"(dst), "l"(src) : "memory");
}
__device__ __forceinline__ void cp_commit(){
    asm volatile("cp.async.commit_group;" ::: "memory");
}
template<int N> __device__ __forceinline__ void cp_wait(){
    asm volatile("cp.async.wait_group %0;" :: "n"(N) : "memory");
}
__device__ __forceinline__ void ldsm4(uint32_t* r, uint32_t addr){
    asm volatile("ldmatrix.sync.aligned.m8n8.x4.shared.b16 {%0,%1,%2,%3}, [%4];"
        : "=r"(r[0]),"=r"(r[1]),"=r"(r[2]),"=r"(r[3]) : "r"(addr));
}
__device__ __forceinline__ void mma16816(float* d, const uint32_t* a, uint32_t b0, uint32_t b1){
    asm volatile("mma.sync.aligned.m16n8k16.row.col.f32.bf16.bf16.f32 "
        "{%0,%1,%2,%3}, {%4,%5,%6,%7}, {%8,%9}, {%0,%1,%2,%3};"
        : "+f"(d[0]),"+f"(d[1]),"+f"(d[2]),"+f"(d[3])
        : "r"(a[0]),"r"(a[1]),"r"(a[2]),"r"(a[3]), "r"(b0),"r"(b1));
}
__device__ __forceinline__ float gelu_tanh(float x){
    float t = tanhf(0.7978845608028654f * (x + 0.044715f * x * x * x));
    return 0.5f * x * (1.0f + t);
}
__device__ __forceinline__ void split_hl(float x, __nv_bfloat16& h, __nv_bfloat16& l){
    h = __float2bfloat16(x);
    l = __float2bfloat16(x - __bfloat162float(h));
}

// ---------------- permutation: deterministic species grouping ---------------
__global__ void __launch_bounds__(1024) perm_kernel(const int* __restrict__ species){
    __shared__ int sc[NSP][1024];
    __shared__ int stot[NSP];
    __shared__ int sbase[NSP+1];
    int t = threadIdx.x;
    for (int r = t; r < NPAD; r += 1024){ g_n2o[r] = -1; g_deg[r] = 0; }
    int c0=0,c1=0,c2=0,c3=0;
    int b0 = t*32;
    #pragma unroll
    for (int j=0;j<32;j++){
        int s = species[b0+j];
        c0 += (s==0); c1 += (s==1); c2 += (s==2); c3 += (s==3);
    }
    sc[0][t]=c0; sc[1][t]=c1; sc[2][t]=c2; sc[3][t]=c3;
    __syncthreads();
    if (t < NSP){
        int run = 0;
        for (int i=0;i<1024;i++){ int v=sc[t][i]; sc[t][i]=run; run+=v; }
        stot[t]=run;
    }
    __syncthreads();
    if (t==0){
        int b=0;
        for (int s=0;s<NSP;s++){ sbase[s]=b; b += ((stot[s]+127)>>7)<<7; }
        sbase[NSP]=b;
        for (int tt=0; tt<NT; tt++){
            int rs = tt*128; int sp=0;
            for (int s=1;s<NSP;s++) if (rs >= sbase[s]) sp=s;
            g_tilesp[tt]=sp;
        }
    }
    __syncthreads();
    int run2[NSP] = {0,0,0,0};
    for (int j=0;j<32;j++){
        int i = b0+j; int s = species[i];
        int pos = sbase[s] + sc[s][t] + run2[s];
        run2[s]++;
        g_p2n[i]=pos; g_n2o[pos]=i;
    }
}

// ---------------- weight transpose + split: W[S][K][N] -> T[S][N][Kpad] ----
__global__ void __launch_bounds__(256) wprep_kernel(const float* __restrict__ W,
                                                    __nv_bfloat16* __restrict__ Th,
                                                    __nv_bfloat16* __restrict__ Tl,
                                                    int K, int Nout, int Kpad){
    long idx = (long)blockIdx.x*256 + threadIdx.x;
    long total = (long)NSP*Nout*Kpad;
    if (idx >= total) return;
    int k = idx % Kpad;
    int n = (idx / Kpad) % Nout;
    int s = idx / ((long)Kpad*Nout);
    float v = (k < K) ? W[((size_t)s*K + k)*Nout + n] : 0.f;
    __nv_bfloat16 h, l; split_hl(v, h, l);
    Th[idx] = h; Tl[idx] = l;
}

// ---------------- edges: decay + endpoint remap + degree count ---------------
__global__ void edge_kernel(const int* __restrict__ ai,
                            const float* __restrict__ dist,
                            const float* __restrict__ fa,
                            const float* __restrict__ pf){
    int p = blockIdx.x*256 + threadIdx.x;
    float d = dist[p];
    float factor = fa[0], pre = pf[0];
    float x = fminf(fmaxf(d*(1.0f/5.2f), 0.0f), 1.0f - 1e-6f);
    float f = (d < 5.2f) ? expf(1.0f - 1.0f/(1.0f - x*x)) : 0.0f;
    g_decay[p] = pre*pre*expf(-factor*factor*d)*f;
    int e0 = g_p2n[ai[p]];
    int e1 = g_p2n[ai[NP + p]];
    g_e0[p] = e0; g_e1[p] = e1;
    atomicAdd(&g_deg[e0], 1);
    atomicAdd(&g_deg[e1], 1);
}

// ---------------- exclusive scan of degrees -> row offsets ------------------
#define SCAN_CH 33
__global__ void __launch_bounds__(1024) scan_kernel(){
    __shared__ int wsum[32];
    int t = threadIdx.x;
    int base = t*SCAN_CH;
    int s = 0;
    for (int j=0;j<SCAN_CH;j++){
        int idx = base+j;
        if (idx < NPAD) s += g_deg[idx];
    }
    int lane = t&31, w = t>>5;
    int v = s;
    #pragma unroll
    for (int o=1;o<32;o<<=1){ int u = __shfl_up_sync(~0u, v, o); if (lane>=o) v += u; }
    if (lane==31) wsum[w] = v;
    __syncthreads();
    if (w==0){
        int x = wsum[lane];
        #pragma unroll
        for (int o=1;o<32;o<<=1){ int u = __shfl_up_sync(~0u, x, o); if (lane>=o) x += u; }
        wsum[lane] = x;
    }
    __syncthreads();
    int excl = v - s + (w>0 ? wsum[w-1] : 0);
    int run = excl;
    for (int j=0;j<SCAN_CH;j++){
        int idx = base+j;
        if (idx < NPAD){
            g_roff[idx] = run;
            g_cur[idx]  = run;
            run += g_deg[idx];
        }
    }
    if (t == 1023) g_roff[NPAD] = run;
}

// ---------------- fill CSR edge lists -----------------------------------------
__global__ void fill_kernel(){
    int p = blockIdx.x*256 + threadIdx.x;
    int e0 = g_e0[p], e1 = g_e1[p];
    float d = g_decay[p];
    int i0 = atomicAdd(&g_cur[e0], 1);
    g_nbr[i0] = e1; g_w[i0] = d;
    int i1 = atomicAdd(&g_cur[e1], 1);
    g_nbr[i1] = e0; g_w[i1] = d;
}

// ---------------- HMMA GEMM, fused 3-phase hi/lo, K-windowed -----------------
// Accumulates A[:,kBeg:kEnd] @ W[:,kBeg:kEnd]^T (hi/lo 3-term) on top of
// optional Cin (raw fp32 partials). rawOut=1 stores raw accum (no bias/act).
#define PITCH 80
#define TSZ   (128*PITCH)      // 10240 B, one tile (128 rows x 32 bf16)
#define STAGE (4*TSZ)          // 40960 B: ah | al | wh | wl
__global__ void __launch_bounds__(256, 2) tgemm_kernel(
    const float* __restrict__ A32,
    const __nv_bfloat16* __restrict__ Ah, const __nv_bfloat16* __restrict__ Al, int lda,
    const __nv_bfloat16* __restrict__ Wh, const __nv_bfloat16* __restrict__ Wl,
    const float* __restrict__ bias,
    int kBeg, int kEnd, int Kstride, int Nout,
    float* C32, int ldc32,
    __nv_bfloat16* Ch, __nv_bfloat16* Cl, int ldcb,
    int act, const float* __restrict__ Cin, int rawOut)
{
    extern __shared__ __align__(128) uint8_t sm[];   // 2*STAGE dynamic
    uint32_t smBase = smem_u32(sm);

    int tid = threadIdx.x, lane = tid & 31, wid = tid >> 5;
    int wm = wid & 3, wn = wid >> 2;
    int bx = blockIdx.x, by = blockIdx.y;
    int sp = g_tilesp[by];

    const __nv_bfloat16* WhS = Wh + ((size_t)sp*Nout + bx*128)*Kstride;
    const __nv_bfloat16* WlS = Wl + ((size_t)sp*Nout + bx*128)*Kstride;

    int rowLo = wm*32 + (lane >> 2);
    int colCta = bx*128 + wn*64;

    float d[2][8][4];
    if (Cin){
        #pragma unroll
        for (int mi=0; mi<2; mi++)
            #pragma unroll
            for (int nj=0; nj<8; nj++){
                int c0 = nj*8 + 2*(lane & 3);
                #pragma unroll
                for (int h=0; h<2; h++){
                    size_t gr = (size_t)by*128 + rowLo + mi*16 + h*8;
                    float2 v = *(const float2*)(Cin + gr*ldc32 + colCta + c0);
                    d[mi][nj][2*h] = v.x; d[mi][nj][2*h+1] = v.y;
                }
            }
    } else {
        #pragma unroll
        for (int i=0;i<2;i++)
            #pragma unroll
            for (int j=0;j<8;j++)
                #pragma unroll
                for (int q=0;q<4;q++) d[i][j][q]=0.f;
    }

    int cBeg = kBeg >> 5, cEnd = kEnd >> 5;

    uint32_t aoff = (uint32_t)((wm*32 + (lane & 15))*PITCH + ((lane >> 4) & 1)*16);
    uint32_t boff = (uint32_t)((wn*64 + (lane & 7) + ((lane >> 4) & 1)*8)*PITCH + ((lane >> 3) & 1)*16);

    auto do_mma = [&](int buf){
        uint32_t base = smBase + (uint32_t)buf*STAGE;
        #pragma unroll
        for (int ks=0; ks<2; ks++){
            uint32_t ah_[2][4], al_[2][4], b_[4][4];
            uint32_t aT = base + aoff + ks*32;
            uint32_t bT = base + boff + ks*32;
            #pragma unroll
            for (int mi=0; mi<2; mi++) ldsm4(ah_[mi], aT + mi*16*PITCH);
            #pragma unroll
            for (int np_=0; np_<4; np_++) ldsm4(b_[np_], bT + 2*TSZ + np_*16*PITCH);
            #pragma unroll
            for (int mi=0; mi<2; mi++)
                #pragma unroll
                for (int nj=0; nj<8; nj++)
                    mma16816(d[mi][nj], ah_[mi], b_[nj>>1][(nj&1)*2], b_[nj>>1][(nj&1)*2+1]);
            #pragma unroll
            for (int mi=0; mi<2; mi++) ldsm4(al_[mi], aT + TSZ + mi*16*PITCH);
            #pragma unroll
            for (int mi=0; mi<2; mi++)
                #pragma unroll
                for (int nj=0; nj<8; nj++)
                    mma16816(d[mi][nj], al_[mi], b_[nj>>1][(nj&1)*2], b_[nj>>1][(nj&1)*2+1]);
            #pragma unroll
            for (int np_=0; np_<4; np_++) ldsm4(b_[np_], bT + 3*TSZ + np_*16*PITCH);
            #pragma unroll
            for (int mi=0; mi<2; mi++)
                #pragma unroll
                for (int nj=0; nj<8; nj++)
                    mma16816(d[mi][nj], ah_[mi], b_[nj>>1][(nj&1)*2], b_[nj>>1][(nj&1)*2+1]);
        }
    };

    if (A32 == nullptr){
        // ---- bf16 A path: 8 cp.async slots cover 4 tiles ----
        const __nv_bfloat16* AhR = Ah + (size_t)by*128*lda;
        const __nv_bfloat16* AlR = Al + (size_t)by*128*lda;
        int itTile[8], itRow[8], itSeg[8];
        #pragma unroll
        for (int t=0;t<8;t++){
            int it = tid + t*256;
            itTile[t] = it >> 9;
            int j = it & 511;
            itRow[t] = j >> 2; itSeg[t] = j & 3;
        }
        auto load_chunk = [&](int kc, int buf){
            uint32_t base = smBase + (uint32_t)buf*STAGE;
            #pragma unroll
            for (int t=0;t<8;t++){
                int tile = itTile[t], row = itRow[t], seg = itSeg[t];
                const __nv_bfloat16* src;
                switch (tile){
                    case 0: src = AhR + (size_t)row*lda;     break;
                    case 1: src = AlR + (size_t)row*lda;     break;
                    case 2: src = WhS + (size_t)row*Kstride; break;
                    default:src = WlS + (size_t)row*Kstride; break;
                }
                src += kc*32 + seg*8;
                cp16(base + tile*TSZ + row*PITCH + seg*16, src);
            }
            cp_commit();
        };
        load_chunk(cBeg, 0);
        for (int c=cBeg; c<cEnd; c++){
            int buf = (c - cBeg) & 1;
            if (c+1 < cEnd){ load_chunk(c+1, buf^1); cp_wait<1>(); }
            else cp_wait<0>();
            __syncthreads();
            do_mma(buf);
            __syncthreads();
        }
    } else {
        // ---- fp32 A path (pass-0, kBeg==0): LDG.128 + in-register split ----
        const float* aptr[4];
        bool avalid[4];
        int aRow[4], aSeg[4];
        #pragma unroll
        for (int t=0;t<4;t++){
            int j = tid + t*256;
            aRow[t] = j >> 3; aSeg[t] = j & 7;
            int src = g_n2o[by*128 + aRow[t]];
            avalid[t] = (src >= 0);
            aptr[t] = A32 + (size_t)(src < 0 ? 0 : src)*AEV;
        }
        auto loadW = [&](int kc, int buf){
            uint32_t base = smBase + (uint32_t)buf*STAGE;
            #pragma unroll
            for (int t=0;t<4;t++){
                int j = tid + t*256;
                int tile = 2 + (j >> 9);
                int row = (j >> 2) & 127, seg = j & 3;
                const __nv_bfloat16* src = (tile==3 ? WlS : WhS) + (size_t)row*Kstride + kc*32 + seg*8;
                cp16(base + tile*TSZ + row*PITCH + seg*16, src);
            }
            cp_commit();
        };
        float4 R[4];
        auto ldgA = [&](int kc){
            #pragma unroll
            for (int t=0;t<4;t++){
                int col = kc*32 + aSeg[t]*4;
                if (avalid[t] && col < AEV) R[t] = *(const float4*)(aptr[t] + col);
                else R[t] = make_float4(0.f,0.f,0.f,0.f);
            }
        };
        auto stsA = [&](int buf){
            uint32_t base = (uint32_t)buf*STAGE;
            #pragma unroll
            for (int t=0;t<4;t++){
                float a[4] = {R[t].x, R[t].y, R[t].z, R[t].w};
                __nv_bfloat16 h[4], l[4];
                #pragma unroll
                for (int q=0;q<4;q++) split_hl(a[q], h[q], l[q]);
                uint32_t off = base + (uint32_t)(aRow[t]*PITCH + aSeg[t]*8);
                *(uint64_t*)(sm + off)       = *(const uint64_t*)h;
                *(uint64_t*)(sm + off + TSZ) = *(const uint64_t*)l;
            }
        };
        ldgA(cBeg);
        loadW(cBeg, 0);
        for (int c=cBeg; c<cEnd; c++){
            int buf = (c - cBeg) & 1;
            stsA(buf);
            if (c+1 < cEnd){ ldgA(c+1); loadW(c+1, buf^1); cp_wait<1>(); }
            else cp_wait<0>();
            __syncthreads();
            do_mma(buf);
            __syncthreads();
        }
    }

    const float* bp = bias + sp*Nout + bx*128 + wn*64;
    #pragma unroll
    for (int mi=0; mi<2; mi++){
        #pragma unroll
        for (int nj=0; nj<8; nj++){
            int c0 = nj*8 + 2*(lane & 3);
            float b0 = bp[c0], b1 = bp[c0+1];
            #pragma unroll
            for (int h=0; h<2; h++){
                size_t gr = (size_t)by*128 + rowLo + mi*16 + h*8;
                float x0 = d[mi][nj][2*h];
                float x1 = d[mi][nj][2*h+1];
                if (!rawOut){
                    x0 += b0; x1 += b1;
                    if (act){ x0 = gelu_tanh(x0); x1 = gelu_tanh(x1); }
                }
                int col = colCta + c0;
                if (C32){
                    *(float2*)(C32 + gr*ldc32 + col) = make_float2(x0, x1);
                }
                if (Ch){
                    __nv_bfloat16 h0,l0,h1,l1;
                    split_hl(x0,h0,l0); split_hl(x1,h1,l1);
                    uint32_t hh = (uint32_t)__bfloat16_as_ushort(h0) |
                                  ((uint32_t)__bfloat16_as_ushort(h1) << 16);
                    uint32_t ll = (uint32_t)__bfloat16_as_ushort(l0) |
                                  ((uint32_t)__bfloat16_as_ushort(l1) << 16);
                    *(uint32_t*)(Ch + gr*ldcb + col) = hh;
                    *(uint32_t*)(Cl + gr*ldcb + col) = ll;
                }
            }
        }
    }
}

// ---------------- CSR gather: merged[r][t] = sum_nb neigh[nb][t]*w ----------
__global__ void __launch_bounds__(128) mpgather_kernel(int mode){
    int r = blockIdx.x, t = threadIdx.x;
    int s = g_roff[r], e = g_roff[r+1];
    float acc = 0.f;
    int j = s;
    for (; j+1 < e; j += 2){
        int nb0 = g_nbr[j], nb1 = g_nbr[j+1];
        float w0 = g_w[j],  w1 = g_w[j+1];
        float x0 = g_neigh[(size_t)nb0*NOUT + t];
        float x1 = g_neigh[(size_t)nb1*NOUT + t];
        acc = fmaf(x0, w0, acc);
        acc = fmaf(x1, w1, acc);
    }
    if (j < e)
        acc = fmaf(g_neigh[(size_t)g_nbr[j]*NOUT + t], g_w[j], acc);
    if (mode == 0){
        __nv_bfloat16 h, l; split_hl(acc, h, l);
        g_f1h[(size_t)r*FIN + 256 + t] = h;
        g_f1l[(size_t)r*FIN + 256 + t] = l;
    } else {
        g_feat2[(size_t)r*FIN + 256 + t] = acc;
    }
}

// ---------------- final routed linear (FIN->1) + outputs --------------------
__global__ void __launch_bounds__(256) final_kernel(const int* __restrict__ species,
                                                    const float* __restrict__ Wf,
                                                    const float* __restrict__ bf,
                                                    float* __restrict__ out){
    int gt = blockIdx.x*256 + threadIdx.x;
    int i = gt >> 5, lane = gt & 31;
    if (i >= NATOMS) return;
    int s = species[i];
    int r = g_p2n[i];
    const float* f = g_feat2 + (size_t)r*FIN;
    const float* w = Wf + s*FIN;
    float sum = 0.f;
    #pragma unroll
    for (int j=0;j<12;j++){
        int k = lane + 32*j;
        sum = fmaf(f[k], w[k], sum);
    }
    #pragma unroll
    for (int o=16;o;o>>=1) sum += __shfl_xor_sync(0xffffffffu, sum, o);
    if (lane == 0){
        float pre = sum + bf[s];
        g_pre[i] = pre;
        out[2*NATOMS + i] = pre;
        out[i] = (float)s;
    }
}

// ---------------- per-molecule charge redistribution -------------------------
__global__ void charge_kernel(const float* __restrict__ tq, float* __restrict__ out){
    __shared__ float ss[4];
    int b = blockIdx.x, a = threadIdx.x;
    float p = g_pre[b*NA + a];
    float v = p;
    #pragma unroll
    for (int o=16;o;o>>=1) v += __shfl_xor_sync(0xffffffffu, v, o);
    int w = a>>5, lane = a&31;
    if (lane == 0) ss[w] = v;
    __syncthreads();
    float sum = ss[0]+ss[1]+ss[2]+ss[3];
    out[NATOMS + b*NA + a] = p + (tq[b] - sum)*(1.0f/128.0f);
}

// ---------------- launch -----------------------------------------------------
extern "C" void kernel_launch(void* const* d_in, const int* in_sizes, int n_in,
                              void* d_out, int out_size){
    const int*   species = (const int*)  d_in[0];
    const float* aev     = (const float*)d_in[1];
    const int*   ai12    = (const int*)  d_in[2];
    const float* dist    = (const float*)d_in[3];
    const float* tq      = (const float*)d_in[4];
    const float* Wm0     = (const float*)d_in[5];
    const float* bm0     = (const float*)d_in[6];
    const float* Wn0     = (const float*)d_in[7];
    const float* bn0     = (const float*)d_in[8];
    const float* Wm1     = (const float*)d_in[9];
    const float* bm1     = (const float*)d_in[10];
    const float* Wn1     = (const float*)d_in[11];
    const float* bn1     = (const float*)d_in[12];
    const float* Wf      = (const float*)d_in[13];
    const float* bf      = (const float*)d_in[14];
    const float* factor  = (const float*)d_in[15];
    const float* prefac  = (const float*)d_in[16];
    float* out = (float*)d_out;

    __nv_bfloat16 *f1h, *f1l, *f2h, *f2l;
    __nv_bfloat16 *wm0h, *wm0l, *wn0h, *wn0l, *wm1h, *wm1l, *wn1h, *wn1l;
    float *feat2, *neigh;
    cudaGetSymbolAddress((void**)&f1h,  g_f1h);
    cudaGetSymbolAddress((void**)&f1l,  g_f1l);
    cudaGetSymbolAddress((void**)&f2h,  g_f2h);
    cudaGetSymbolAddress((void**)&f2l,  g_f2l);
    cudaGetSymbolAddress((void**)&wm0h, g_wm0h);
    cudaGetSymbolAddress((void**)&wm0l, g_wm0l);
    cudaGetSymbolAddress((void**)&wn0h, g_wn0h);
    cudaGetSymbolAddress((void**)&wn0l, g_wn0l);
    cudaGetSymbolAddress((void**)&wm1h, g_wm1h);
    cudaGetSymbolAddress((void**)&wm1l, g_wm1l);
    cudaGetSymbolAddress((void**)&wn1h, g_wn1h);
    cudaGetSymbolAddress((void**)&wn1l, g_wn1l);
    cudaGetSymbolAddress((void**)&feat2, g_feat2);
    cudaGetSymbolAddress((void**)&neigh, g_neigh);

    cudaFuncSetAttribute(tgemm_kernel, cudaFuncAttributeMaxDynamicSharedMemorySize, 2*STAGE);

    // side streams + events (created once; never destroyed -> capture-safe)
    static cudaStream_t s1 = 0, s2 = 0;
    static cudaEvent_t evStart=0, evPerm=0, evW0m=0, evW1m=0, evWn0=0, evWrest=0,
                       evCsr=0, evG0m=0, evPart1=0;
    if (!s1){
        cudaStreamCreateWithFlags(&s1, cudaStreamNonBlocking);
        cudaStreamCreateWithFlags(&s2, cudaStreamNonBlocking);
        cudaEventCreateWithFlags(&evStart, cudaEventDisableTiming);
        cudaEventCreateWithFlags(&evPerm,  cudaEventDisableTiming);
        cudaEventCreateWithFlags(&evW0m,   cudaEventDisableTiming);
        cudaEventCreateWithFlags(&evW1m,   cudaEventDisableTiming);
        cudaEventCreateWithFlags(&evWn0,   cudaEventDisableTiming);
        cudaEventCreateWithFlags(&evWrest, cudaEventDisableTiming);
        cudaEventCreateWithFlags(&evCsr,   cudaEventDisableTiming);
        cudaEventCreateWithFlags(&evG0m,   cudaEventDisableTiming);
        cudaEventCreateWithFlags(&evPart1, cudaEventDisableTiming);
    }

    // fork s2: weight prep (order: wm0 first, then wm1 for part1, then wn0, wn1)
    cudaEventRecord(evStart, 0);
    cudaStreamWaitEvent(s2, evStart, 0);
    wprep_kernel<<<(NSP*MO*AEVP)/256, 256, 0, s2>>>(Wm0, wm0h, wm0l, AEV, MO, AEVP);
    cudaEventRecord(evW0m, s2);
    wprep_kernel<<<(NSP*MO*FIN)/256, 256, 0, s2>>>(Wm1, wm1h, wm1l, FIN, MO, FIN);
    cudaEventRecord(evW1m, s2);
    wprep_kernel<<<(NSP*NOUT*MO)/256, 256, 0, s2>>>(Wn0, wn0h, wn0l, MO, NOUT, MO);
    cudaEventRecord(evWn0, s2);
    wprep_kernel<<<(NSP*NOUT*MO)/256, 256, 0, s2>>>(Wn1, wn1h, wn1l, MO, NOUT, MO);
    cudaEventRecord(evWrest, s2);

    // main: permutation; fork s1: CSR build
    perm_kernel<<<1, 1024>>>(species);
    cudaEventRecord(evPerm, 0);
    cudaStreamWaitEvent(s1, evPerm, 0);
    edge_kernel<<<NP/256, 256, 0, s1>>>(ai12, dist, factor, prefac);
    scan_kernel<<<1, 1024, 0, s1>>>();
    fill_kernel<<<NP/256, 256, 0, s1>>>();
    cudaEventRecord(evCsr, s1);

    // pass 0 big GEMM (A = fp32 AEV, loaded+split inside)
    cudaStreamWaitEvent(0, evW0m, 0);
    tgemm_kernel<<<dim3(2, NT), 256, 2*STAGE>>>(aev,
        (__nv_bfloat16*)0, (__nv_bfloat16*)0, 0, wm0h, wm0l, bm0,
        0, AEVP, AEVP, MO, (float*)0, 0, f1h, f1l, FIN, 1, (const float*)0, 0);
    cudaEventRecord(evG0m, 0);

    // s1: gemm1m part1 (K 0:256, internal0 only) concurrent with gemm0n+mpgather0
    cudaStreamWaitEvent(s1, evG0m, 0);
    cudaStreamWaitEvent(s1, evW1m, 0);
    tgemm_kernel<<<dim3(2, NT), 256, 2*STAGE, s1>>>((const float*)0,
        f1h, f1l, FIN, wm1h, wm1l, bm1,
        0, 256, FIN, MO, feat2, FIN, (__nv_bfloat16*)0, (__nv_bfloat16*)0, 0,
        0, (const float*)0, 1);
    cudaEventRecord(evPart1, s1);

    // main: gemm0n -> mpgather0
    cudaStreamWaitEvent(0, evWn0, 0);
    tgemm_kernel<<<dim3(1, NT), 256, 2*STAGE>>>((const float*)0,
        f1h, f1l, FIN, wn0h, wn0l, bn0,
        0, 256, MO, NOUT, neigh, NOUT, (__nv_bfloat16*)0, (__nv_bfloat16*)0, 0,
        1, (const float*)0, 0);
    cudaStreamWaitEvent(0, evCsr, 0);
    mpgather_kernel<<<NPAD, 128>>>(0);

    // main: gemm1m part2 (K 256:384, merged0) with accumulator preload
    cudaStreamWaitEvent(0, evPart1, 0);
    tgemm_kernel<<<dim3(2, NT), 256, 2*STAGE>>>((const float*)0,
        f1h, f1l, FIN, wm1h, wm1l, bm1,
        256, 384, FIN, MO, feat2, FIN, f2h, f2l, MO,
        1, feat2, 0);

    // pass 1 small GEMM -> mpgather1
    cudaStreamWaitEvent(0, evWrest, 0);
    tgemm_kernel<<<dim3(1, NT), 256, 2*STAGE>>>((const float*)0,
        f2h, f2l, MO, wn1h, wn1l, bn1,
        0, 256, MO, NOUT, neigh, NOUT, (__nv_bfloat16*)0, (__nv_bfloat16*)0, 0,
        1, (const float*)0, 0);
    mpgather_kernel<<<NPAD, 128>>>(1);

    // outputs
    final_kernel <<<NATOMS*32/256, 256>>>(species, Wf, bf, out);
    charge_kernel<<<NB, NA>>>(tq, out);
}

// round 10
// speedup vs baseline: 2.3824x; 1.0019x over previous
#include <cuda_runtime.h>
#include <cuda_bf16.h>
#include <math.h>
#include <stdint.h>

#define NB     256
#define NA     128
#define NATOMS 32768
#define AEV    1008
#define AEVP   1024
#define MO     256
#define NOUT   128
#define FIN    384
#define NP     262144
#define NSP    4
#define NPAD   33280
#define NT     (NPAD/128)

// ---------------- scratch (device globals) ----------------------------------
__device__ __align__(16) __nv_bfloat16 g_f1h[(size_t)NPAD*FIN];
__device__ __align__(16) __nv_bfloat16 g_f1l[(size_t)NPAD*FIN];
__device__ __align__(16) __nv_bfloat16 g_f2h[(size_t)NPAD*MO];
__device__ __align__(16) __nv_bfloat16 g_f2l[(size_t)NPAD*MO];
__device__ float g_feat2[(size_t)NPAD*FIN];     // fp32: internal1 | merged1
__device__ float g_neigh[(size_t)NPAD*NOUT];
__device__ float g_decay[NP];
__device__ int   g_e0[NP], g_e1[NP];
__device__ int   g_p2n[NATOMS];
__device__ int   g_n2o[NPAD];
__device__ int   g_tilesp[NT];
__device__ float g_pre[NATOMS];
// CSR adjacency (rebuilt every launch)
__device__ int   g_deg[NPAD];
__device__ int   g_roff[NPAD+1];
__device__ int   g_cur[NPAD];
__device__ int   g_nbr[2*NP];
__device__ float g_w[2*NP];
// transposed + hi/lo-split weights: [S][Nout][Kpad]
__device__ __align__(16) __nv_bfloat16 g_wm0h[(size_t)NSP*MO*AEVP],  g_wm0l[(size_t)NSP*MO*AEVP];
__device__ __align__(16) __nv_bfloat16 g_wn0h[(size_t)NSP*NOUT*MO],  g_wn0l[(size_t)NSP*NOUT*MO];
__device__ __align__(16) __nv_bfloat16 g_wm1h[(size_t)NSP*MO*FIN],   g_wm1l[(size_t)NSP*MO*FIN];
__device__ __align__(16) __nv_bfloat16 g_wn1h[(size_t)NSP*NOUT*MO],  g_wn1l[(size_t)NSP*NOUT*MO];

// ---------------- small helpers ---------------------------------------------
__device__ __forceinline__ uint32_t smem_u32(const void* p){
    uint32_t a;
    asm("{ .reg .u64 t; cvta.to.shared.u64 t, %1; cvt.u32.u64 %0, t; }" : "=r"(a) : "l"(p));
    return a;
}
__device__ __forceinline__ void cp16(uint32_t dst, const void* src){
    asm volatile("cp.async.cg.shared.global [%0], [%1], 16;" :: "r"(dst), "l"(src) : "memory");
}
__device__ __forceinline__ void cp_commit(){
    asm volatile("cp.async.commit_group;" ::: "memory");
}
template<int N> __device__ __forceinline__ void cp_wait(){
    asm volatile("cp.async.wait_group %0;" :: "n"(N) : "memory");
}
__device__ __forceinline__ void ldsm4(uint32_t* r, uint32_t addr){
    asm volatile("ldmatrix.sync.aligned.m8n8.x4.shared.b16 {%0,%1,%2,%3}, [%4];"
        : "=r"(r[0]),"=r"(r[1]),"=r"(r[2]),"=r"(r[3]) : "r"(addr));
}
__device__ __forceinline__ void mma16816(float* d, const uint32_t* a, uint32_t b0, uint32_t b1){
    asm volatile("mma.sync.aligned.m16n8k16.row.col.f32.bf16.bf16.f32 "
        "{%0,%1,%2,%3}, {%4,%5,%6,%7}, {%8,%9}, {%0,%1,%2,%3};"
        : "+f"(d[0]),"+f"(d[1]),"+f"(d[2]),"+f"(d[3])
        : "r"(a[0]),"r"(a[1]),"r"(a[2]),"r"(a[3]), "r"(b0),"r"(b1));
}
__device__ __forceinline__ float gelu_tanh(float x){
    float t = tanhf(0.7978845608028654f * (x + 0.044715f * x * x * x));
    return 0.5f * x * (1.0f + t);
}
__device__ __forceinline__ void split_hl(float x, __nv_bfloat16& h, __nv_bfloat16& l){
    h = __float2bfloat16(x);
    l = __float2bfloat16(x - __bfloat162float(h));
}

// ---------------- permutation: deterministic species grouping ---------------
__global__ void __launch_bounds__(1024) perm_kernel(const int* __restrict__ species){
    __shared__ int sc[NSP][1024];
    __shared__ int stot[NSP];
    __shared__ int sbase[NSP+1];
    int t = threadIdx.x;
    for (int r = t; r < NPAD; r += 1024){ g_n2o[r] = -1; g_deg[r] = 0; }
    int c0=0,c1=0,c2=0,c3=0;
    int b0 = t*32;
    #pragma unroll
    for (int j=0;j<32;j++){
        int s = species[b0+j];
        c0 += (s==0); c1 += (s==1); c2 += (s==2); c3 += (s==3);
    }
    sc[0][t]=c0; sc[1][t]=c1; sc[2][t]=c2; sc[3][t]=c3;
    __syncthreads();
    if (t < NSP){
        int run = 0;
        for (int i=0;i<1024;i++){ int v=sc[t][i]; sc[t][i]=run; run+=v; }
        stot[t]=run;
    }
    __syncthreads();
    if (t==0){
        int b=0;
        for (int s=0;s<NSP;s++){ sbase[s]=b; b += ((stot[s]+127)>>7)<<7; }
        sbase[NSP]=b;
        for (int tt=0; tt<NT; tt++){
            int rs = tt*128; int sp=0;
            for (int s=1;s<NSP;s++) if (rs >= sbase[s]) sp=s;
            g_tilesp[tt]=sp;
        }
    }
    __syncthreads();
    int run2[NSP] = {0,0,0,0};
    for (int j=0;j<32;j++){
        int i = b0+j; int s = species[i];
        int pos = sbase[s] + sc[s][t] + run2[s];
        run2[s]++;
        g_p2n[i]=pos; g_n2o[pos]=i;
    }
}

// ---------------- weight transpose + split: W[S][K][N] -> T[S][N][Kpad] ----
__global__ void __launch_bounds__(256) wprep_kernel(const float* __restrict__ W,
                                                    __nv_bfloat16* __restrict__ Th,
                                                    __nv_bfloat16* __restrict__ Tl,
                                                    int K, int Nout, int Kpad){
    long idx = (long)blockIdx.x*256 + threadIdx.x;
    long total = (long)NSP*Nout*Kpad;
    if (idx >= total) return;
    int k = idx % Kpad;
    int n = (idx / Kpad) % Nout;
    int s = idx / ((long)Kpad*Nout);
    float v = (k < K) ? W[((size_t)s*K + k)*Nout + n] : 0.f;
    __nv_bfloat16 h, l; split_hl(v, h, l);
    Th[idx] = h; Tl[idx] = l;
}

// ---------------- edges: decay + endpoint remap + degree count ---------------
__global__ void edge_kernel(const int* __restrict__ ai,
                            const float* __restrict__ dist,
                            const float* __restrict__ fa,
                            const float* __restrict__ pf){
    int p = blockIdx.x*256 + threadIdx.x;
    float d = dist[p];
    float factor = fa[0], pre = pf[0];
    float x = fminf(fmaxf(d*(1.0f/5.2f), 0.0f), 1.0f - 1e-6f);
    float f = (d < 5.2f) ? expf(1.0f - 1.0f/(1.0f - x*x)) : 0.0f;
    g_decay[p] = pre*pre*expf(-factor*factor*d)*f;
    int e0 = g_p2n[ai[p]];
    int e1 = g_p2n[ai[NP + p]];
    g_e0[p] = e0; g_e1[p] = e1;
    atomicAdd(&g_deg[e0], 1);
    atomicAdd(&g_deg[e1], 1);
}

// ---------------- exclusive scan of degrees -> row offsets ------------------
#define SCAN_CH 33
__global__ void __launch_bounds__(1024) scan_kernel(){
    __shared__ int wsum[32];
    int t = threadIdx.x;
    int base = t*SCAN_CH;
    int s = 0;
    for (int j=0;j<SCAN_CH;j++){
        int idx = base+j;
        if (idx < NPAD) s += g_deg[idx];
    }
    int lane = t&31, w = t>>5;
    int v = s;
    #pragma unroll
    for (int o=1;o<32;o<<=1){ int u = __shfl_up_sync(~0u, v, o); if (lane>=o) v += u; }
    if (lane==31) wsum[w] = v;
    __syncthreads();
    if (w==0){
        int x = wsum[lane];
        #pragma unroll
        for (int o=1;o<32;o<<=1){ int u = __shfl_up_sync(~0u, x, o); if (lane>=o) x += u; }
        wsum[lane] = x;
    }
    __syncthreads();
    int excl = v - s + (w>0 ? wsum[w-1] : 0);
    int run = excl;
    for (int j=0;j<SCAN_CH;j++){
        int idx = base+j;
        if (idx < NPAD){
            g_roff[idx] = run;
            g_cur[idx]  = run;
            run += g_deg[idx];
        }
    }
    if (t == 1023) g_roff[NPAD] = run;
}

// ---------------- fill CSR edge lists -----------------------------------------
__global__ void fill_kernel(){
    int p = blockIdx.x*256 + threadIdx.x;
    int e0 = g_e0[p], e1 = g_e1[p];
    float d = g_decay[p];
    int i0 = atomicAdd(&g_cur[e0], 1);
    g_nbr[i0] = e1; g_w[i0] = d;
    int i1 = atomicAdd(&g_cur[e1], 1);
    g_nbr[i1] = e0; g_w[i1] = d;
}

#define PITCH 80

// ============ tgemm128: N=128, 2-stage, 2 CTA/SM (bf16 A only) ==============
#define TSZ   (128*PITCH)
#define STAGE (4*TSZ)
__global__ void __launch_bounds__(256, 2) tgemm128_kernel(
    const __nv_bfloat16* __restrict__ Ah, const __nv_bfloat16* __restrict__ Al, int lda,
    const __nv_bfloat16* __restrict__ Wh, const __nv_bfloat16* __restrict__ Wl,
    const float* __restrict__ bias,
    int K, float* C32, int ldc32, int act)
{
    extern __shared__ __align__(128) uint8_t sm[];
    uint32_t smBase = smem_u32(sm);
    const int Nout = 128;

    int tid = threadIdx.x, lane = tid & 31, wid = tid >> 5;
    int wm = wid & 3, wn = wid >> 2;
    int by = blockIdx.x;
    int sp = g_tilesp[by];

    const __nv_bfloat16* AhR = Ah + (size_t)by*128*lda;
    const __nv_bfloat16* AlR = Al + (size_t)by*128*lda;
    const __nv_bfloat16* WhS = Wh + (size_t)sp*Nout*K;
    const __nv_bfloat16* WlS = Wl + (size_t)sp*Nout*K;

    float d[2][8][4];
    #pragma unroll
    for (int i=0;i<2;i++)
        #pragma unroll
        for (int j=0;j<8;j++)
            #pragma unroll
            for (int q=0;q<4;q++) d[i][j][q]=0.f;

    int nkc = K >> 5;

    int itTile[8], itRow[8], itSeg[8];
    #pragma unroll
    for (int t=0;t<8;t++){
        int it = tid + t*256;
        itTile[t] = it >> 9;
        int j = it & 511;
        itRow[t] = j >> 2; itSeg[t] = j & 3;
    }

    uint32_t aoff = (uint32_t)((wm*32 + (lane & 15))*PITCH + ((lane >> 4) & 1)*16);
    uint32_t boff = (uint32_t)((wn*64 + (lane & 7) + ((lane >> 4) & 1)*8)*PITCH + ((lane >> 3) & 1)*16);

    auto load_chunk = [&](int kc, int buf){
        uint32_t base = smBase + (uint32_t)buf*STAGE;
        #pragma unroll
        for (int t=0;t<8;t++){
            int tile = itTile[t], row = itRow[t], seg = itSeg[t];
            const __nv_bfloat16* src;
            switch (tile){
                case 0: src = AhR + (size_t)row*lda; break;
                case 1: src = AlR + (size_t)row*lda; break;
                case 2: src = WhS + (size_t)row*K;   break;
                default:src = WlS + (size_t)row*K;   break;
            }
            src += kc*32 + seg*8;
            cp16(base + tile*TSZ + row*PITCH + seg*16, src);
        }
        cp_commit();
    };

    auto do_mma = [&](int buf){
        uint32_t base = smBase + (uint32_t)buf*STAGE;
        #pragma unroll
        for (int ks=0; ks<2; ks++){
            uint32_t ah_[2][4], al_[2][4], b_[4][4];
            uint32_t aT = base + aoff + ks*32;
            uint32_t bT = base + boff + ks*32;
            #pragma unroll
            for (int mi=0; mi<2; mi++) ldsm4(ah_[mi], aT + mi*16*PITCH);
            #pragma unroll
            for (int np_=0; np_<4; np_++) ldsm4(b_[np_], bT + 2*TSZ + np_*16*PITCH);
            #pragma unroll
            for (int mi=0; mi<2; mi++)
                #pragma unroll
                for (int nj=0; nj<8; nj++)
                    mma16816(d[mi][nj], ah_[mi], b_[nj>>1][(nj&1)*2], b_[nj>>1][(nj&1)*2+1]);
            #pragma unroll
            for (int mi=0; mi<2; mi++) ldsm4(al_[mi], aT + TSZ + mi*16*PITCH);
            #pragma unroll
            for (int mi=0; mi<2; mi++)
                #pragma unroll
                for (int nj=0; nj<8; nj++)
                    mma16816(d[mi][nj], al_[mi], b_[nj>>1][(nj&1)*2], b_[nj>>1][(nj&1)*2+1]);
            #pragma unroll
            for (int np_=0; np_<4; np_++) ldsm4(b_[np_], bT + 3*TSZ + np_*16*PITCH);
            #pragma unroll
            for (int mi=0; mi<2; mi++)
                #pragma unroll
                for (int nj=0; nj<8; nj++)
                    mma16816(d[mi][nj], ah_[mi], b_[nj>>1][(nj&1)*2], b_[nj>>1][(nj&1)*2+1]);
        }
    };

    load_chunk(0, 0);
    for (int c=0; c<nkc; c++){
        int buf = c & 1;
        if (c+1 < nkc){ load_chunk(c+1, buf^1); cp_wait<1>(); }
        else cp_wait<0>();
        __syncthreads();
        do_mma(buf);
        __syncthreads();
    }

    const float* bp = bias + sp*Nout + wn*64;
    int rowLo = wm*32 + (lane >> 2);
    int colCta = wn*64;
    #pragma unroll
    for (int mi=0; mi<2; mi++){
        #pragma unroll
        for (int nj=0; nj<8; nj++){
            int c0 = nj*8 + 2*(lane & 3);
            float b0 = bp[c0], b1 = bp[c0+1];
            #pragma unroll
            for (int h=0; h<2; h++){
                size_t gr = (size_t)by*128 + rowLo + mi*16 + h*8;
                float x0 = d[mi][nj][2*h]   + b0;
                float x1 = d[mi][nj][2*h+1] + b1;
                if (act){ x0 = gelu_tanh(x0); x1 = gelu_tanh(x1); }
                *(float2*)(C32 + gr*ldc32 + colCta + c0) = make_float2(x0, x1);
            }
        }
    }
}

// ============ tgemm256: N=256 mega-CTA, 3-stage, 512 threads ================
// A loaded ONCE per chunk (halves A L2 traffic vs two N=128 CTAs).
#define ATS   10240          // one A tile (128 x 80B)
#define WTS   20480          // one W tile (256 x 80B)
#define STG3  61440          // ah | al | wh | wl
__global__ void __launch_bounds__(512, 1) tgemm256_kernel(
    const float* __restrict__ A32,
    const __nv_bfloat16* __restrict__ Ah, const __nv_bfloat16* __restrict__ Al, int lda,
    const __nv_bfloat16* __restrict__ Wh, const __nv_bfloat16* __restrict__ Wl,
    const float* __restrict__ bias,
    int K,
    float* C32, int ldc32,
    __nv_bfloat16* Ch, __nv_bfloat16* Cl, int ldcb)
{
    extern __shared__ __align__(128) uint8_t sm[];   // 3*STG3 dynamic
    uint32_t smBase = smem_u32(sm);
    const int Nout = 256;

    int tid = threadIdx.x, lane = tid & 31, wid = tid >> 5;
    int wm = wid & 3, wn = wid >> 2;     // 4 x 4 warp grid: 128 x 256
    int by = blockIdx.x;
    int sp = g_tilesp[by];

    const __nv_bfloat16* WhS = Wh + (size_t)sp*Nout*K;
    const __nv_bfloat16* WlS = Wl + (size_t)sp*Nout*K;

    float d[2][8][4];
    #pragma unroll
    for (int i=0;i<2;i++)
        #pragma unroll
        for (int j=0;j<8;j++)
            #pragma unroll
            for (int q=0;q<4;q++) d[i][j][q]=0.f;

    int nkc = K >> 5;

    uint32_t aoff = (uint32_t)((wm*32 + (lane & 15))*PITCH + ((lane >> 4) & 1)*16);
    uint32_t boff = (uint32_t)((wn*64 + (lane & 7) + ((lane >> 4) & 1)*8)*PITCH + ((lane >> 3) & 1)*16);

    auto do_mma = [&](int st){
        uint32_t base = smBase + (uint32_t)st*STG3;
        #pragma unroll
        for (int ks=0; ks<2; ks++){
            uint32_t ah_[2][4], al_[2][4], b_[4][4];
            uint32_t aT = base + aoff + ks*32;
            uint32_t bT = base + 2*ATS + boff + ks*32;
            #pragma unroll
            for (int mi=0; mi<2; mi++) ldsm4(ah_[mi], aT + mi*16*PITCH);
            #pragma unroll
            for (int np_=0; np_<4; np_++) ldsm4(b_[np_], bT + np_*16*PITCH);
            #pragma unroll
            for (int mi=0; mi<2; mi++)
                #pragma unroll
                for (int nj=0; nj<8; nj++)
                    mma16816(d[mi][nj], ah_[mi], b_[nj>>1][(nj&1)*2], b_[nj>>1][(nj&1)*2+1]);
            #pragma unroll
            for (int mi=0; mi<2; mi++) ldsm4(al_[mi], aT + ATS + mi*16*PITCH);
            #pragma unroll
            for (int mi=0; mi<2; mi++)
                #pragma unroll
                for (int nj=0; nj<8; nj++)
                    mma16816(d[mi][nj], al_[mi], b_[nj>>1][(nj&1)*2], b_[nj>>1][(nj&1)*2+1]);
            #pragma unroll
            for (int np_=0; np_<4; np_++) ldsm4(b_[np_], bT + WTS + np_*16*PITCH);
            #pragma unroll
            for (int mi=0; mi<2; mi++)
                #pragma unroll
                for (int nj=0; nj<8; nj++)
                    mma16816(d[mi][nj], ah_[mi], b_[nj>>1][(nj&1)*2], b_[nj>>1][(nj&1)*2+1]);
        }
    };

    if (A32 == nullptr){
        // ---- bf16 A path: A+W via cp.async, 6 x 16B per thread ----
        const __nv_bfloat16* AhR = Ah + (size_t)by*128*lda;
        const __nv_bfloat16* AlR = Al + (size_t)by*128*lda;
        auto load_chunk = [&](int kc, int st){
            uint32_t base = smBase + (uint32_t)st*STG3;
            #pragma unroll
            for (int t=0;t<6;t++){
                int it = tid + t*512;
                const __nv_bfloat16* src; uint32_t dst;
                if (it < 1024){
                    int tile = it >> 9;
                    int j = it & 511;
                    int row = j >> 2, seg = j & 3;
                    src = (tile ? AlR : AhR) + (size_t)row*lda + kc*32 + seg*8;
                    dst = base + (uint32_t)tile*ATS + row*PITCH + seg*16;
                } else {
                    int j = it - 1024;
                    int tile = j >> 10;
                    int jj = j & 1023;
                    int row = jj >> 2, seg = jj & 3;
                    src = (tile ? WlS : WhS) + (size_t)row*K + kc*32 + seg*8;
                    dst = base + 2*ATS + (uint32_t)tile*WTS + row*PITCH + seg*16;
                }
                cp16(dst, src);
            }
            cp_commit();
        };
        load_chunk(0, 0);
        if (nkc > 1) load_chunk(1, 1);
        for (int c=0; c<nkc; c++){
            int st = c % 3;
            if (c+2 < nkc) load_chunk(c+2, (c+2)%3);
            if (c+2 < nkc) cp_wait<2>();
            else if (c+1 < nkc) cp_wait<1>();
            else cp_wait<0>();
            __syncthreads();
            do_mma(st);
            __syncthreads();
        }
    } else {
        // ---- fp32 A path (pass-0): LDG.128 + in-register hi/lo split ----
        const float* aptr[2];
        bool avalid[2];
        int aRow[2], aSeg[2];
        #pragma unroll
        for (int t=0;t<2;t++){
            int j = tid + t*512;
            aRow[t] = j >> 3; aSeg[t] = j & 7;
            int src = g_n2o[by*128 + aRow[t]];
            avalid[t] = (src >= 0);
            aptr[t] = A32 + (size_t)(src < 0 ? 0 : src)*AEV;
        }
        auto loadW = [&](int kc, int st){
            uint32_t base = smBase + (uint32_t)st*STG3 + 2*ATS;
            #pragma unroll
            for (int t=0;t<4;t++){
                int j = tid + t*512;
                int tile = j >> 10;
                int jj = j & 1023;
                int row = jj >> 2, seg = jj & 3;
                const __nv_bfloat16* src = (tile ? WlS : WhS) + (size_t)row*K + kc*32 + seg*8;
                cp16(base + (uint32_t)tile*WTS + row*PITCH + seg*16, src);
            }
            cp_commit();
        };
        float4 R[2];
        auto ldgA = [&](int kc){
            #pragma unroll
            for (int t=0;t<2;t++){
                int col = kc*32 + aSeg[t]*4;
                if (avalid[t] && col < AEV) R[t] = *(const float4*)(aptr[t] + col);
                else R[t] = make_float4(0.f,0.f,0.f,0.f);
            }
        };
        auto stsA = [&](int st){
            uint32_t base = (uint32_t)st*STG3;
            #pragma unroll
            for (int t=0;t<2;t++){
                float a[4] = {R[t].x, R[t].y, R[t].z, R[t].w};
                __nv_bfloat16 h[4], l[4];
                #pragma unroll
                for (int q=0;q<4;q++) split_hl(a[q], h[q], l[q]);
                uint32_t off = base + (uint32_t)(aRow[t]*PITCH + aSeg[t]*8);
                *(uint64_t*)(sm + off)       = *(const uint64_t*)h;
                *(uint64_t*)(sm + off + ATS) = *(const uint64_t*)l;
            }
        };
        loadW(0, 0);
        if (nkc > 1) loadW(1, 1);
        ldgA(0); stsA(0);                 // chunk 0 A in smem
        if (nkc > 1) ldgA(1);             // chunk 1 A held in regs
        for (int c=0; c<nkc; c++){
            int st = c % 3;
            if (c+2 < nkc) loadW(c+2, (c+2)%3);
            if (c+1 < nkc) stsA((c+1)%3); // stage held chunk c-2 (done) or empty
            if (c+2 < nkc) ldgA(c+2);
            if (c+2 < nkc) cp_wait<2>();
            else if (c+1 < nkc) cp_wait<1>();
            else cp_wait<0>();
            __syncthreads();
            do_mma(st);
            __syncthreads();
        }
    }

    const float* bp = bias + sp*Nout + wn*64;
    int rowLo = wm*32 + (lane >> 2);
    int colCta = wn*64;
    #pragma unroll
    for (int mi=0; mi<2; mi++){
        #pragma unroll
        for (int nj=0; nj<8; nj++){
            int c0 = nj*8 + 2*(lane & 3);
            float b0 = bp[c0], b1 = bp[c0+1];
            #pragma unroll
            for (int h=0; h<2; h++){
                size_t gr = (size_t)by*128 + rowLo + mi*16 + h*8;
                float x0 = gelu_tanh(d[mi][nj][2*h]   + b0);
                float x1 = gelu_tanh(d[mi][nj][2*h+1] + b1);
                int col = colCta + c0;
                if (C32){
                    *(float2*)(C32 + gr*ldc32 + col) = make_float2(x0, x1);
                }
                if (Ch){
                    __nv_bfloat16 h0,l0,h1,l1;
                    split_hl(x0,h0,l0); split_hl(x1,h1,l1);
                    uint32_t hh = (uint32_t)__bfloat16_as_ushort(h0) |
                                  ((uint32_t)__bfloat16_as_ushort(h1) << 16);
                    uint32_t ll = (uint32_t)__bfloat16_as_ushort(l0) |
                                  ((uint32_t)__bfloat16_as_ushort(l1) << 16);
                    *(uint32_t*)(Ch + gr*ldcb + col) = hh;
                    *(uint32_t*)(Cl + gr*ldcb + col) = ll;
                }
            }
        }
    }
}

// ---------------- CSR gather: merged[r][t] = sum_nb neigh[nb][t]*w ----------
__global__ void __launch_bounds__(128) mpgather_kernel(int mode){
    int r = blockIdx.x, t = threadIdx.x;
    int s = g_roff[r], e = g_roff[r+1];
    float acc = 0.f;
    int j = s;
    for (; j+1 < e; j += 2){
        int nb0 = g_nbr[j], nb1 = g_nbr[j+1];
        float w0 = g_w[j],  w1 = g_w[j+1];
        float x0 = g_neigh[(size_t)nb0*NOUT + t];
        float x1 = g_neigh[(size_t)nb1*NOUT + t];
        acc = fmaf(x0, w0, acc);
        acc = fmaf(x1, w1, acc);
    }
    if (j < e)
        acc = fmaf(g_neigh[(size_t)g_nbr[j]*NOUT + t], g_w[j], acc);
    if (mode == 0){
        __nv_bfloat16 h, l; split_hl(acc, h, l);
        g_f1h[(size_t)r*FIN + 256 + t] = h;
        g_f1l[(size_t)r*FIN + 256 + t] = l;
    } else {
        g_feat2[(size_t)r*FIN + 256 + t] = acc;
    }
}

// ---------------- final routed linear (FIN->1) + outputs --------------------
__global__ void __launch_bounds__(256) final_kernel(const int* __restrict__ species,
                                                    const float* __restrict__ Wf,
                                                    const float* __restrict__ bf,
                                                    float* __restrict__ out){
    int gt = blockIdx.x*256 + threadIdx.x;
    int i = gt >> 5, lane = gt & 31;
    if (i >= NATOMS) return;
    int s = species[i];
    int r = g_p2n[i];
    const float* f = g_feat2 + (size_t)r*FIN;
    const float* w = Wf + s*FIN;
    float sum = 0.f;
    #pragma unroll
    for (int j=0;j<12;j++){
        int k = lane + 32*j;
        sum = fmaf(f[k], w[k], sum);
    }
    #pragma unroll
    for (int o=16;o;o>>=1) sum += __shfl_xor_sync(0xffffffffu, sum, o);
    if (lane == 0){
        float pre = sum + bf[s];
        g_pre[i] = pre;
        out[2*NATOMS + i] = pre;
        out[i] = (float)s;
    }
}

// ---------------- per-molecule charge redistribution -------------------------
__global__ void charge_kernel(const float* __restrict__ tq, float* __restrict__ out){
    __shared__ float ss[4];
    int b = blockIdx.x, a = threadIdx.x;
    float p = g_pre[b*NA + a];
    float v = p;
    #pragma unroll
    for (int o=16;o;o>>=1) v += __shfl_xor_sync(0xffffffffu, v, o);
    int w = a>>5, lane = a&31;
    if (lane == 0) ss[w] = v;
    __syncthreads();
    float sum = ss[0]+ss[1]+ss[2]+ss[3];
    out[NATOMS + b*NA + a] = p + (tq[b] - sum)*(1.0f/128.0f);
}

// ---------------- launch -----------------------------------------------------
extern "C" void kernel_launch(void* const* d_in, const int* in_sizes, int n_in,
                              void* d_out, int out_size){
    const int*   species = (const int*)  d_in[0];
    const float* aev     = (const float*)d_in[1];
    const int*   ai12    = (const int*)  d_in[2];
    const float* dist    = (const float*)d_in[3];
    const float* tq      = (const float*)d_in[4];
    const float* Wm0     = (const float*)d_in[5];
    const float* bm0     = (const float*)d_in[6];
    const float* Wn0     = (const float*)d_in[7];
    const float* bn0     = (const float*)d_in[8];
    const float* Wm1     = (const float*)d_in[9];
    const float* bm1     = (const float*)d_in[10];
    const float* Wn1     = (const float*)d_in[11];
    const float* bn1     = (const float*)d_in[12];
    const float* Wf      = (const float*)d_in[13];
    const float* bf      = (const float*)d_in[14];
    const float* factor  = (const float*)d_in[15];
    const float* prefac  = (const float*)d_in[16];
    float* out = (float*)d_out;

    __nv_bfloat16 *f1h, *f1l, *f2h, *f2l;
    __nv_bfloat16 *wm0h, *wm0l, *wn0h, *wn0l, *wm1h, *wm1l, *wn1h, *wn1l;
    float *feat2, *neigh;
    cudaGetSymbolAddress((void**)&f1h,  g_f1h);
    cudaGetSymbolAddress((void**)&f1l,  g_f1l);
    cudaGetSymbolAddress((void**)&f2h,  g_f2h);
    cudaGetSymbolAddress((void**)&f2l,  g_f2l);
    cudaGetSymbolAddress((void**)&wm0h, g_wm0h);
    cudaGetSymbolAddress((void**)&wm0l, g_wm0l);
    cudaGetSymbolAddress((void**)&wn0h, g_wn0h);
    cudaGetSymbolAddress((void**)&wn0l, g_wn0l);
    cudaGetSymbolAddress((void**)&wm1h, g_wm1h);
    cudaGetSymbolAddress((void**)&wm1l, g_wm1l);
    cudaGetSymbolAddress((void**)&wn1h, g_wn1h);
    cudaGetSymbolAddress((void**)&wn1l, g_wn1l);
    cudaGetSymbolAddress((void**)&feat2, g_feat2);
    cudaGetSymbolAddress((void**)&neigh, g_neigh);

    cudaFuncSetAttribute(tgemm128_kernel, cudaFuncAttributeMaxDynamicSharedMemorySize, 2*STAGE);
    cudaFuncSetAttribute(tgemm256_kernel, cudaFuncAttributeMaxDynamicSharedMemorySize, 3*STG3);

    // side streams + events (created once; never destroyed -> capture-safe)
    static cudaStream_t s1 = 0, s2 = 0;
    static cudaEvent_t evStart=0, evPerm=0, evW0m=0, evWn0=0, evW1m=0, evWrest=0, evCsr=0;
    if (!s1){
        cudaStreamCreateWithFlags(&s1, cudaStreamNonBlocking);
        cudaStreamCreateWithFlags(&s2, cudaStreamNonBlocking);
        cudaEventCreateWithFlags(&evStart, cudaEventDisableTiming);
        cudaEventCreateWithFlags(&evPerm,  cudaEventDisableTiming);
        cudaEventCreateWithFlags(&evW0m,   cudaEventDisableTiming);
        cudaEventCreateWithFlags(&evWn0,   cudaEventDisableTiming);
        cudaEventCreateWithFlags(&evW1m,   cudaEventDisableTiming);
        cudaEventCreateWithFlags(&evWrest, cudaEventDisableTiming);
        cudaEventCreateWithFlags(&evCsr,   cudaEventDisableTiming);
    }

    // fork s2: weight prep in consumption order
    cudaEventRecord(evStart, 0);
    cudaStreamWaitEvent(s2, evStart, 0);
    wprep_kernel<<<(NSP*MO*AEVP)/256, 256, 0, s2>>>(Wm0, wm0h, wm0l, AEV, MO, AEVP);
    cudaEventRecord(evW0m, s2);
    wprep_kernel<<<(NSP*NOUT*MO)/256, 256, 0, s2>>>(Wn0, wn0h, wn0l, MO, NOUT, MO);
    cudaEventRecord(evWn0, s2);
    wprep_kernel<<<(NSP*MO*FIN)/256, 256, 0, s2>>>(Wm1, wm1h, wm1l, FIN, MO, FIN);
    cudaEventRecord(evW1m, s2);
    wprep_kernel<<<(NSP*NOUT*MO)/256, 256, 0, s2>>>(Wn1, wn1h, wn1l, MO, NOUT, MO);
    cudaEventRecord(evWrest, s2);

    // main: permutation; fork s1: CSR build
    perm_kernel<<<1, 1024>>>(species);
    cudaEventRecord(evPerm, 0);
    cudaStreamWaitEvent(s1, evPerm, 0);
    edge_kernel<<<NP/256, 256, 0, s1>>>(ai12, dist, factor, prefac);
    scan_kernel<<<1, 1024, 0, s1>>>();
    fill_kernel<<<NP/256, 256, 0, s1>>>();
    cudaEventRecord(evCsr, s1);

    // pass 0
    cudaStreamWaitEvent(0, evW0m, 0);
    tgemm256_kernel<<<NT, 512, 3*STG3>>>(aev,
        (__nv_bfloat16*)0, (__nv_bfloat16*)0, 0, wm0h, wm0l, bm0,
        AEVP, (float*)0, 0, f1h, f1l, FIN);
    cudaStreamWaitEvent(0, evWn0, 0);
    tgemm128_kernel<<<NT, 256, 2*STAGE>>>(f1h, f1l, FIN, wn0h, wn0l, bn0,
        MO, neigh, NOUT, 1);
    cudaStreamWaitEvent(0, evCsr, 0);
    mpgather_kernel<<<NPAD, 128>>>(0);

    // pass 1
    cudaStreamWaitEvent(0, evW1m, 0);
    tgemm256_kernel<<<NT, 512, 3*STG3>>>((const float*)0,
        f1h, f1l, FIN, wm1h, wm1l, bm1,
        FIN, feat2, FIN, f2h, f2l, MO);
    cudaStreamWaitEvent(0, evWrest, 0);
    tgemm128_kernel<<<NT, 256, 2*STAGE>>>(f2h, f2l, MO, wn1h, wn1l, bn1,
        MO, neigh, NOUT, 1);
    mpgather_kernel<<<NPAD, 128>>>(1);

    // outputs
    final_kernel <<<NATOMS*32/256, 256>>>(species, Wf, bf, out);
    charge_kernel<<<NB, NA>>>(tq, out);
}

// round 11
// speedup vs baseline: 2.8749x; 1.2067x over previous
#include <cuda_runtime.h>
#include <cuda_fp16.h>
#include <math.h>
#include <stdint.h>

#define NB     256
#define NA     128
#define NATOMS 32768
#define AEV    1008
#define AEVP   1024
#define MO     256
#define NOUT   128
#define FIN    384
#define NP     262144
#define NSP    4
#define NPAD   33280
#define NT     (NPAD/128)

// ---------------- scratch (device globals) ----------------------------------
__device__ __align__(16) __half g_f1h[(size_t)NPAD*FIN];
__device__ __align__(16) __half g_f1l[(size_t)NPAD*FIN];
__device__ __align__(16) __half g_f2h[(size_t)NPAD*MO];
__device__ __align__(16) __half g_f2l[(size_t)NPAD*MO];
__device__ float g_feat2[(size_t)NPAD*FIN];     // fp32: internal1 | merged1
__device__ float g_neigh[(size_t)NPAD*NOUT];
__device__ float g_decay[NP];
__device__ int   g_e0[NP], g_e1[NP];
__device__ int   g_p2n[NATOMS];
__device__ int   g_n2o[NPAD];
__device__ int   g_tilesp[NT];
__device__ float g_pre[NATOMS];
// CSR adjacency (rebuilt every launch)
__device__ int   g_deg[NPAD];
__device__ int   g_roff[NPAD+1];
__device__ int   g_cur[NPAD];
__device__ int   g_nbr[2*NP];
__device__ float g_w[2*NP];
// transposed fp16 weights: [S][Nout][Kpad]
__device__ __align__(16) __half g_wm0h[(size_t)NSP*MO*AEVP];
__device__ __align__(16) __half g_wn0h[(size_t)NSP*NOUT*MO];
__device__ __align__(16) __half g_wm1h[(size_t)NSP*MO*FIN];
__device__ __align__(16) __half g_wn1h[(size_t)NSP*NOUT*MO];

// ---------------- small helpers ---------------------------------------------
__device__ __forceinline__ uint32_t smem_u32(const void* p){
    uint32_t a;
    asm("{ .reg .u64 t; cvta.to.shared.u64 t, %1; cvt.u32.u64 %0, t; }" : "=r"(a) : "l"(p));
    return a;
}
__device__ __forceinline__ void cp16(uint32_t dst, const void* src){
    asm volatile("cp.async.cg.shared.global [%0], [%1], 16;" :: "r"(dst), "l"(src) : "memory");
}
__device__ __forceinline__ void cp_commit(){
    asm volatile("cp.async.commit_group;" ::: "memory");
}
template<int N> __device__ __forceinline__ void cp_wait(){
    asm volatile("cp.async.wait_group %0;" :: "n"(N) : "memory");
}
__device__ __forceinline__ void ldsm4(uint32_t* r, uint32_t addr){
    asm volatile("ldmatrix.sync.aligned.m8n8.x4.shared.b16 {%0,%1,%2,%3}, [%4];"
        : "=r"(r[0]),"=r"(r[1]),"=r"(r[2]),"=r"(r[3]) : "r"(addr));
}
__device__ __forceinline__ void mma16816(float* d, const uint32_t* a, uint32_t b0, uint32_t b1){
    asm volatile("mma.sync.aligned.m16n8k16.row.col.f32.f16.f16.f32 "
        "{%0,%1,%2,%3}, {%4,%5,%6,%7}, {%8,%9}, {%0,%1,%2,%3};"
        : "+f"(d[0]),"+f"(d[1]),"+f"(d[2]),"+f"(d[3])
        : "r"(a[0]),"r"(a[1]),"r"(a[2]),"r"(a[3]), "r"(b0),"r"(b1));
}
__device__ __forceinline__ float gelu_tanh(float x){
    float t = tanhf(0.7978845608028654f * (x + 0.044715f * x * x * x));
    return 0.5f * x * (1.0f + t);
}
__device__ __forceinline__ void split_hl(float x, __half& h, __half& l){
    h = __float2half_rn(x);
    l = __float2half_rn(x - __half2float(h));
}

// ---------------- permutation: deterministic species grouping ---------------
__global__ void __launch_bounds__(1024) perm_kernel(const int* __restrict__ species){
    __shared__ int sc[NSP][1024];
    __shared__ int stot[NSP];
    __shared__ int sbase[NSP+1];
    int t = threadIdx.x;
    for (int r = t; r < NPAD; r += 1024){ g_n2o[r] = -1; g_deg[r] = 0; }
    int c0=0,c1=0,c2=0,c3=0;
    int b0 = t*32;
    #pragma unroll
    for (int j=0;j<32;j++){
        int s = species[b0+j];
        c0 += (s==0); c1 += (s==1); c2 += (s==2); c3 += (s==3);
    }
    sc[0][t]=c0; sc[1][t]=c1; sc[2][t]=c2; sc[3][t]=c3;
    __syncthreads();
    if (t < NSP){
        int run = 0;
        for (int i=0;i<1024;i++){ int v=sc[t][i]; sc[t][i]=run; run+=v; }
        stot[t]=run;
    }
    __syncthreads();
    if (t==0){
        int b=0;
        for (int s=0;s<NSP;s++){ sbase[s]=b; b += ((stot[s]+127)>>7)<<7; }
        sbase[NSP]=b;
        for (int tt=0; tt<NT; tt++){
            int rs = tt*128; int sp=0;
            for (int s=1;s<NSP;s++) if (rs >= sbase[s]) sp=s;
            g_tilesp[tt]=sp;
        }
    }
    __syncthreads();
    int run2[NSP] = {0,0,0,0};
    for (int j=0;j<32;j++){
        int i = b0+j; int s = species[i];
        int pos = sbase[s] + sc[s][t] + run2[s];
        run2[s]++;
        g_p2n[i]=pos; g_n2o[pos]=i;
    }
}

// ---------------- weight transpose: W[S][K][N] -> fp16 T[S][N][Kpad] --------
__global__ void __launch_bounds__(256) wprep_kernel(const float* __restrict__ W,
                                                    __half* __restrict__ Th,
                                                    int K, int Nout, int Kpad){
    long idx = (long)blockIdx.x*256 + threadIdx.x;
    long total = (long)NSP*Nout*Kpad;
    if (idx >= total) return;
    int k = idx % Kpad;
    int n = (idx / Kpad) % Nout;
    int s = idx / ((long)Kpad*Nout);
    float v = (k < K) ? W[((size_t)s*K + k)*Nout + n] : 0.f;
    Th[idx] = __float2half_rn(v);
}

// ---------------- edges: decay + endpoint remap + degree count ---------------
__global__ void edge_kernel(const int* __restrict__ ai,
                            const float* __restrict__ dist,
                            const float* __restrict__ fa,
                            const float* __restrict__ pf){
    int p = blockIdx.x*256 + threadIdx.x;
    float d = dist[p];
    float factor = fa[0], pre = pf[0];
    float x = fminf(fmaxf(d*(1.0f/5.2f), 0.0f), 1.0f - 1e-6f);
    float f = (d < 5.2f) ? expf(1.0f - 1.0f/(1.0f - x*x)) : 0.0f;
    g_decay[p] = pre*pre*expf(-factor*factor*d)*f;
    int e0 = g_p2n[ai[p]];
    int e1 = g_p2n[ai[NP + p]];
    g_e0[p] = e0; g_e1[p] = e1;
    atomicAdd(&g_deg[e0], 1);
    atomicAdd(&g_deg[e1], 1);
}

// ---------------- exclusive scan of degrees -> row offsets ------------------
#define SCAN_CH 33
__global__ void __launch_bounds__(1024) scan_kernel(){
    __shared__ int wsum[32];
    int t = threadIdx.x;
    int base = t*SCAN_CH;
    int s = 0;
    for (int j=0;j<SCAN_CH;j++){
        int idx = base+j;
        if (idx < NPAD) s += g_deg[idx];
    }
    int lane = t&31, w = t>>5;
    int v = s;
    #pragma unroll
    for (int o=1;o<32;o<<=1){ int u = __shfl_up_sync(~0u, v, o); if (lane>=o) v += u; }
    if (lane==31) wsum[w] = v;
    __syncthreads();
    if (w==0){
        int x = wsum[lane];
        #pragma unroll
        for (int o=1;o<32;o<<=1){ int u = __shfl_up_sync(~0u, x, o); if (lane>=o) x += u; }
        wsum[lane] = x;
    }
    __syncthreads();
    int excl = v - s + (w>0 ? wsum[w-1] : 0);
    int run = excl;
    for (int j=0;j<SCAN_CH;j++){
        int idx = base+j;
        if (idx < NPAD){
            g_roff[idx] = run;
            g_cur[idx]  = run;
            run += g_deg[idx];
        }
    }
    if (t == 1023) g_roff[NPAD] = run;
}

// ---------------- fill CSR edge lists -----------------------------------------
__global__ void fill_kernel(){
    int p = blockIdx.x*256 + threadIdx.x;
    int e0 = g_e0[p], e1 = g_e1[p];
    float d = g_decay[p];
    int i0 = atomicAdd(&g_cur[e0], 1);
    g_nbr[i0] = e1; g_w[i0] = d;
    int i1 = atomicAdd(&g_cur[e1], 1);
    g_nbr[i1] = e0; g_w[i1] = d;
}

#define PITCH 80
#define ATS   (128*PITCH)      // 10240 B: one 128-row tile (32 fp16/row)

// ============ tgemm128: N=128, 2-phase fp16, 2-stage, 2 CTA/SM ==============
#define STG128 (3*ATS)         // ah | al | wh = 30720
__global__ void __launch_bounds__(256, 2) tgemm128_kernel(
    const __half* __restrict__ Ah, const __half* __restrict__ Al, int lda,
    const __half* __restrict__ Wh,
    const float* __restrict__ bias,
    int K, float* C32, int ldc32, int act)
{
    extern __shared__ __align__(128) uint8_t sm[];
    uint32_t smBase = smem_u32(sm);
    const int Nout = 128;

    int tid = threadIdx.x, lane = tid & 31, wid = tid >> 5;
    int wm = wid & 3, wn = wid >> 2;
    int by = blockIdx.x;
    int sp = g_tilesp[by];

    const __half* AhR = Ah + (size_t)by*128*lda;
    const __half* AlR = Al + (size_t)by*128*lda;
    const __half* WhS = Wh + (size_t)sp*Nout*K;

    float d[2][8][4];
    #pragma unroll
    for (int i=0;i<2;i++)
        #pragma unroll
        for (int j=0;j<8;j++)
            #pragma unroll
            for (int q=0;q<4;q++) d[i][j][q]=0.f;

    int nkc = K >> 5;

    uint32_t aoff = (uint32_t)((wm*32 + (lane & 15))*PITCH + ((lane >> 4) & 1)*16);
    uint32_t boff = (uint32_t)((wn*64 + (lane & 7) + ((lane >> 4) & 1)*8)*PITCH + ((lane >> 3) & 1)*16);

    auto load_chunk = [&](int kc, int buf){
        uint32_t base = smBase + (uint32_t)buf*STG128;
        #pragma unroll
        for (int t=0;t<6;t++){
            int it = tid + t*256;     // 1536 items: ah 512 | al 512 | wh 512
            int tile = it >> 9;
            int j = it & 511;
            int row = j >> 2, seg = j & 3;
            const __half* src;
            if (tile == 0)      src = AhR + (size_t)row*lda;
            else if (tile == 1) src = AlR + (size_t)row*lda;
            else                src = WhS + (size_t)row*K;
            src += kc*32 + seg*8;
            cp16(base + (uint32_t)tile*ATS + row*PITCH + seg*16, src);
        }
        cp_commit();
    };

    auto do_mma = [&](int buf){
        uint32_t base = smBase + (uint32_t)buf*STG128;
        #pragma unroll
        for (int ks=0; ks<2; ks++){
            uint32_t ah_[2][4], al_[2][4], b_[4][4];
            uint32_t aT = base + aoff + ks*32;
            uint32_t bT = base + 2*ATS + boff + ks*32;
            #pragma unroll
            for (int mi=0; mi<2; mi++) ldsm4(ah_[mi], aT + mi*16*PITCH);
            #pragma unroll
            for (int np_=0; np_<4; np_++) ldsm4(b_[np_], bT + np_*16*PITCH);
            #pragma unroll
            for (int mi=0; mi<2; mi++)
                #pragma unroll
                for (int nj=0; nj<8; nj++)
                    mma16816(d[mi][nj], ah_[mi], b_[nj>>1][(nj&1)*2], b_[nj>>1][(nj&1)*2+1]);
            #pragma unroll
            for (int mi=0; mi<2; mi++) ldsm4(al_[mi], aT + ATS + mi*16*PITCH);
            #pragma unroll
            for (int mi=0; mi<2; mi++)
                #pragma unroll
                for (int nj=0; nj<8; nj++)
                    mma16816(d[mi][nj], al_[mi], b_[nj>>1][(nj&1)*2], b_[nj>>1][(nj&1)*2+1]);
        }
    };

    load_chunk(0, 0);
    for (int c=0; c<nkc; c++){
        int buf = c & 1;
        if (c+1 < nkc){ load_chunk(c+1, buf^1); cp_wait<1>(); }
        else cp_wait<0>();
        __syncthreads();
        do_mma(buf);
        __syncthreads();
    }

    const float* bp = bias + sp*Nout + wn*64;
    int rowLo = wm*32 + (lane >> 2);
    int colCta = wn*64;
    #pragma unroll
    for (int mi=0; mi<2; mi++){
        #pragma unroll
        for (int nj=0; nj<8; nj++){
            int c0 = nj*8 + 2*(lane & 3);
            float b0 = bp[c0], b1 = bp[c0+1];
            #pragma unroll
            for (int h=0; h<2; h++){
                size_t gr = (size_t)by*128 + rowLo + mi*16 + h*8;
                float x0 = d[mi][nj][2*h]   + b0;
                float x1 = d[mi][nj][2*h+1] + b1;
                if (act){ x0 = gelu_tanh(x0); x1 = gelu_tanh(x1); }
                *(float2*)(C32 + gr*ldc32 + colCta + c0) = make_float2(x0, x1);
            }
        }
    }
}

// ============ tgemm256: N=256 mega-CTA, 2-phase fp16, 3-stage ===============
#define WTS   20480            // one W tile (256 x 80B)
#define STG3  (2*ATS + WTS)    // 40960: ah | al | wh
__global__ void __launch_bounds__(512, 1) tgemm256_kernel(
    const float* __restrict__ A32,
    const __half* __restrict__ Ah, const __half* __restrict__ Al, int lda,
    const __half* __restrict__ Wh,
    const float* __restrict__ bias,
    int K,
    float* C32, int ldc32,
    __half* Ch, __half* Cl, int ldcb)
{
    extern __shared__ __align__(128) uint8_t sm[];   // 3*STG3 dynamic
    uint32_t smBase = smem_u32(sm);
    const int Nout = 256;

    int tid = threadIdx.x, lane = tid & 31, wid = tid >> 5;
    int wm = wid & 3, wn = wid >> 2;     // 4 x 4 warp grid: 128 x 256
    int by = blockIdx.x;
    int sp = g_tilesp[by];

    const __half* WhS = Wh + (size_t)sp*Nout*K;

    float d[2][8][4];
    #pragma unroll
    for (int i=0;i<2;i++)
        #pragma unroll
        for (int j=0;j<8;j++)
            #pragma unroll
            for (int q=0;q<4;q++) d[i][j][q]=0.f;

    int nkc = K >> 5;

    uint32_t aoff = (uint32_t)((wm*32 + (lane & 15))*PITCH + ((lane >> 4) & 1)*16);
    uint32_t boff = (uint32_t)((wn*64 + (lane & 7) + ((lane >> 4) & 1)*8)*PITCH + ((lane >> 3) & 1)*16);

    auto do_mma = [&](int st){
        uint32_t base = smBase + (uint32_t)st*STG3;
        #pragma unroll
        for (int ks=0; ks<2; ks++){
            uint32_t ah_[2][4], al_[2][4], b_[4][4];
            uint32_t aT = base + aoff + ks*32;
            uint32_t bT = base + 2*ATS + boff + ks*32;
            #pragma unroll
            for (int mi=0; mi<2; mi++) ldsm4(ah_[mi], aT + mi*16*PITCH);
            #pragma unroll
            for (int np_=0; np_<4; np_++) ldsm4(b_[np_], bT + np_*16*PITCH);
            #pragma unroll
            for (int mi=0; mi<2; mi++)
                #pragma unroll
                for (int nj=0; nj<8; nj++)
                    mma16816(d[mi][nj], ah_[mi], b_[nj>>1][(nj&1)*2], b_[nj>>1][(nj&1)*2+1]);
            #pragma unroll
            for (int mi=0; mi<2; mi++) ldsm4(al_[mi], aT + ATS + mi*16*PITCH);
            #pragma unroll
            for (int mi=0; mi<2; mi++)
                #pragma unroll
                for (int nj=0; nj<8; nj++)
                    mma16816(d[mi][nj], al_[mi], b_[nj>>1][(nj&1)*2], b_[nj>>1][(nj&1)*2+1]);
        }
    };

    if (A32 == nullptr){
        // ---- fp16 A path: A+W via cp.async, 4 x 16B per thread ----
        const __half* AhR = Ah + (size_t)by*128*lda;
        const __half* AlR = Al + (size_t)by*128*lda;
        auto load_chunk = [&](int kc, int st){
            uint32_t base = smBase + (uint32_t)st*STG3;
            #pragma unroll
            for (int t=0;t<4;t++){
                int it = tid + t*512;    // 2048 items: ah 512 | al 512 | wh 1024
                const __half* src; uint32_t dst;
                if (it < 1024){
                    int tile = it >> 9;
                    int j = it & 511;
                    int row = j >> 2, seg = j & 3;
                    src = (tile ? AlR : AhR) + (size_t)row*lda + kc*32 + seg*8;
                    dst = base + (uint32_t)tile*ATS + row*PITCH + seg*16;
                } else {
                    int j = it - 1024;
                    int row = j >> 2, seg = j & 3;
                    src = WhS + (size_t)row*K + kc*32 + seg*8;
                    dst = base + 2*ATS + row*PITCH + seg*16;
                }
                cp16(dst, src);
            }
            cp_commit();
        };
        load_chunk(0, 0);
        if (nkc > 1) load_chunk(1, 1);
        for (int c=0; c<nkc; c++){
            int st = c % 3;
            if (c+2 < nkc) load_chunk(c+2, (c+2)%3);
            if (c+2 < nkc) cp_wait<2>();
            else if (c+1 < nkc) cp_wait<1>();
            else cp_wait<0>();
            __syncthreads();
            do_mma(st);
            __syncthreads();
        }
    } else {
        // ---- fp32 A path (pass-0): LDG.128 + in-register hi/lo split ----
        const float* aptr[2];
        bool avalid[2];
        int aRow[2], aSeg[2];
        #pragma unroll
        for (int t=0;t<2;t++){
            int j = tid + t*512;
            aRow[t] = j >> 3; aSeg[t] = j & 7;
            int src = g_n2o[by*128 + aRow[t]];
            avalid[t] = (src >= 0);
            aptr[t] = A32 + (size_t)(src < 0 ? 0 : src)*AEV;
        }
        auto loadW = [&](int kc, int st){
            uint32_t base = smBase + (uint32_t)st*STG3 + 2*ATS;
            #pragma unroll
            for (int t=0;t<2;t++){
                int j = tid + t*512;     // 1024 items
                int row = j >> 2, seg = j & 3;
                const __half* src = WhS + (size_t)row*K + kc*32 + seg*8;
                cp16(base + row*PITCH + seg*16, src);
            }
            cp_commit();
        };
        float4 R[2];
        auto ldgA = [&](int kc){
            #pragma unroll
            for (int t=0;t<2;t++){
                int col = kc*32 + aSeg[t]*4;
                if (avalid[t] && col < AEV) R[t] = *(const float4*)(aptr[t] + col);
                else R[t] = make_float4(0.f,0.f,0.f,0.f);
            }
        };
        auto stsA = [&](int st){
            uint32_t base = (uint32_t)st*STG3;
            #pragma unroll
            for (int t=0;t<2;t++){
                float a[4] = {R[t].x, R[t].y, R[t].z, R[t].w};
                __half h[4], l[4];
                #pragma unroll
                for (int q=0;q<4;q++) split_hl(a[q], h[q], l[q]);
                uint32_t off = base + (uint32_t)(aRow[t]*PITCH + aSeg[t]*8);
                *(uint64_t*)(sm + off)       = *(const uint64_t*)h;
                *(uint64_t*)(sm + off + ATS) = *(const uint64_t*)l;
            }
        };
        loadW(0, 0);
        if (nkc > 1) loadW(1, 1);
        ldgA(0); stsA(0);
        if (nkc > 1) ldgA(1);
        for (int c=0; c<nkc; c++){
            int st = c % 3;
            if (c+2 < nkc) loadW(c+2, (c+2)%3);
            if (c+1 < nkc) stsA((c+1)%3);
            if (c+2 < nkc) ldgA(c+2);
            if (c+2 < nkc) cp_wait<2>();
            else if (c+1 < nkc) cp_wait<1>();
            else cp_wait<0>();
            __syncthreads();
            do_mma(st);
            __syncthreads();
        }
    }

    const float* bp = bias + sp*Nout + wn*64;
    int rowLo = wm*32 + (lane >> 2);
    int colCta = wn*64;
    #pragma unroll
    for (int mi=0; mi<2; mi++){
        #pragma unroll
        for (int nj=0; nj<8; nj++){
            int c0 = nj*8 + 2*(lane & 3);
            float b0 = bp[c0], b1 = bp[c0+1];
            #pragma unroll
            for (int h=0; h<2; h++){
                size_t gr = (size_t)by*128 + rowLo + mi*16 + h*8;
                float x0 = gelu_tanh(d[mi][nj][2*h]   + b0);
                float x1 = gelu_tanh(d[mi][nj][2*h+1] + b1);
                int col = colCta + c0;
                if (C32){
                    *(float2*)(C32 + gr*ldc32 + col) = make_float2(x0, x1);
                }
                if (Ch){
                    __half h0,l0,h1,l1;
                    split_hl(x0,h0,l0); split_hl(x1,h1,l1);
                    uint32_t hh = (uint32_t)__half_as_ushort(h0) |
                                  ((uint32_t)__half_as_ushort(h1) << 16);
                    uint32_t ll = (uint32_t)__half_as_ushort(l0) |
                                  ((uint32_t)__half_as_ushort(l1) << 16);
                    *(uint32_t*)(Ch + gr*ldcb + col) = hh;
                    *(uint32_t*)(Cl + gr*ldcb + col) = ll;
                }
            }
        }
    }
}

// ---------------- CSR gather: merged[r][t] = sum_nb neigh[nb][t]*w ----------
__global__ void __launch_bounds__(128) mpgather_kernel(int mode){
    int r = blockIdx.x, t = threadIdx.x;
    int s = g_roff[r], e = g_roff[r+1];
    float acc = 0.f;
    int j = s;
    for (; j+1 < e; j += 2){
        int nb0 = g_nbr[j], nb1 = g_nbr[j+1];
        float w0 = g_w[j],  w1 = g_w[j+1];
        float x0 = g_neigh[(size_t)nb0*NOUT + t];
        float x1 = g_neigh[(size_t)nb1*NOUT + t];
        acc = fmaf(x0, w0, acc);
        acc = fmaf(x1, w1, acc);
    }
    if (j < e)
        acc = fmaf(g_neigh[(size_t)g_nbr[j]*NOUT + t], g_w[j], acc);
    if (mode == 0){
        __half h, l; split_hl(acc, h, l);
        g_f1h[(size_t)r*FIN + 256 + t] = h;
        g_f1l[(size_t)r*FIN + 256 + t] = l;
    } else {
        g_feat2[(size_t)r*FIN + 256 + t] = acc;
    }
}

// ---------------- final routed linear (FIN->1) + outputs --------------------
__global__ void __launch_bounds__(256) final_kernel(const int* __restrict__ species,
                                                    const float* __restrict__ Wf,
                                                    const float* __restrict__ bf,
                                                    float* __restrict__ out){
    int gt = blockIdx.x*256 + threadIdx.x;
    int i = gt >> 5, lane = gt & 31;
    if (i >= NATOMS) return;
    int s = species[i];
    int r = g_p2n[i];
    const float* f = g_feat2 + (size_t)r*FIN;
    const float* w = Wf + s*FIN;
    float sum = 0.f;
    #pragma unroll
    for (int j=0;j<12;j++){
        int k = lane + 32*j;
        sum = fmaf(f[k], w[k], sum);
    }
    #pragma unroll
    for (int o=16;o;o>>=1) sum += __shfl_xor_sync(0xffffffffu, sum, o);
    if (lane == 0){
        float pre = sum + bf[s];
        g_pre[i] = pre;
        out[2*NATOMS + i] = pre;
        out[i] = (float)s;
    }
}

// ---------------- per-molecule charge redistribution -------------------------
__global__ void charge_kernel(const float* __restrict__ tq, float* __restrict__ out){
    __shared__ float ss[4];
    int b = blockIdx.x, a = threadIdx.x;
    float p = g_pre[b*NA + a];
    float v = p;
    #pragma unroll
    for (int o=16;o;o>>=1) v += __shfl_xor_sync(0xffffffffu, v, o);
    int w = a>>5, lane = a&31;
    if (lane == 0) ss[w] = v;
    __syncthreads();
    float sum = ss[0]+ss[1]+ss[2]+ss[3];
    out[NATOMS + b*NA + a] = p + (tq[b] - sum)*(1.0f/128.0f);
}

// ---------------- launch -----------------------------------------------------
extern "C" void kernel_launch(void* const* d_in, const int* in_sizes, int n_in,
                              void* d_out, int out_size){
    const int*   species = (const int*)  d_in[0];
    const float* aev     = (const float*)d_in[1];
    const int*   ai12    = (const int*)  d_in[2];
    const float* dist    = (const float*)d_in[3];
    const float* tq      = (const float*)d_in[4];
    const float* Wm0     = (const float*)d_in[5];
    const float* bm0     = (const float*)d_in[6];
    const float* Wn0     = (const float*)d_in[7];
    const float* bn0     = (const float*)d_in[8];
    const float* Wm1     = (const float*)d_in[9];
    const float* bm1     = (const float*)d_in[10];
    const float* Wn1     = (const float*)d_in[11];
    const float* bn1     = (const float*)d_in[12];
    const float* Wf      = (const float*)d_in[13];
    const float* bf      = (const float*)d_in[14];
    const float* factor  = (const float*)d_in[15];
    const float* prefac  = (const float*)d_in[16];
    float* out = (float*)d_out;

    __half *f1h, *f1l, *f2h, *f2l, *wm0h, *wn0h, *wm1h, *wn1h;
    float *feat2, *neigh;
    cudaGetSymbolAddress((void**)&f1h,  g_f1h);
    cudaGetSymbolAddress((void**)&f1l,  g_f1l);
    cudaGetSymbolAddress((void**)&f2h,  g_f2h);
    cudaGetSymbolAddress((void**)&f2l,  g_f2l);
    cudaGetSymbolAddress((void**)&wm0h, g_wm0h);
    cudaGetSymbolAddress((void**)&wn0h, g_wn0h);
    cudaGetSymbolAddress((void**)&wm1h, g_wm1h);
    cudaGetSymbolAddress((void**)&wn1h, g_wn1h);
    cudaGetSymbolAddress((void**)&feat2, g_feat2);
    cudaGetSymbolAddress((void**)&neigh, g_neigh);

    cudaFuncSetAttribute(tgemm128_kernel, cudaFuncAttributeMaxDynamicSharedMemorySize, 2*STG128);
    cudaFuncSetAttribute(tgemm256_kernel, cudaFuncAttributeMaxDynamicSharedMemorySize, 3*STG3);

    // side streams + events (created once; never destroyed -> capture-safe)
    static cudaStream_t s1 = 0, s2 = 0;
    static cudaEvent_t evStart=0, evPerm=0, evW0m=0, evWn0=0, evW1m=0, evWrest=0, evCsr=0;
    if (!s1){
        cudaStreamCreateWithFlags(&s1, cudaStreamNonBlocking);
        cudaStreamCreateWithFlags(&s2, cudaStreamNonBlocking);
        cudaEventCreateWithFlags(&evStart, cudaEventDisableTiming);
        cudaEventCreateWithFlags(&evPerm,  cudaEventDisableTiming);
        cudaEventCreateWithFlags(&evW0m,   cudaEventDisableTiming);
        cudaEventCreateWithFlags(&evWn0,   cudaEventDisableTiming);
        cudaEventCreateWithFlags(&evW1m,   cudaEventDisableTiming);
        cudaEventCreateWithFlags(&evWrest, cudaEventDisableTiming);
        cudaEventCreateWithFlags(&evCsr,   cudaEventDisableTiming);
    }

    // fork s2: weight prep in consumption order
    cudaEventRecord(evStart, 0);
    cudaStreamWaitEvent(s2, evStart, 0);
    wprep_kernel<<<(NSP*MO*AEVP)/256, 256, 0, s2>>>(Wm0, wm0h, AEV, MO, AEVP);
    cudaEventRecord(evW0m, s2);
    wprep_kernel<<<(NSP*NOUT*MO)/256, 256, 0, s2>>>(Wn0, wn0h, MO, NOUT, MO);
    cudaEventRecord(evWn0, s2);
    wprep_kernel<<<(NSP*MO*FIN)/256, 256, 0, s2>>>(Wm1, wm1h, FIN, MO, FIN);
    cudaEventRecord(evW1m, s2);
    wprep_kernel<<<(NSP*NOUT*MO)/256, 256, 0, s2>>>(Wn1, wn1h, MO, NOUT, MO);
    cudaEventRecord(evWrest, s2);

    // main: permutation; fork s1: CSR build
    perm_kernel<<<1, 1024>>>(species);
    cudaEventRecord(evPerm, 0);
    cudaStreamWaitEvent(s1, evPerm, 0);
    edge_kernel<<<NP/256, 256, 0, s1>>>(ai12, dist, factor, prefac);
    scan_kernel<<<1, 1024, 0, s1>>>();
    fill_kernel<<<NP/256, 256, 0, s1>>>();
    cudaEventRecord(evCsr, s1);

    // pass 0
    cudaStreamWaitEvent(0, evW0m, 0);
    tgemm256_kernel<<<NT, 512, 3*STG3>>>(aev,
        (__half*)0, (__half*)0, 0, wm0h, bm0,
        AEVP, (float*)0, 0, f1h, f1l, FIN);
    cudaStreamWaitEvent(0, evWn0, 0);
    tgemm128_kernel<<<NT, 256, 2*STG128>>>(f1h, f1l, FIN, wn0h, bn0,
        MO, neigh, NOUT, 1);
    cudaStreamWaitEvent(0, evCsr, 0);
    mpgather_kernel<<<NPAD, 128>>>(0);

    // pass 1
    cudaStreamWaitEvent(0, evW1m, 0);
    tgemm256_kernel<<<NT, 512, 3*STG3>>>((const float*)0,
        f1h, f1l, FIN, wm1h, bm1,
        FIN, feat2, FIN, f2h, f2l, MO);
    cudaStreamWaitEvent(0, evWrest, 0);
    tgemm128_kernel<<<NT, 256, 2*STG128>>>(f2h, f2l, MO, wn1h, bn1,
        MO, neigh, NOUT, 1);
    mpgather_kernel<<<NPAD, 128>>>(1);

    // outputs
    final_kernel <<<NATOMS*32/256, 256>>>(species, Wf, bf, out);
    charge_kernel<<<NB, NA>>>(tq, out);
}

// round 12
// speedup vs baseline: 3.5597x; 1.2382x over previous
#include <cuda_runtime.h>
#include <cuda_fp16.h>
#include <math.h>
#include <stdint.h>

#define NB     256
#define NA     128
#define NATOMS 32768
#define AEV    1008
#define AEVP   1024
#define MO     256
#define NOUT   128
#define FIN    384
#define NP     262144
#define NSP    4
#define NPAD   33280
#define NT     (NPAD/128)

// ---------------- scratch (device globals) ----------------------------------
__device__ __align__(16) __half g_f1h[(size_t)NPAD*FIN];
__device__ __align__(16) __half g_f2h[(size_t)NPAD*MO];
__device__ float g_feat2[(size_t)NPAD*FIN];     // fp32: internal1 | merged1
__device__ float g_neigh[(size_t)NPAD*NOUT];
__device__ float g_decay[NP];
__device__ int   g_e0[NP], g_e1[NP];
__device__ int   g_p2n[NATOMS];
__device__ int   g_n2o[NPAD];
__device__ int   g_tilesp[NT];
__device__ float g_pre[NATOMS];
// CSR adjacency (rebuilt every launch)
__device__ int   g_deg[NPAD];
__device__ int   g_roff[NPAD+1];
__device__ int   g_cur[NPAD];
__device__ int   g_nbr[2*NP];
__device__ float g_w[2*NP];
// transposed fp16 weights: [S][Nout][Kpad]
__device__ __align__(16) __half g_wm0h[(size_t)NSP*MO*AEVP];
__device__ __align__(16) __half g_wn0h[(size_t)NSP*NOUT*MO];
__device__ __align__(16) __half g_wm1h[(size_t)NSP*MO*FIN];
__device__ __align__(16) __half g_wn1h[(size_t)NSP*NOUT*MO];

// ---------------- small helpers ---------------------------------------------
__device__ __forceinline__ uint32_t smem_u32(const void* p){
    uint32_t a;
    asm("{ .reg .u64 t; cvta.to.shared.u64 t, %1; cvt.u32.u64 %0, t; }" : "=r"(a) : "l"(p));
    return a;
}
__device__ __forceinline__ void cp16(uint32_t dst, const void* src){
    asm volatile("cp.async.cg.shared.global [%0], [%1], 16;" :: "r"(dst), "l"(src) : "memory");
}
__device__ __forceinline__ void cp_commit(){
    asm volatile("cp.async.commit_group;" ::: "memory");
}
template<int N> __device__ __forceinline__ void cp_wait(){
    asm volatile("cp.async.wait_group %0;" :: "n"(N) : "memory");
}
__device__ __forceinline__ void ldsm4(uint32_t* r, uint32_t addr){
    asm volatile("ldmatrix.sync.aligned.m8n8.x4.shared.b16 {%0,%1,%2,%3}, [%4];"
        : "=r"(r[0]),"=r"(r[1]),"=r"(r[2]),"=r"(r[3]) : "r"(addr));
}
__device__ __forceinline__ void mma16816(float* d, const uint32_t* a, uint32_t b0, uint32_t b1){
    asm volatile("mma.sync.aligned.m16n8k16.row.col.f32.f16.f16.f32 "
        "{%0,%1,%2,%3}, {%4,%5,%6,%7}, {%8,%9}, {%0,%1,%2,%3};"
        : "+f"(d[0]),"+f"(d[1]),"+f"(d[2]),"+f"(d[3])
        : "r"(a[0]),"r"(a[1]),"r"(a[2]),"r"(a[3]), "r"(b0),"r"(b1));
}
__device__ __forceinline__ float gelu_tanh(float x){
    float t = tanhf(0.7978845608028654f * (x + 0.044715f * x * x * x));
    return 0.5f * x * (1.0f + t);
}

// ---------------- permutation: deterministic species grouping ---------------
__global__ void __launch_bounds__(1024) perm_kernel(const int* __restrict__ species){
    __shared__ int sc[NSP][1024];
    __shared__ int stot[NSP];
    __shared__ int sbase[NSP+1];
    int t = threadIdx.x;
    for (int r = t; r < NPAD; r += 1024){ g_n2o[r] = -1; g_deg[r] = 0; }
    int c0=0,c1=0,c2=0,c3=0;
    int b0 = t*32;
    #pragma unroll
    for (int j=0;j<32;j++){
        int s = species[b0+j];
        c0 += (s==0); c1 += (s==1); c2 += (s==2); c3 += (s==3);
    }
    sc[0][t]=c0; sc[1][t]=c1; sc[2][t]=c2; sc[3][t]=c3;
    __syncthreads();
    if (t < NSP){
        int run = 0;
        for (int i=0;i<1024;i++){ int v=sc[t][i]; sc[t][i]=run; run+=v; }
        stot[t]=run;
    }
    __syncthreads();
    if (t==0){
        int b=0;
        for (int s=0;s<NSP;s++){ sbase[s]=b; b += ((stot[s]+127)>>7)<<7; }
        sbase[NSP]=b;
        for (int tt=0; tt<NT; tt++){
            int rs = tt*128; int sp=0;
            for (int s=1;s<NSP;s++) if (rs >= sbase[s]) sp=s;
            g_tilesp[tt]=sp;
        }
    }
    __syncthreads();
    int run2[NSP] = {0,0,0,0};
    for (int j=0;j<32;j++){
        int i = b0+j; int s = species[i];
        int pos = sbase[s] + sc[s][t] + run2[s];
        run2[s]++;
        g_p2n[i]=pos; g_n2o[pos]=i;
    }
}

// ---------------- weight transpose: W[S][K][N] -> fp16 T[S][N][Kpad] --------
__global__ void __launch_bounds__(256) wprep_kernel(const float* __restrict__ W,
                                                    __half* __restrict__ Th,
                                                    int K, int Nout, int Kpad){
    long idx = (long)blockIdx.x*256 + threadIdx.x;
    long total = (long)NSP*Nout*Kpad;
    if (idx >= total) return;
    int k = idx % Kpad;
    int n = (idx / Kpad) % Nout;
    int s = idx / ((long)Kpad*Nout);
    float v = (k < K) ? W[((size_t)s*K + k)*Nout + n] : 0.f;
    Th[idx] = __float2half_rn(v);
}

// ---------------- edges: decay + endpoint remap + degree count ---------------
__global__ void edge_kernel(const int* __restrict__ ai,
                            const float* __restrict__ dist,
                            const float* __restrict__ fa,
                            const float* __restrict__ pf){
    int p = blockIdx.x*256 + threadIdx.x;
    float d = dist[p];
    float factor = fa[0], pre = pf[0];
    float x = fminf(fmaxf(d*(1.0f/5.2f), 0.0f), 1.0f - 1e-6f);
    float f = (d < 5.2f) ? expf(1.0f - 1.0f/(1.0f - x*x)) : 0.0f;
    g_decay[p] = pre*pre*expf(-factor*factor*d)*f;
    int e0 = g_p2n[ai[p]];
    int e1 = g_p2n[ai[NP + p]];
    g_e0[p] = e0; g_e1[p] = e1;
    atomicAdd(&g_deg[e0], 1);
    atomicAdd(&g_deg[e1], 1);
}

// ---------------- exclusive scan of degrees -> row offsets ------------------
#define SCAN_CH 33
__global__ void __launch_bounds__(1024) scan_kernel(){
    __shared__ int wsum[32];
    int t = threadIdx.x;
    int base = t*SCAN_CH;
    int s = 0;
    for (int j=0;j<SCAN_CH;j++){
        int idx = base+j;
        if (idx < NPAD) s += g_deg[idx];
    }
    int lane = t&31, w = t>>5;
    int v = s;
    #pragma unroll
    for (int o=1;o<32;o<<=1){ int u = __shfl_up_sync(~0u, v, o); if (lane>=o) v += u; }
    if (lane==31) wsum[w] = v;
    __syncthreads();
    if (w==0){
        int x = wsum[lane];
        #pragma unroll
        for (int o=1;o<32;o<<=1){ int u = __shfl_up_sync(~0u, x, o); if (lane>=o) x += u; }
        wsum[lane] = x;
    }
    __syncthreads();
    int excl = v - s + (w>0 ? wsum[w-1] : 0);
    int run = excl;
    for (int j=0;j<SCAN_CH;j++){
        int idx = base+j;
        if (idx < NPAD){
            g_roff[idx] = run;
            g_cur[idx]  = run;
            run += g_deg[idx];
        }
    }
    if (t == 1023) g_roff[NPAD] = run;
}

// ---------------- fill CSR edge lists -----------------------------------------
__global__ void fill_kernel(){
    int p = blockIdx.x*256 + threadIdx.x;
    int e0 = g_e0[p], e1 = g_e1[p];
    float d = g_decay[p];
    int i0 = atomicAdd(&g_cur[e0], 1);
    g_nbr[i0] = e1; g_w[i0] = d;
    int i1 = atomicAdd(&g_cur[e1], 1);
    g_nbr[i1] = e0; g_w[i1] = d;
}

#define PITCH 80
#define ATS   (128*PITCH)      // 10240 B: one 128-row tile (32 fp16/row)

// ============ tgemm128: N=128 pure fp16, 2-stage, 2 CTA/SM ==================
#define STG128 (2*ATS)         // ah | wh = 20480
__global__ void __launch_bounds__(256, 2) tgemm128_kernel(
    const __half* __restrict__ Ah, int lda,
    const __half* __restrict__ Wh,
    const float* __restrict__ bias,
    int K, float* C32, int ldc32, int act)
{
    extern __shared__ __align__(128) uint8_t sm[];
    uint32_t smBase = smem_u32(sm);
    const int Nout = 128;

    int tid = threadIdx.x, lane = tid & 31, wid = tid >> 5;
    int wm = wid & 3, wn = wid >> 2;
    int by = blockIdx.x;
    int sp = g_tilesp[by];

    const __half* AhR = Ah + (size_t)by*128*lda;
    const __half* WhS = Wh + (size_t)sp*Nout*K;

    float d[2][8][4];
    #pragma unroll
    for (int i=0;i<2;i++)
        #pragma unroll
        for (int j=0;j<8;j++)
            #pragma unroll
            for (int q=0;q<4;q++) d[i][j][q]=0.f;

    int nkc = K >> 5;

    uint32_t aoff = (uint32_t)((wm*32 + (lane & 15))*PITCH + ((lane >> 4) & 1)*16);
    uint32_t boff = (uint32_t)((wn*64 + (lane & 7) + ((lane >> 4) & 1)*8)*PITCH + ((lane >> 3) & 1)*16);

    auto load_chunk = [&](int kc, int buf){
        uint32_t base = smBase + (uint32_t)buf*STG128;
        #pragma unroll
        for (int t=0;t<4;t++){
            int it = tid + t*256;     // 1024 items: ah 512 | wh 512
            int tile = it >> 9;
            int j = it & 511;
            int row = j >> 2, seg = j & 3;
            const __half* src = (tile ? WhS + (size_t)row*K : AhR + (size_t)row*lda)
                                + kc*32 + seg*8;
            cp16(base + (uint32_t)tile*ATS + row*PITCH + seg*16, src);
        }
        cp_commit();
    };

    auto do_mma = [&](int buf){
        uint32_t base = smBase + (uint32_t)buf*STG128;
        #pragma unroll
        for (int ks=0; ks<2; ks++){
            uint32_t a_[2][4], b_[4][4];
            uint32_t aT = base + aoff + ks*32;
            uint32_t bT = base + ATS + boff + ks*32;
            #pragma unroll
            for (int mi=0; mi<2; mi++) ldsm4(a_[mi], aT + mi*16*PITCH);
            #pragma unroll
            for (int np_=0; np_<4; np_++) ldsm4(b_[np_], bT + np_*16*PITCH);
            #pragma unroll
            for (int mi=0; mi<2; mi++)
                #pragma unroll
                for (int nj=0; nj<8; nj++)
                    mma16816(d[mi][nj], a_[mi], b_[nj>>1][(nj&1)*2], b_[nj>>1][(nj&1)*2+1]);
        }
    };

    load_chunk(0, 0);
    for (int c=0; c<nkc; c++){
        int buf = c & 1;
        if (c+1 < nkc){ load_chunk(c+1, buf^1); cp_wait<1>(); }
        else cp_wait<0>();
        __syncthreads();
        do_mma(buf);
        __syncthreads();
    }

    const float* bp = bias + sp*Nout + wn*64;
    int rowLo = wm*32 + (lane >> 2);
    int colCta = wn*64;
    #pragma unroll
    for (int mi=0; mi<2; mi++){
        #pragma unroll
        for (int nj=0; nj<8; nj++){
            int c0 = nj*8 + 2*(lane & 3);
            float b0 = bp[c0], b1 = bp[c0+1];
            #pragma unroll
            for (int h=0; h<2; h++){
                size_t gr = (size_t)by*128 + rowLo + mi*16 + h*8;
                float x0 = d[mi][nj][2*h]   + b0;
                float x1 = d[mi][nj][2*h+1] + b1;
                if (act){ x0 = gelu_tanh(x0); x1 = gelu_tanh(x1); }
                *(float2*)(C32 + gr*ldc32 + colCta + c0) = make_float2(x0, x1);
            }
        }
    }
}

// ============ tgemm256: N=256 mega-CTA pure fp16, 3-stage ===================
#define WTS   20480            // one W tile (256 x 80B)
#define STG3  (ATS + WTS)      // 30720: ah | wh
__global__ void __launch_bounds__(512, 1) tgemm256_kernel(
    const float* __restrict__ A32,
    const __half* __restrict__ Ah, int lda,
    const __half* __restrict__ Wh,
    const float* __restrict__ bias,
    int K,
    float* C32, int ldc32,
    __half* Ch, int ldcb)
{
    extern __shared__ __align__(128) uint8_t sm[];   // 3*STG3 dynamic
    uint32_t smBase = smem_u32(sm);
    const int Nout = 256;

    int tid = threadIdx.x, lane = tid & 31, wid = tid >> 5;
    int wm = wid & 3, wn = wid >> 2;     // 4 x 4 warp grid: 128 x 256
    int by = blockIdx.x;
    int sp = g_tilesp[by];

    const __half* WhS = Wh + (size_t)sp*Nout*K;

    float d[2][8][4];
    #pragma unroll
    for (int i=0;i<2;i++)
        #pragma unroll
        for (int j=0;j<8;j++)
            #pragma unroll
            for (int q=0;q<4;q++) d[i][j][q]=0.f;

    int nkc = K >> 5;

    uint32_t aoff = (uint32_t)((wm*32 + (lane & 15))*PITCH + ((lane >> 4) & 1)*16);
    uint32_t boff = (uint32_t)((wn*64 + (lane & 7) + ((lane >> 4) & 1)*8)*PITCH + ((lane >> 3) & 1)*16);

    auto do_mma = [&](int st){
        uint32_t base = smBase + (uint32_t)st*STG3;
        #pragma unroll
        for (int ks=0; ks<2; ks++){
            uint32_t a_[2][4], b_[4][4];
            uint32_t aT = base + aoff + ks*32;
            uint32_t bT = base + ATS + boff + ks*32;
            #pragma unroll
            for (int mi=0; mi<2; mi++) ldsm4(a_[mi], aT + mi*16*PITCH);
            #pragma unroll
            for (int np_=0; np_<4; np_++) ldsm4(b_[np_], bT + np_*16*PITCH);
            #pragma unroll
            for (int mi=0; mi<2; mi++)
                #pragma unroll
                for (int nj=0; nj<8; nj++)
                    mma16816(d[mi][nj], a_[mi], b_[nj>>1][(nj&1)*2], b_[nj>>1][(nj&1)*2+1]);
        }
    };

    if (A32 == nullptr){
        // ---- fp16 A path: 3 x 16B per thread (ah 512 | wh 1024) ----
        const __half* AhR = Ah + (size_t)by*128*lda;
        auto load_chunk = [&](int kc, int st){
            uint32_t base = smBase + (uint32_t)st*STG3;
            #pragma unroll
            for (int t=0;t<3;t++){
                int it = tid + t*512;
                const __half* src; uint32_t dst;
                if (it < 512){
                    int row = it >> 2, seg = it & 3;
                    src = AhR + (size_t)row*lda + kc*32 + seg*8;
                    dst = base + row*PITCH + seg*16;
                } else {
                    int j = it - 512;
                    int row = j >> 2, seg = j & 3;
                    src = WhS + (size_t)row*K + kc*32 + seg*8;
                    dst = base + ATS + row*PITCH + seg*16;
                }
                cp16(dst, src);
            }
            cp_commit();
        };
        load_chunk(0, 0);
        if (nkc > 1) load_chunk(1, 1);
        for (int c=0; c<nkc; c++){
            int st = c % 3;
            if (c+2 < nkc) load_chunk(c+2, (c+2)%3);
            if (c+2 < nkc) cp_wait<2>();
            else if (c+1 < nkc) cp_wait<1>();
            else cp_wait<0>();
            __syncthreads();
            do_mma(st);
            __syncthreads();
        }
    } else {
        // ---- fp32 A path (pass-0): LDG.128 + fp16 convert ----
        const float* aptr[2];
        bool avalid[2];
        int aRow[2], aSeg[2];
        #pragma unroll
        for (int t=0;t<2;t++){
            int j = tid + t*512;
            aRow[t] = j >> 3; aSeg[t] = j & 7;
            int src = g_n2o[by*128 + aRow[t]];
            avalid[t] = (src >= 0);
            aptr[t] = A32 + (size_t)(src < 0 ? 0 : src)*AEV;
        }
        auto loadW = [&](int kc, int st){
            uint32_t base = smBase + (uint32_t)st*STG3 + ATS;
            #pragma unroll
            for (int t=0;t<2;t++){
                int j = tid + t*512;     // 1024 items
                int row = j >> 2, seg = j & 3;
                const __half* src = WhS + (size_t)row*K + kc*32 + seg*8;
                cp16(base + row*PITCH + seg*16, src);
            }
            cp_commit();
        };
        float4 R[2];
        auto ldgA = [&](int kc){
            #pragma unroll
            for (int t=0;t<2;t++){
                int col = kc*32 + aSeg[t]*4;
                if (avalid[t] && col < AEV) R[t] = *(const float4*)(aptr[t] + col);
                else R[t] = make_float4(0.f,0.f,0.f,0.f);
            }
        };
        auto stsA = [&](int st){
            uint32_t base = (uint32_t)st*STG3;
            #pragma unroll
            for (int t=0;t<2;t++){
                __half h[4];
                h[0] = __float2half_rn(R[t].x);
                h[1] = __float2half_rn(R[t].y);
                h[2] = __float2half_rn(R[t].z);
                h[3] = __float2half_rn(R[t].w);
                uint32_t off = base + (uint32_t)(aRow[t]*PITCH + aSeg[t]*8);
                *(uint64_t*)(sm + off) = *(const uint64_t*)h;
            }
        };
        loadW(0, 0);
        if (nkc > 1) loadW(1, 1);
        ldgA(0); stsA(0);
        if (nkc > 1) ldgA(1);
        for (int c=0; c<nkc; c++){
            int st = c % 3;
            if (c+2 < nkc) loadW(c+2, (c+2)%3);
            if (c+1 < nkc) stsA((c+1)%3);
            if (c+2 < nkc) ldgA(c+2);
            if (c+2 < nkc) cp_wait<2>();
            else if (c+1 < nkc) cp_wait<1>();
            else cp_wait<0>();
            __syncthreads();
            do_mma(st);
            __syncthreads();
        }
    }

    const float* bp = bias + sp*Nout + wn*64;
    int rowLo = wm*32 + (lane >> 2);
    int colCta = wn*64;
    #pragma unroll
    for (int mi=0; mi<2; mi++){
        #pragma unroll
        for (int nj=0; nj<8; nj++){
            int c0 = nj*8 + 2*(lane & 3);
            float b0 = bp[c0], b1 = bp[c0+1];
            #pragma unroll
            for (int h=0; h<2; h++){
                size_t gr = (size_t)by*128 + rowLo + mi*16 + h*8;
                float x0 = gelu_tanh(d[mi][nj][2*h]   + b0);
                float x1 = gelu_tanh(d[mi][nj][2*h+1] + b1);
                int col = colCta + c0;
                if (C32){
                    *(float2*)(C32 + gr*ldc32 + col) = make_float2(x0, x1);
                }
                if (Ch){
                    uint32_t hh = (uint32_t)__half_as_ushort(__float2half_rn(x0)) |
                                  ((uint32_t)__half_as_ushort(__float2half_rn(x1)) << 16);
                    *(uint32_t*)(Ch + gr*ldcb + col) = hh;
                }
            }
        }
    }
}

// ---------------- CSR gather: merged[r][t] = sum_nb neigh[nb][t]*w ----------
__global__ void __launch_bounds__(128) mpgather_kernel(int mode){
    int r = blockIdx.x, t = threadIdx.x;
    int s = g_roff[r], e = g_roff[r+1];
    float acc = 0.f;
    int j = s;
    for (; j+1 < e; j += 2){
        int nb0 = g_nbr[j], nb1 = g_nbr[j+1];
        float w0 = g_w[j],  w1 = g_w[j+1];
        float x0 = g_neigh[(size_t)nb0*NOUT + t];
        float x1 = g_neigh[(size_t)nb1*NOUT + t];
        acc = fmaf(x0, w0, acc);
        acc = fmaf(x1, w1, acc);
    }
    if (j < e)
        acc = fmaf(g_neigh[(size_t)g_nbr[j]*NOUT + t], g_w[j], acc);
    if (mode == 0){
        g_f1h[(size_t)r*FIN + 256 + t] = __float2half_rn(acc);
    } else {
        g_feat2[(size_t)r*FIN + 256 + t] = acc;
    }
}

// ---------------- final routed linear (FIN->1) + outputs --------------------
__global__ void __launch_bounds__(256) final_kernel(const int* __restrict__ species,
                                                    const float* __restrict__ Wf,
                                                    const float* __restrict__ bf,
                                                    float* __restrict__ out){
    int gt = blockIdx.x*256 + threadIdx.x;
    int i = gt >> 5, lane = gt & 31;
    if (i >= NATOMS) return;
    int s = species[i];
    int r = g_p2n[i];
    const float* f = g_feat2 + (size_t)r*FIN;
    const float* w = Wf + s*FIN;
    float sum = 0.f;
    #pragma unroll
    for (int j=0;j<12;j++){
        int k = lane + 32*j;
        sum = fmaf(f[k], w[k], sum);
    }
    #pragma unroll
    for (int o=16;o;o>>=1) sum += __shfl_xor_sync(0xffffffffu, sum, o);
    if (lane == 0){
        float pre = sum + bf[s];
        g_pre[i] = pre;
        out[2*NATOMS + i] = pre;
        out[i] = (float)s;
    }
}

// ---------------- per-molecule charge redistribution -------------------------
__global__ void charge_kernel(const float* __restrict__ tq, float* __restrict__ out){
    __shared__ float ss[4];
    int b = blockIdx.x, a = threadIdx.x;
    float p = g_pre[b*NA + a];
    float v = p;
    #pragma unroll
    for (int o=16;o;o>>=1) v += __shfl_xor_sync(0xffffffffu, v, o);
    int w = a>>5, lane = a&31;
    if (lane == 0) ss[w] = v;
    __syncthreads();
    float sum = ss[0]+ss[1]+ss[2]+ss[3];
    out[NATOMS + b*NA + a] = p + (tq[b] - sum)*(1.0f/128.0f);
}

// ---------------- launch -----------------------------------------------------
extern "C" void kernel_launch(void* const* d_in, const int* in_sizes, int n_in,
                              void* d_out, int out_size){
    const int*   species = (const int*)  d_in[0];
    const float* aev     = (const float*)d_in[1];
    const int*   ai12    = (const int*)  d_in[2];
    const float* dist    = (const float*)d_in[3];
    const float* tq      = (const float*)d_in[4];
    const float* Wm0     = (const float*)d_in[5];
    const float* bm0     = (const float*)d_in[6];
    const float* Wn0     = (const float*)d_in[7];
    const float* bn0     = (const float*)d_in[8];
    const float* Wm1     = (const float*)d_in[9];
    const float* bm1     = (const float*)d_in[10];
    const float* Wn1     = (const float*)d_in[11];
    const float* bn1     = (const float*)d_in[12];
    const float* Wf      = (const float*)d_in[13];
    const float* bf      = (const float*)d_in[14];
    const float* factor  = (const float*)d_in[15];
    const float* prefac  = (const float*)d_in[16];
    float* out = (float*)d_out;

    __half *f1h, *f2h, *wm0h, *wn0h, *wm1h, *wn1h;
    float *feat2, *neigh;
    cudaGetSymbolAddress((void**)&f1h,  g_f1h);
    cudaGetSymbolAddress((void**)&f2h,  g_f2h);
    cudaGetSymbolAddress((void**)&wm0h, g_wm0h);
    cudaGetSymbolAddress((void**)&wn0h, g_wn0h);
    cudaGetSymbolAddress((void**)&wm1h, g_wm1h);
    cudaGetSymbolAddress((void**)&wn1h, g_wn1h);
    cudaGetSymbolAddress((void**)&feat2, g_feat2);
    cudaGetSymbolAddress((void**)&neigh, g_neigh);

    cudaFuncSetAttribute(tgemm128_kernel, cudaFuncAttributeMaxDynamicSharedMemorySize, 2*STG128);
    cudaFuncSetAttribute(tgemm256_kernel, cudaFuncAttributeMaxDynamicSharedMemorySize, 3*STG3);

    // side streams + events (created once; never destroyed -> capture-safe)
    static cudaStream_t s1 = 0, s2 = 0;
    static cudaEvent_t evStart=0, evPerm=0, evW0m=0, evWn0=0, evW1m=0, evWrest=0, evCsr=0;
    if (!s1){
        cudaStreamCreateWithFlags(&s1, cudaStreamNonBlocking);
        cudaStreamCreateWithFlags(&s2, cudaStreamNonBlocking);
        cudaEventCreateWithFlags(&evStart, cudaEventDisableTiming);
        cudaEventCreateWithFlags(&evPerm,  cudaEventDisableTiming);
        cudaEventCreateWithFlags(&evW0m,   cudaEventDisableTiming);
        cudaEventCreateWithFlags(&evWn0,   cudaEventDisableTiming);
        cudaEventCreateWithFlags(&evW1m,   cudaEventDisableTiming);
        cudaEventCreateWithFlags(&evWrest, cudaEventDisableTiming);
        cudaEventCreateWithFlags(&evCsr,   cudaEventDisableTiming);
    }

    // fork s2: weight prep in consumption order
    cudaEventRecord(evStart, 0);
    cudaStreamWaitEvent(s2, evStart, 0);
    wprep_kernel<<<(NSP*MO*AEVP)/256, 256, 0, s2>>>(Wm0, wm0h, AEV, MO, AEVP);
    cudaEventRecord(evW0m, s2);
    wprep_kernel<<<(NSP*NOUT*MO)/256, 256, 0, s2>>>(Wn0, wn0h, MO, NOUT, MO);
    cudaEventRecord(evWn0, s2);
    wprep_kernel<<<(NSP*MO*FIN)/256, 256, 0, s2>>>(Wm1, wm1h, FIN, MO, FIN);
    cudaEventRecord(evW1m, s2);
    wprep_kernel<<<(NSP*NOUT*MO)/256, 256, 0, s2>>>(Wn1, wn1h, MO, NOUT, MO);
    cudaEventRecord(evWrest, s2);

    // main: permutation; fork s1: CSR build
    perm_kernel<<<1, 1024>>>(species);
    cudaEventRecord(evPerm, 0);
    cudaStreamWaitEvent(s1, evPerm, 0);
    edge_kernel<<<NP/256, 256, 0, s1>>>(ai12, dist, factor, prefac);
    scan_kernel<<<1, 1024, 0, s1>>>();
    fill_kernel<<<NP/256, 256, 0, s1>>>();
    cudaEventRecord(evCsr, s1);

    // pass 0
    cudaStreamWaitEvent(0, evW0m, 0);
    tgemm256_kernel<<<NT, 512, 3*STG3>>>(aev,
        (__half*)0, 0, wm0h, bm0,
        AEVP, (float*)0, 0, f1h, FIN);
    cudaStreamWaitEvent(0, evWn0, 0);
    tgemm128_kernel<<<NT, 256, 2*STG128>>>(f1h, FIN, wn0h, bn0,
        MO, neigh, NOUT, 1);
    cudaStreamWaitEvent(0, evCsr, 0);
    mpgather_kernel<<<NPAD, 128>>>(0);

    // pass 1
    cudaStreamWaitEvent(0, evW1m, 0);
    tgemm256_kernel<<<NT, 512, 3*STG3>>>((const float*)0,
        f1h, FIN, wm1h, bm1,
        FIN, feat2, FIN, f2h, MO);
    cudaStreamWaitEvent(0, evWrest, 0);
    tgemm128_kernel<<<NT, 256, 2*STG128>>>(f2h, MO, wn1h, bn1,
        MO, neigh, NOUT, 1);
    mpgather_kernel<<<NPAD, 128>>>(1);

    // outputs
    final_kernel <<<NATOMS*32/256, 256>>>(species, Wf, bf, out);
    charge_kernel<<<NB, NA>>>(tq, out);
}